// round 7
// baseline (speedup 1.0000x reference)
#include <cuda_runtime.h>
#include <cuda_bf16.h>
#include <math.h>
#include <stdint.h>

// ---------------- problem constants ----------------
#define AA    32
#define CC    16
#define KKn   9
#define KKA   288
#define NB    16      // Bc
#define ND    16      // D
#define NE    256     // Bc*D
#define HW    14
#define LL    196
#define NBSZ  4
#define NBL   784     // NBSZ*LL
#define NCOL  12544   // NBL*NB
#define KKA2  145
#define KP    320     // padded K for tensor GEMM (5 x 64)
#define NCG   1568    // NCOL/8 column groups

// ---------------- scratch (static device mem; no allocs allowed) ----------------
__device__ float g_h[16 * 288];                                        //  18 KB
__device__ __align__(1024) __nv_bfloat16 g_Hb[(size_t)16 * 288 * KP];  //  2.95 MB  H circulant bf16 [d][m][k]
// P bf16, interleaved: [d][cg=col/8][g=m-block(8 m = 16B)][ci=col%8][8 m]
__device__ __align__(1024) __nv_bfloat16 g_Pb[(size_t)16 * NCOL * KP]; //  128 MB
__device__ float g_C[(size_t)288 * NCOL];                              //  14.4 MB  coeff [m][col]

// fast exact-gelu via Abramowitz-Stegun 7.1.26 erf (|abs err| <= 1.5e-7)
__device__ __forceinline__ float gelu_fast(float v) {
    float x  = v * 0.70710678118654752f;
    float ax = fabsf(x);
    float t  = __fdividef(1.0f, fmaf(0.3275911f, ax, 1.0f));
    float poly = t * fmaf(t, fmaf(t, fmaf(t, fmaf(t, 1.061405429f, -1.453152027f),
                                          1.421413741f), -0.284496736f), 0.254829592f);
    float r  = 1.0f - poly * __expf(-ax * ax);
    float erfv = copysignf(r, x);
    return 0.5f * v * (1.0f + erfv);
}

// ---------------- PTX helpers (sm_100 baseline: cp.async / ldmatrix / mma.sync) ----------------
__device__ __forceinline__ uint32_t smem_u32(const void* p) {
    uint32_t a;
    asm("{ .reg .u64 t; cvta.to.shared.u64 t, %1; cvt.u32.u64 %0, t; }" : "=r"(a) : "l"(p));
    return a;
}
__device__ __forceinline__ void cp_async16(uint32_t saddr, const void* gaddr) {
    asm volatile("cp.async.cg.shared.global [%0], [%1], 16;" :: "r"(saddr), "l"(gaddr) : "memory");
}
#define CP_COMMIT() asm volatile("cp.async.commit_group;" ::: "memory")
#define CP_WAIT(n)  asm volatile("cp.async.wait_group %0;" :: "n"(n) : "memory")

__device__ __forceinline__ void ldsm_x4(uint32_t& r0, uint32_t& r1, uint32_t& r2, uint32_t& r3,
                                        uint32_t addr) {
    asm volatile("ldmatrix.sync.aligned.m8n8.x4.shared.b16 {%0,%1,%2,%3}, [%4];"
                 : "=r"(r0), "=r"(r1), "=r"(r2), "=r"(r3) : "r"(addr));
}
__device__ __forceinline__ void mma_bf16(float* d, const uint32_t* a, const uint32_t* b) {
    asm volatile("mma.sync.aligned.m16n8k16.row.col.f32.bf16.bf16.f32 "
                 "{%0,%1,%2,%3}, {%4,%5,%6,%7}, {%8,%9}, {%0,%1,%2,%3};"
                 : "+f"(d[0]), "+f"(d[1]), "+f"(d[2]), "+f"(d[3])
                 : "r"(a[0]), "r"(a[1]), "r"(a[2]), "r"(a[3]), "r"(b[0]), "r"(b[1]));
}

// ============ kernel 0: h[d][t] = irfft(W_d)[t] ============
__global__ void k_build_h(const float* __restrict__ cw) {
    __shared__ float ct[288], st[288];
    int t = threadIdx.x;  // 288 threads
    float ang = 6.283185307179586f * (float)t * (1.0f / 288.0f);
    ct[t] = cosf(ang);
    st[t] = sinf(ang);
    __syncthreads();
    for (int d = 0; d < 16; d++) {
        float wr0  = cw[(0 * 16 + d) * 2];
        float wnyq = cw[(144 * 16 + d) * 2];
        float acc = wr0 + ((t & 1) ? -wnyq : wnyq);
        float s2 = 0.0f;
        int idx = 0;
        for (int k = 1; k <= 143; k++) {
            idx += t; if (idx >= 288) idx -= 288;
            float wr = cw[(k * 16 + d) * 2];
            float wi = cw[(k * 16 + d) * 2 + 1];
            s2 += wr * ct[idx] - wi * st[idx];
        }
        g_h[d * 288 + t] = (acc + 2.0f * s2) * (1.0f / 288.0f);
    }
}

// ============ kernel 1: H bf16 circulant [d][m][k<=320], zero padded ============
__global__ void k_expand_Hb() {
    int m = blockIdx.x;      // 288
    int d = blockIdx.y;      // 16
    int j = threadIdx.x;     // 320
    float v = 0.0f;
    if (j < 288) {
        int t = m - j; if (t < 0) t += 288;
        v = g_h[d * 288 + t];
    }
    g_Hb[((size_t)d * 288 + m) * KP + j] = __float2bfloat16(v);
}

// ============ kernel 2: per-position producer ============
extern __shared__ float smem_dyn[];
__global__ void __launch_bounds__(256) k_main(
    const float* __restrict__ a_in, const float* __restrict__ pose,
    const float* __restrict__ mpose_w, const float* __restrict__ mpose_b,
    const float* __restrict__ cpose2_w, const float* __restrict__ cpose2_b,
    const float* __restrict__ ln_gamma, const float* __restrict__ ln_beta,
    const float* __restrict__ sp_w, const float* __restrict__ sp_b,
    float* __restrict__ out)
{
    float* s_pu  = smem_dyn;               // [288][17]
    float* s_lg  = s_pu  + 288 * 17;       // [288][17]
    float* s_gn  = s_lg  + 288 * 17;       // [288][17]
    float* s_cw  = s_gn  + 288 * 17;       // [16][17]
    float* s_cb  = s_cw  + 16 * 17;
    float* s_spw = s_cb  + 16;
    float* s_spb = s_spw + 81;
    float* s_gam = s_spb + 16;
    float* s_bet = s_gam + 32;
    float* s_au  = s_bet + 32;
    float* s_mu  = s_au  + 288;
    float* s_rs  = s_mu  + 144;
    float* s_red = s_rs  + 144;
    float* s_ars = s_red + 256;
    float* s_aus = s_ars + 16;

    const int tid = threadIdx.x;
    const int bl = blockIdx.x;
    const int b = bl / LL, l = bl % LL;
    const int y = l / HW, x = l % HW;

    {
        int Bi = tid >> 4, c = tid & 15;
        s_cw[Bi * 17 + c] = cpose2_w[tid];
        if (tid < 16)  s_cb[tid]  = cpose2_b[tid];
        if (tid < 81)  s_spw[tid] = sp_w[tid];
        if (tid < 9)   s_spb[tid] = sp_b[tid];
        if (tid < 32)  s_gam[tid] = ln_gamma[tid];
        if (tid >= 32 && tid < 64) s_bet[tid - 32] = ln_beta[tid - 32];
    }

    // S1: gather pu and au
    for (int idx = tid; idx < 4608; idx += 256) {
        int m = idx >> 4, c = idx & 15;
        int kk = m >> 5, ai = m & 31;
        int py = y + kk / 3 - 1, px = x + kk % 3 - 1;
        float v = 0.0f;
        if ((unsigned)py < 14u && (unsigned)px < 14u)
            v = pose[(((size_t)b * 512 + (size_t)ai * 16 + c) * 14 + py) * 14 + px];
        s_pu[m * 17 + c] = v;
    }
    for (int m = tid; m < 288; m += 256) {
        int kk = m >> 5, ai = m & 31;
        int py = y + kk / 3 - 1, px = x + kk % 3 - 1;
        float v = 0.0f;
        if ((unsigned)py < 14u && (unsigned)px < 14u)
            v = a_in[(((size_t)b * 32 + ai) * 14 + py) * 14 + px];
        s_au[m] = v;
    }
    __syncthreads();

    // S2: logits
    for (int idx = tid; idx < 4608; idx += 256) {
        int m = idx >> 4, Bi = idx & 15;
        const float* pv = s_pu + m * 17;
        const float* pw = s_cw + Bi * 17;
        float acc = s_cb[Bi];
        #pragma unroll
        for (int c = 0; c < 16; c++) acc = fmaf(pv[c], pw[c], acc);
        s_lg[m * 17 + Bi] = acc;
    }
    __syncthreads();

    // S3: LayerNorm over a
    if (tid < 144) {
        int kk = tid >> 4, Bi = tid & 15;
        float s = 0.0f, s2 = 0.0f;
        #pragma unroll 4
        for (int ai = 0; ai < 32; ai++) {
            float v = s_lg[(kk * 32 + ai) * 17 + Bi];
            s += v; s2 += v * v;
        }
        float mu = s * (1.0f / 32.0f);
        float var = s2 * (1.0f / 32.0f) - mu * mu;
        s_mu[tid] = mu;
        s_rs[tid] = rsqrtf(var + 1e-5f);
    }
    __syncthreads();
    for (int idx = tid; idx < 4608; idx += 256) {
        int m = idx >> 4, Bi = idx & 15;
        int kk = m >> 5, ai = m & 31;
        float v = s_lg[m * 17 + Bi];
        s_gn[m * 17 + Bi] = (v - s_mu[kk * 16 + Bi]) * s_rs[kk * 16 + Bi] * s_gam[ai] + s_bet[ai];
    }
    __syncthreads();

    // S4: spatial gate
    for (int idx = tid; idx < 4608; idx += 256) {
        int m = idx >> 4, Bi = idx & 15;
        int o = m >> 5, ai = m & 31;
        float acc = s_spb[o];
        #pragma unroll
        for (int i = 0; i < 9; i++)
            acc = fmaf(s_spw[o * 9 + i], s_gn[(i * 32 + ai) * 17 + Bi], acc);
        s_lg[m * 17 + Bi] = 2.0f * s_lg[m * 17 + Bi] + gelu_fast(acc);
    }
    __syncthreads();

    // S5: softmax over Bi; au sum
    for (int m = tid; m < 288; m += 256) {
        float* row = s_lg + m * 17;
        float mx = row[0];
        #pragma unroll
        for (int i = 1; i < 16; i++) mx = fmaxf(mx, row[i]);
        float s = 0.0f;
        #pragma unroll
        for (int i = 0; i < 16; i++) { float e = expf(row[i] - mx); row[i] = e; s += e; }
        float inv = 1.0f / s;
        #pragma unroll
        for (int i = 0; i < 16; i++) row[i] *= inv;
    }
    if (tid < 32) {
        float p = 0.0f;
        for (int m = tid; m < 288; m += 32) p += s_au[m];
        #pragma unroll
        for (int o = 16; o; o >>= 1) p += __shfl_xor_sync(0xffffffffu, p, o);
        if (tid == 0) *s_aus = p;
    }
    __syncthreads();

    // S6: ar and ar_sum
    {
        int Bi = tid & 15, ck = tid >> 4;
        float p = 0.0f;
        #pragma unroll 2
        for (int r = 0; r < 18; r++) {
            int m = ck * 18 + r;
            float ar = s_au[m] * s_lg[m * 17 + Bi];
            s_gn[m * 17 + Bi] = ar;
            p += ar;
        }
        s_red[ck * 16 + Bi] = p;
    }
    __syncthreads();
    if (tid < 16) {
        float s = 0.0f;
        #pragma unroll
        for (int c = 0; c < 16; c++) s += s_red[c * 16 + tid];
        s_ars[tid] = s;
        out[((size_t)b * 16 + tid) * LL + l] = s / (*s_aus);
    }
    __syncthreads();

    // S7: coeff; write C[m][col]
    for (int idx = tid; idx < 4608; idx += 256) {
        int m = idx >> 4, Bi = idx & 15;
        float cf = s_gn[m * 17 + Bi] / s_ars[Bi];
        s_gn[m * 17 + Bi] = cf;
        g_C[(size_t)m * NCOL + (size_t)bl * 16 + Bi] = cf;
    }
    __syncthreads();

    // S8: p = gelu(pu@W^T+b); po_base = sum coeff*p; write P bf16 interleaved layout.
    // Interleaved layout: uint4 index = ((d*NCG + cg)*40 + g)*8 + ci  (cg=col/8, ci=col%8)
    // -> 8 consecutive Bi-lanes hit 8 consecutive uint4 (one 128B line) per g: coalesced.
    {
        int Bi = tid & 15, d = tid >> 4;
        int e = Bi * 16 + d;
        int col = bl * 16 + Bi;
        int cg = col >> 3, ci = col & 7;
        float W[16];
        #pragma unroll
        for (int c = 0; c < 16; c++) W[c] = mpose_w[e * 16 + c];
        float bs = mpose_b[e];
        float acc = 0.0f;
        uint4* Pd4 = reinterpret_cast<uint4*>(g_Pb) +
                     (((size_t)d * NCG + cg) * 40) * 8 + ci;
        for (int g = 0; g < 36; g++) {            // 36 * 8 = 288 m-values
            uint32_t pk[4];
            #pragma unroll
            for (int pp = 0; pp < 4; pp++) {
                float vv[2];
                #pragma unroll
                for (int h = 0; h < 2; h++) {
                    int m = g * 8 + pp * 2 + h;
                    const float* pv = s_pu + m * 17;
                    float v = bs;
                    #pragma unroll
                    for (int c = 0; c < 16; c++) v = fmaf(pv[c], W[c], v);
                    float pval = gelu_fast(v);
                    acc = fmaf(s_gn[m * 17 + Bi], pval, acc);
                    vv[h] = pval;
                }
                __nv_bfloat162 h2 = __floats2bfloat162_rn(vv[0], vv[1]);
                pk[pp] = *reinterpret_cast<uint32_t*>(&h2);
            }
            Pd4[g * 8] = make_uint4(pk[0], pk[1], pk[2], pk[3]);
        }
        // zero pad m-blocks g = 36..39 (k = 288..319)
        uint4 z = make_uint4(0, 0, 0, 0);
        Pd4[36 * 8] = z; Pd4[37 * 8] = z; Pd4[38 * 8] = z; Pd4[39 * 8] = z;
        out[12544 + (size_t)b * 50176 + (size_t)e * LL + l] = acc;
    }
}

// ============ kernel 3: mma.sync bf16 circulant GEMM + fused coeff reduction ============
// grid (98 col-tiles, 3 m-tiles, 16 d), 256 threads (8 warps: 2 m-warps x 4 n-warps).
// D[m(96), col(128)] = H_d[m, k] x P_d[col, k]^T ; epilogue po[col,d] += sum_m C[m,col]*D.
#define SA_STG 12288            // 96 rows x 128B
#define SB_STG 16384            // 128 rows x 128B
#define GEMM_SMEM (2 * SA_STG + 2 * SB_STG)

__global__ void __launch_bounds__(256, 2) k_gemm_mma(float* __restrict__ out) {
    extern __shared__ __align__(128) char smemc[];
    const uint32_t sb = smem_u32(smemc);
    const int tid  = threadIdx.x;
    const int lane = tid & 31;
    const int wid  = tid >> 5;
    const int wm   = wid >> 2;          // 0..1  (m-warp, 48 rows each)
    const int wn   = wid & 3;           // 0..3  (n-warp, 32 cols each)

    const int d    = blockIdx.z;
    const int m0   = blockIdx.y * 96;
    const int col0 = blockIdx.x * 128;
    const int cg0  = col0 >> 3;

    const __nv_bfloat16* Hg = g_Hb + ((size_t)d * 288 + m0) * KP;
    const char* Pgd = reinterpret_cast<const char*>(g_Pb) +
                      ((size_t)d * NCG) * 40 * 128;   // d block base (bytes)

    float acc[3][4][4];
    #pragma unroll
    for (int r = 0; r < 3; r++)
        #pragma unroll
        for (int q = 0; q < 4; q++)
            #pragma unroll
            for (int i = 0; i < 4; i++) acc[r][q][i] = 0.0f;

    // ---- chunk loader: chunk c (k in [c*64, c*64+64)) into stage s ----
    auto load_chunk = [&](int c, int s) {
        uint32_t abase = sb + s * SA_STG;
        uint32_t bbase = sb + 2 * SA_STG + s * SB_STG;
        #pragma unroll
        for (int it = 0; it < 3; it++) {          // 96 rows x 8 chunks = 768
            int i = tid + it * 256;
            int row = i >> 3, u = i & 7;
            cp_async16(abase + row * 128 + ((u ^ (row & 7)) << 4),
                       Hg + (size_t)row * KP + c * 64 + u * 8);
        }
        // B (interleaved P): decode so 8 consecutive lanes read one full 128B line:
        //   ci = j&7 (16B within line), u = (j>>3)&7 (k-block = line), cgl = j>>6.
        #pragma unroll
        for (int it = 0; it < 4; it++) {          // 16 cg x 8 u x 8 ci = 1024
            int j = tid + it * 256;
            int ci = j & 7, u = (j >> 3) & 7, cgl = j >> 6;
            int row = cgl * 8 + ci;               // smem row = local column index
            size_t go = ((size_t)(cg0 + cgl) * 40 + (c * 8 + u)) * 128 + (ci << 4);
            cp_async16(bbase + row * 128 + ((u ^ (row & 7)) << 4), Pgd + go);
        }
        CP_COMMIT();
    };

    load_chunk(0, 0);

    // per-lane ldmatrix address components
    const int a_row_l = wm * 48 + (lane & 15);          // + r*16
    const int a_chalf = lane >> 4;                      // k-half select
    // B loads paired: one ldsm_x4 covers q-pair (2 n-fragments x 2 k-halves)
    const int b_row_l = wn * 32 + ((lane >> 4) << 3) + (lane & 7);   // + qp*16
    const int b_chalf = (lane >> 3) & 1;

    for (int c = 0; c < 5; c++) {
        if (c < 4) load_chunk(c + 1, (c + 1) & 1);
        if (c < 4) CP_WAIT(1); else CP_WAIT(0);
        __syncthreads();

        uint32_t Ab = sb + (c & 1) * SA_STG;
        uint32_t Bb = sb + 2 * SA_STG + (c & 1) * SB_STG;

        #pragma unroll
        for (int ks = 0; ks < 4; ks++) {
            uint32_t a[3][4], bfrag[4][2];
            #pragma unroll
            for (int r = 0; r < 3; r++) {
                int row = a_row_l + r * 16;
                int c16 = ks * 2 + a_chalf;
                ldsm_x4(a[r][0], a[r][1], a[r][2], a[r][3],
                        Ab + row * 128 + (((c16 ^ (row & 7)) & 7) << 4));
            }
            #pragma unroll
            for (int qp = 0; qp < 2; qp++) {
                int row = b_row_l + qp * 16;
                int c16 = ks * 2 + b_chalf;
                ldsm_x4(bfrag[qp * 2][0], bfrag[qp * 2][1],
                        bfrag[qp * 2 + 1][0], bfrag[qp * 2 + 1][1],
                        Bb + row * 128 + (((c16 ^ (row & 7)) & 7) << 4));
            }
            #pragma unroll
            for (int r = 0; r < 3; r++)
                #pragma unroll
                for (int q = 0; q < 4; q++)
                    mma_bf16(acc[r][q], a[r], bfrag[q]);
        }
        __syncthreads();
    }

    // ---- fused epilogue: s[col] = sum_m C[m,col] * D[m,col] ----
    float s[8];
    #pragma unroll
    for (int j = 0; j < 8; j++) s[j] = 0.0f;
    const int colb = col0 + wn * 32 + ((lane & 3) << 1);
    #pragma unroll
    for (int r = 0; r < 3; r++) {
        #pragma unroll
        for (int half = 0; half < 2; half++) {
            int m = m0 + wm * 48 + r * 16 + (lane >> 2) + half * 8;
            const float* Crow = g_C + (size_t)m * NCOL;
            #pragma unroll
            for (int q = 0; q < 4; q++) {
                s[q * 2 + 0] = fmaf(Crow[colb + q * 8 + 0], acc[r][q][half * 2 + 0], s[q * 2 + 0]);
                s[q * 2 + 1] = fmaf(Crow[colb + q * 8 + 1], acc[r][q][half * 2 + 1], s[q * 2 + 1]);
            }
        }
    }
    #pragma unroll
    for (int off = 4; off < 32; off <<= 1)
        #pragma unroll
        for (int j = 0; j < 8; j++) s[j] += __shfl_xor_sync(0xffffffffu, s[j], off);

    if (lane < 4) {
        #pragma unroll
        for (int q = 0; q < 4; q++) {
            #pragma unroll
            for (int j = 0; j < 2; j++) {
                int col = col0 + wn * 32 + q * 8 + lane * 2 + j;
                int bl = col >> 4, Bi = col & 15;
                int bb = bl / LL, ll = bl % LL;
                atomicAdd(&out[12544 + (size_t)bb * 50176 + (size_t)(Bi * 16 + d) * LL + ll],
                          s[q * 2 + j]);
            }
        }
    }
}

// ---------------- launch ----------------
extern "C" void kernel_launch(void* const* d_in, const int* in_sizes, int n_in,
                              void* d_out, int out_size) {
    const float* a     = (const float*)d_in[0];
    const float* pose  = (const float*)d_in[1];
    const float* mw    = (const float*)d_in[2];
    const float* mb    = (const float*)d_in[3];
    const float* cw2   = (const float*)d_in[4];
    const float* cb2   = (const float*)d_in[5];
    const float* cplx  = (const float*)d_in[6];
    const float* gam   = (const float*)d_in[7];
    const float* bet   = (const float*)d_in[8];
    const float* spw   = (const float*)d_in[9];
    const float* spb   = (const float*)d_in[10];
    float* out = (float*)d_out;

    size_t smem_floats = (size_t)3 * 288 * 17 + 16 * 17 + 16 + 81 + 16 + 32 + 32 + 288 + 144 + 144 + 256 + 16 + 1;
    size_t smem_bytes = smem_floats * sizeof(float);
    cudaFuncSetAttribute(k_main, cudaFuncAttributeMaxDynamicSharedMemorySize, (int)smem_bytes);
    cudaFuncSetAttribute(k_gemm_mma, cudaFuncAttributeMaxDynamicSharedMemorySize, GEMM_SMEM);

    k_build_h<<<1, 288>>>(cplx);
    k_expand_Hb<<<dim3(288, 16), 320>>>();
    k_main<<<NBL, 256, smem_bytes>>>(a, pose, mw, mb, cw2, cb2, gam, bet, spw, spb, out);
    k_gemm_mma<<<dim3(NCOL / 128, 288 / 96, 16), 256, GEMM_SMEM>>>(out);
}

// round 8
// speedup vs baseline: 1.0433x; 1.0433x over previous
#include <cuda_runtime.h>
#include <cuda_bf16.h>
#include <math.h>
#include <stdint.h>

// ---------------- problem constants ----------------
#define AA    32
#define CC    16
#define KKn   9
#define KKA   288
#define NB    16      // Bc
#define ND    16      // D
#define NE    256     // Bc*D
#define HW    14
#define LL    196
#define NBSZ  4
#define NBL   784     // NBSZ*LL
#define NCOL  12544   // NBL*NB
#define KKA2  145
#define KP    320     // padded K for tensor GEMM (5 x 64)
#define PUS   20      // s_pu row stride (floats): 80B, 16B-aligned for LDS.128

// ---------------- scratch (static device mem; no allocs allowed) ----------------
__device__ float g_h[16 * 288];                                        //  18 KB
__device__ __align__(1024) __nv_bfloat16 g_Hb[(size_t)16 * 288 * KP];  //  2.95 MB  H circulant bf16 [d][m][k]
__device__ __align__(1024) __nv_bfloat16 g_Pb[(size_t)16 * NCOL * KP]; //  128 MB   P bf16 [d][col][k] (FLAT)
__device__ float g_C[(size_t)288 * NCOL];                              //  14.4 MB  coeff [m][col]

// fast exact-gelu via Abramowitz-Stegun 7.1.26 erf (|abs err| <= 1.5e-7)
__device__ __forceinline__ float gelu_fast(float v) {
    float x  = v * 0.70710678118654752f;
    float ax = fabsf(x);
    float t  = __fdividef(1.0f, fmaf(0.3275911f, ax, 1.0f));
    float poly = t * fmaf(t, fmaf(t, fmaf(t, fmaf(t, 1.061405429f, -1.453152027f),
                                          1.421413741f), -0.284496736f), 0.254829592f);
    float r  = 1.0f - poly * __expf(-ax * ax);
    float erfv = copysignf(r, x);
    return 0.5f * v * (1.0f + erfv);
}

// ---------------- PTX helpers (sm_100 baseline: cp.async / ldmatrix / mma.sync) ----------------
__device__ __forceinline__ uint32_t smem_u32(const void* p) {
    uint32_t a;
    asm("{ .reg .u64 t; cvta.to.shared.u64 t, %1; cvt.u32.u64 %0, t; }" : "=r"(a) : "l"(p));
    return a;
}
__device__ __forceinline__ void cp_async16(uint32_t saddr, const void* gaddr) {
    asm volatile("cp.async.cg.shared.global [%0], [%1], 16;" :: "r"(saddr), "l"(gaddr) : "memory");
}
#define CP_COMMIT() asm volatile("cp.async.commit_group;" ::: "memory")
#define CP_WAIT(n)  asm volatile("cp.async.wait_group %0;" :: "n"(n) : "memory")

__device__ __forceinline__ void ldsm_x4(uint32_t& r0, uint32_t& r1, uint32_t& r2, uint32_t& r3,
                                        uint32_t addr) {
    asm volatile("ldmatrix.sync.aligned.m8n8.x4.shared.b16 {%0,%1,%2,%3}, [%4];"
                 : "=r"(r0), "=r"(r1), "=r"(r2), "=r"(r3) : "r"(addr));
}
__device__ __forceinline__ void mma_bf16(float* d, const uint32_t* a, const uint32_t* b) {
    asm volatile("mma.sync.aligned.m16n8k16.row.col.f32.bf16.bf16.f32 "
                 "{%0,%1,%2,%3}, {%4,%5,%6,%7}, {%8,%9}, {%0,%1,%2,%3};"
                 : "+f"(d[0]), "+f"(d[1]), "+f"(d[2]), "+f"(d[3])
                 : "r"(a[0]), "r"(a[1]), "r"(a[2]), "r"(a[3]), "r"(b[0]), "r"(b[1]));
}

// ============ kernel 0: h[d][t] = irfft(W_d)[t] ============
__global__ void k_build_h(const float* __restrict__ cw) {
    __shared__ float ct[288], st[288];
    int t = threadIdx.x;  // 288 threads
    float ang = 6.283185307179586f * (float)t * (1.0f / 288.0f);
    ct[t] = cosf(ang);
    st[t] = sinf(ang);
    __syncthreads();
    for (int d = 0; d < 16; d++) {
        float wr0  = cw[(0 * 16 + d) * 2];
        float wnyq = cw[(144 * 16 + d) * 2];
        float acc = wr0 + ((t & 1) ? -wnyq : wnyq);
        float s2 = 0.0f;
        int idx = 0;
        for (int k = 1; k <= 143; k++) {
            idx += t; if (idx >= 288) idx -= 288;
            float wr = cw[(k * 16 + d) * 2];
            float wi = cw[(k * 16 + d) * 2 + 1];
            s2 += wr * ct[idx] - wi * st[idx];
        }
        g_h[d * 288 + t] = (acc + 2.0f * s2) * (1.0f / 288.0f);
    }
}

// ============ kernel 1: H bf16 circulant [d][m][k<=320], zero padded ============
__global__ void k_expand_Hb() {
    int m = blockIdx.x;      // 288
    int d = blockIdx.y;      // 16
    int j = threadIdx.x;     // 320
    float v = 0.0f;
    if (j < 288) {
        int t = m - j; if (t < 0) t += 288;
        v = g_h[d * 288 + t];
    }
    g_Hb[((size_t)d * 288 + m) * KP + j] = __float2bfloat16(v);
}

// ============ kernel 2: per-position producer ============
extern __shared__ float smem_dyn[];
__global__ void __launch_bounds__(256) k_main(
    const float* __restrict__ a_in, const float* __restrict__ pose,
    const float* __restrict__ mpose_w, const float* __restrict__ mpose_b,
    const float* __restrict__ cpose2_w, const float* __restrict__ cpose2_b,
    const float* __restrict__ ln_gamma, const float* __restrict__ ln_beta,
    const float* __restrict__ sp_w, const float* __restrict__ sp_b,
    float* __restrict__ out)
{
    float* s_pu  = smem_dyn;               // [288][20]  (16B-aligned rows)
    float* s_lg  = s_pu  + 288 * PUS;      // [288][17]
    float* s_gn  = s_lg  + 288 * 17;       // [288][17]
    float* s_cw  = s_gn  + 288 * 17;       // [16][17]
    float* s_cb  = s_cw  + 16 * 17;
    float* s_spw = s_cb  + 16;
    float* s_spb = s_spw + 81;
    float* s_gam = s_spb + 16;
    float* s_bet = s_gam + 32;
    float* s_au  = s_bet + 32;
    float* s_mu  = s_au  + 288;
    float* s_rs  = s_mu  + 144;
    float* s_red = s_rs  + 144;
    float* s_ars = s_red + 256;
    float* s_aus = s_ars + 16;

    const int tid = threadIdx.x;
    const int bl = blockIdx.x;
    const int b = bl / LL, l = bl % LL;
    const int y = l / HW, x = l % HW;

    {
        int Bi = tid >> 4, c = tid & 15;
        s_cw[Bi * 17 + c] = cpose2_w[tid];
        if (tid < 16)  s_cb[tid]  = cpose2_b[tid];
        if (tid < 81)  s_spw[tid] = sp_w[tid];
        if (tid < 9)   s_spb[tid] = sp_b[tid];
        if (tid < 32)  s_gam[tid] = ln_gamma[tid];
        if (tid >= 32 && tid < 64) s_bet[tid - 32] = ln_beta[tid - 32];
    }

    // S1: gather pu and au
    for (int idx = tid; idx < 4608; idx += 256) {
        int m = idx >> 4, c = idx & 15;
        int kk = m >> 5, ai = m & 31;
        int py = y + kk / 3 - 1, px = x + kk % 3 - 1;
        float v = 0.0f;
        if ((unsigned)py < 14u && (unsigned)px < 14u)
            v = pose[(((size_t)b * 512 + (size_t)ai * 16 + c) * 14 + py) * 14 + px];
        s_pu[m * PUS + c] = v;
    }
    for (int m = tid; m < 288; m += 256) {
        int kk = m >> 5, ai = m & 31;
        int py = y + kk / 3 - 1, px = x + kk % 3 - 1;
        float v = 0.0f;
        if ((unsigned)py < 14u && (unsigned)px < 14u)
            v = a_in[(((size_t)b * 32 + ai) * 14 + py) * 14 + px];
        s_au[m] = v;
    }
    __syncthreads();

    // S2: logits (vectorized pu reads)
    for (int idx = tid; idx < 4608; idx += 256) {
        int m = idx >> 4, Bi = idx & 15;
        const float4* pv4 = reinterpret_cast<const float4*>(s_pu + m * PUS);
        const float* pw = s_cw + Bi * 17;
        float4 p0 = pv4[0], p1 = pv4[1], p2 = pv4[2], p3 = pv4[3];
        float acc = s_cb[Bi];
        acc = fmaf(p0.x, pw[0],  acc); acc = fmaf(p0.y, pw[1],  acc);
        acc = fmaf(p0.z, pw[2],  acc); acc = fmaf(p0.w, pw[3],  acc);
        acc = fmaf(p1.x, pw[4],  acc); acc = fmaf(p1.y, pw[5],  acc);
        acc = fmaf(p1.z, pw[6],  acc); acc = fmaf(p1.w, pw[7],  acc);
        acc = fmaf(p2.x, pw[8],  acc); acc = fmaf(p2.y, pw[9],  acc);
        acc = fmaf(p2.z, pw[10], acc); acc = fmaf(p2.w, pw[11], acc);
        acc = fmaf(p3.x, pw[12], acc); acc = fmaf(p3.y, pw[13], acc);
        acc = fmaf(p3.z, pw[14], acc); acc = fmaf(p3.w, pw[15], acc);
        s_lg[m * 17 + Bi] = acc;
    }
    __syncthreads();

    // S3: LayerNorm over a
    if (tid < 144) {
        int kk = tid >> 4, Bi = tid & 15;
        float s = 0.0f, s2 = 0.0f;
        #pragma unroll 4
        for (int ai = 0; ai < 32; ai++) {
            float v = s_lg[(kk * 32 + ai) * 17 + Bi];
            s += v; s2 += v * v;
        }
        float mu = s * (1.0f / 32.0f);
        float var = s2 * (1.0f / 32.0f) - mu * mu;
        s_mu[tid] = mu;
        s_rs[tid] = rsqrtf(var + 1e-5f);
    }
    __syncthreads();
    for (int idx = tid; idx < 4608; idx += 256) {
        int m = idx >> 4, Bi = idx & 15;
        int kk = m >> 5, ai = m & 31;
        float v = s_lg[m * 17 + Bi];
        s_gn[m * 17 + Bi] = (v - s_mu[kk * 16 + Bi]) * s_rs[kk * 16 + Bi] * s_gam[ai] + s_bet[ai];
    }
    __syncthreads();

    // S4: spatial gate
    for (int idx = tid; idx < 4608; idx += 256) {
        int m = idx >> 4, Bi = idx & 15;
        int o = m >> 5, ai = m & 31;
        float acc = s_spb[o];
        #pragma unroll
        for (int i = 0; i < 9; i++)
            acc = fmaf(s_spw[o * 9 + i], s_gn[(i * 32 + ai) * 17 + Bi], acc);
        s_lg[m * 17 + Bi] = 2.0f * s_lg[m * 17 + Bi] + gelu_fast(acc);
    }
    __syncthreads();

    // S5: softmax over Bi; au sum
    for (int m = tid; m < 288; m += 256) {
        float* row = s_lg + m * 17;
        float mx = row[0];
        #pragma unroll
        for (int i = 1; i < 16; i++) mx = fmaxf(mx, row[i]);
        float s = 0.0f;
        #pragma unroll
        for (int i = 0; i < 16; i++) { float e = __expf(row[i] - mx); row[i] = e; s += e; }
        float inv = 1.0f / s;
        #pragma unroll
        for (int i = 0; i < 16; i++) row[i] *= inv;
    }
    if (tid < 32) {
        float p = 0.0f;
        for (int m = tid; m < 288; m += 32) p += s_au[m];
        #pragma unroll
        for (int o = 16; o; o >>= 1) p += __shfl_xor_sync(0xffffffffu, p, o);
        if (tid == 0) *s_aus = p;
    }
    __syncthreads();

    // S6: ar and ar_sum
    {
        int Bi = tid & 15, ck = tid >> 4;
        float p = 0.0f;
        #pragma unroll 2
        for (int r = 0; r < 18; r++) {
            int m = ck * 18 + r;
            float ar = s_au[m] * s_lg[m * 17 + Bi];
            s_gn[m * 17 + Bi] = ar;
            p += ar;
        }
        s_red[ck * 16 + Bi] = p;
    }
    __syncthreads();
    if (tid < 16) {
        float s = 0.0f;
        #pragma unroll
        for (int c = 0; c < 16; c++) s += s_red[c * 16 + tid];
        s_ars[tid] = s;
        out[((size_t)b * 16 + tid) * LL + l] = s / (*s_aus);
    }
    __syncthreads();

    // S7: coeff; write C[m][col]
    for (int idx = tid; idx < 4608; idx += 256) {
        int m = idx >> 4, Bi = idx & 15;
        float cf = s_gn[m * 17 + Bi] / s_ars[Bi];
        s_gn[m * 17 + Bi] = cf;
        g_C[(size_t)m * NCOL + (size_t)bl * 16 + Bi] = cf;
    }
    __syncthreads();

    // S8: p = gelu(pu@W^T+b); po_base = sum coeff*p; write P bf16 FLAT [d][col][k].
    // Packed stores: 8 consecutive m per STG.128; pu read via broadcast LDS.128.
    {
        int Bi = tid & 15, d = tid >> 4;
        int e = Bi * 16 + d;
        float W[16];
        #pragma unroll
        for (int c = 0; c < 16; c++) W[c] = mpose_w[e * 16 + c];
        float bs = mpose_b[e];
        float acc = 0.0f;
        uint4* Pd4 = reinterpret_cast<uint4*>(
            g_Pb + ((size_t)d * NCOL + (size_t)bl * 16 + Bi) * KP);
        for (int g = 0; g < 36; g++) {            // 36 * 8 = 288 m-values
            uint32_t pk[4];
            #pragma unroll
            for (int pp = 0; pp < 4; pp++) {
                float vv[2];
                #pragma unroll
                for (int h = 0; h < 2; h++) {
                    int m = g * 8 + pp * 2 + h;
                    const float4* pv4 = reinterpret_cast<const float4*>(s_pu + m * PUS);
                    float4 p0 = pv4[0], p1 = pv4[1], p2 = pv4[2], p3 = pv4[3];
                    float v = bs;
                    v = fmaf(p0.x, W[0],  v); v = fmaf(p0.y, W[1],  v);
                    v = fmaf(p0.z, W[2],  v); v = fmaf(p0.w, W[3],  v);
                    v = fmaf(p1.x, W[4],  v); v = fmaf(p1.y, W[5],  v);
                    v = fmaf(p1.z, W[6],  v); v = fmaf(p1.w, W[7],  v);
                    v = fmaf(p2.x, W[8],  v); v = fmaf(p2.y, W[9],  v);
                    v = fmaf(p2.z, W[10], v); v = fmaf(p2.w, W[11], v);
                    v = fmaf(p3.x, W[12], v); v = fmaf(p3.y, W[13], v);
                    v = fmaf(p3.z, W[14], v); v = fmaf(p3.w, W[15], v);
                    float pval = gelu_fast(v);
                    acc = fmaf(s_gn[m * 17 + Bi], pval, acc);
                    vv[h] = pval;
                }
                __nv_bfloat162 h2 = __floats2bfloat162_rn(vv[0], vv[1]);
                pk[pp] = *reinterpret_cast<uint32_t*>(&h2);
            }
            Pd4[g] = make_uint4(pk[0], pk[1], pk[2], pk[3]);
        }
        // zero pad k = 288..319
        uint4 z = make_uint4(0, 0, 0, 0);
        Pd4[36] = z; Pd4[37] = z; Pd4[38] = z; Pd4[39] = z;
        out[12544 + (size_t)b * 50176 + (size_t)e * LL + l] = acc;
    }
}

// ============ kernel 3: mma.sync bf16 circulant GEMM + fused coeff reduction ============
// EXACT R5 configuration (measured 153 us): flat P, launch_bounds(256,2), paired B ldsm.
#define SA_STG 12288            // 96 rows x 128B
#define SB_STG 16384            // 128 rows x 128B
#define GEMM_SMEM (2 * SA_STG + 2 * SB_STG)

__global__ void __launch_bounds__(256, 2) k_gemm_mma(float* __restrict__ out) {
    extern __shared__ __align__(128) char smemc[];
    const uint32_t sb = smem_u32(smemc);
    const int tid  = threadIdx.x;
    const int lane = tid & 31;
    const int wid  = tid >> 5;
    const int wm   = wid >> 2;          // 0..1  (m-warp, 48 rows each)
    const int wn   = wid & 3;           // 0..3  (n-warp, 32 cols each)

    const int d    = blockIdx.z;
    const int m0   = blockIdx.y * 96;
    const int col0 = blockIdx.x * 128;

    const __nv_bfloat16* Hg = g_Hb + ((size_t)d * 288 + m0) * KP;
    const __nv_bfloat16* Pg = g_Pb + ((size_t)d * NCOL + col0) * KP;

    float acc[3][4][4];
    #pragma unroll
    for (int r = 0; r < 3; r++)
        #pragma unroll
        for (int q = 0; q < 4; q++)
            #pragma unroll
            for (int i = 0; i < 4; i++) acc[r][q][i] = 0.0f;

    // ---- chunk loader: chunk c (k in [c*64, c*64+64)) into stage s ----
    auto load_chunk = [&](int c, int s) {
        uint32_t abase = sb + s * SA_STG;
        uint32_t bbase = sb + 2 * SA_STG + s * SB_STG;
        #pragma unroll
        for (int it = 0; it < 3; it++) {          // 96 rows x 8 chunks = 768
            int i = tid + it * 256;
            int row = i >> 3, u = i & 7;
            cp_async16(abase + row * 128 + ((u ^ (row & 7)) << 4),
                       Hg + (size_t)row * KP + c * 64 + u * 8);
        }
        #pragma unroll
        for (int it = 0; it < 4; it++) {          // 128 rows x 8 chunks = 1024
            int i = tid + it * 256;
            int row = i >> 3, u = i & 7;
            cp_async16(bbase + row * 128 + ((u ^ (row & 7)) << 4),
                       Pg + (size_t)row * KP + c * 64 + u * 8);
        }
        CP_COMMIT();
    };

    load_chunk(0, 0);

    // per-lane ldmatrix address components
    const int a_row_l = wm * 48 + (lane & 15);          // + r*16
    const int a_chalf = lane >> 4;                      // k-half select
    // B loads paired: one ldsm_x4 covers q-pair (2 n-fragments x 2 k-halves)
    const int b_row_l = wn * 32 + ((lane >> 4) << 3) + (lane & 7);   // + qp*16
    const int b_chalf = (lane >> 3) & 1;

    for (int c = 0; c < 5; c++) {
        if (c < 4) load_chunk(c + 1, (c + 1) & 1);
        if (c < 4) CP_WAIT(1); else CP_WAIT(0);
        __syncthreads();

        uint32_t Ab = sb + (c & 1) * SA_STG;
        uint32_t Bb = sb + 2 * SA_STG + (c & 1) * SB_STG;

        #pragma unroll
        for (int ks = 0; ks < 4; ks++) {
            uint32_t a[3][4], bfrag[4][2];
            #pragma unroll
            for (int r = 0; r < 3; r++) {
                int row = a_row_l + r * 16;
                int c16 = ks * 2 + a_chalf;
                ldsm_x4(a[r][0], a[r][1], a[r][2], a[r][3],
                        Ab + row * 128 + (((c16 ^ (row & 7)) & 7) << 4));
            }
            #pragma unroll
            for (int qp = 0; qp < 2; qp++) {
                int row = b_row_l + qp * 16;
                int c16 = ks * 2 + b_chalf;
                ldsm_x4(bfrag[qp * 2][0], bfrag[qp * 2][1],
                        bfrag[qp * 2 + 1][0], bfrag[qp * 2 + 1][1],
                        Bb + row * 128 + (((c16 ^ (row & 7)) & 7) << 4));
            }
            #pragma unroll
            for (int r = 0; r < 3; r++)
                #pragma unroll
                for (int q = 0; q < 4; q++)
                    mma_bf16(acc[r][q], a[r], bfrag[q]);
        }
        __syncthreads();
    }

    // ---- fused epilogue: s[col] = sum_m C[m,col] * D[m,col] ----
    float s[8];
    #pragma unroll
    for (int j = 0; j < 8; j++) s[j] = 0.0f;
    const int colb = col0 + wn * 32 + ((lane & 3) << 1);
    #pragma unroll
    for (int r = 0; r < 3; r++) {
        #pragma unroll
        for (int half = 0; half < 2; half++) {
            int m = m0 + wm * 48 + r * 16 + (lane >> 2) + half * 8;
            const float* Crow = g_C + (size_t)m * NCOL;
            #pragma unroll
            for (int q = 0; q < 4; q++) {
                s[q * 2 + 0] = fmaf(Crow[colb + q * 8 + 0], acc[r][q][half * 2 + 0], s[q * 2 + 0]);
                s[q * 2 + 1] = fmaf(Crow[colb + q * 8 + 1], acc[r][q][half * 2 + 1], s[q * 2 + 1]);
            }
        }
    }
    #pragma unroll
    for (int off = 4; off < 32; off <<= 1)
        #pragma unroll
        for (int j = 0; j < 8; j++) s[j] += __shfl_xor_sync(0xffffffffu, s[j], off);

    if (lane < 4) {
        #pragma unroll
        for (int q = 0; q < 4; q++) {
            #pragma unroll
            for (int j = 0; j < 2; j++) {
                int col = col0 + wn * 32 + q * 8 + lane * 2 + j;
                int bl = col >> 4, Bi = col & 15;
                int bb = bl / LL, ll = bl % LL;
                atomicAdd(&out[12544 + (size_t)bb * 50176 + (size_t)(Bi * 16 + d) * LL + ll],
                          s[q * 2 + j]);
            }
        }
    }
}

// ---------------- launch ----------------
extern "C" void kernel_launch(void* const* d_in, const int* in_sizes, int n_in,
                              void* d_out, int out_size) {
    const float* a     = (const float*)d_in[0];
    const float* pose  = (const float*)d_in[1];
    const float* mw    = (const float*)d_in[2];
    const float* mb    = (const float*)d_in[3];
    const float* cw2   = (const float*)d_in[4];
    const float* cb2   = (const float*)d_in[5];
    const float* cplx  = (const float*)d_in[6];
    const float* gam   = (const float*)d_in[7];
    const float* bet   = (const float*)d_in[8];
    const float* spw   = (const float*)d_in[9];
    const float* spb   = (const float*)d_in[10];
    float* out = (float*)d_out;

    size_t smem_floats = (size_t)288 * PUS + 2 * 288 * 17 + 16 * 17 + 16 + 81 + 16 + 32 + 32 + 288 + 144 + 144 + 256 + 16 + 1;
    size_t smem_bytes = smem_floats * sizeof(float);
    cudaFuncSetAttribute(k_main, cudaFuncAttributeMaxDynamicSharedMemorySize, (int)smem_bytes);
    cudaFuncSetAttribute(k_gemm_mma, cudaFuncAttributeMaxDynamicSharedMemorySize, GEMM_SMEM);

    k_build_h<<<1, 288>>>(cplx);
    k_expand_Hb<<<dim3(288, 16), 320>>>();
    k_main<<<NBL, 256, smem_bytes>>>(a, pose, mw, mb, cw2, cb2, gam, bet, spw, spb, out);
    k_gemm_mma<<<dim3(NCOL / 128, 288 / 96, 16), 256, GEMM_SMEM>>>(out);
}

// round 9
// speedup vs baseline: 1.1411x; 1.0937x over previous
#include <cuda_runtime.h>
#include <cuda_bf16.h>
#include <math.h>
#include <stdint.h>

// ---------------- problem constants ----------------
#define AA    32
#define CC    16
#define KKn   9
#define KKA   288
#define NB    16      // Bc
#define ND    16      // D
#define NE    256     // Bc*D
#define HW    14
#define LL    196
#define NBSZ  4
#define NBL   784     // NBSZ*LL
#define NCOL  12544   // NBL*NB
#define KKA2  145
#define KP    320     // padded K for tensor GEMM (5 x 64)
#define PUS   20      // s_pu row stride (floats): 80B, 16B-aligned for LDS.128

// ---------------- scratch (static device mem; no allocs allowed) ----------------
__device__ float g_h[16 * 288];                                        //  18 KB
__device__ __align__(1024) __nv_bfloat16 g_Hb[(size_t)16 * 288 * KP];  //  2.95 MB  H circulant bf16 [d][m][k]
__device__ __align__(1024) __nv_bfloat16 g_Pb[(size_t)16 * NCOL * KP]; //  128 MB   P bf16 [d][col][k] (FLAT)
__device__ float g_C[(size_t)288 * NCOL];                              //  14.4 MB  coeff [m][col]

// fast exact-gelu via Abramowitz-Stegun 7.1.26 erf (|abs err| <= 1.5e-7)
__device__ __forceinline__ float gelu_fast(float v) {
    float x  = v * 0.70710678118654752f;
    float ax = fabsf(x);
    float t  = __fdividef(1.0f, fmaf(0.3275911f, ax, 1.0f));
    float poly = t * fmaf(t, fmaf(t, fmaf(t, fmaf(t, 1.061405429f, -1.453152027f),
                                          1.421413741f), -0.284496736f), 0.254829592f);
    float r  = 1.0f - poly * __expf(-ax * ax);
    float erfv = copysignf(r, x);
    return 0.5f * v * (1.0f + erfv);
}

// ---------------- PTX helpers (sm_100 baseline: cp.async / ldmatrix / mma.sync) ----------------
__device__ __forceinline__ uint32_t smem_u32(const void* p) {
    uint32_t a;
    asm("{ .reg .u64 t; cvta.to.shared.u64 t, %1; cvt.u32.u64 %0, t; }" : "=r"(a) : "l"(p));
    return a;
}
__device__ __forceinline__ void cp_async16(uint32_t saddr, const void* gaddr) {
    asm volatile("cp.async.cg.shared.global [%0], [%1], 16;" :: "r"(saddr), "l"(gaddr) : "memory");
}
#define CP_COMMIT() asm volatile("cp.async.commit_group;" ::: "memory")
#define CP_WAIT(n)  asm volatile("cp.async.wait_group %0;" :: "n"(n) : "memory")

__device__ __forceinline__ void ldsm_x4(uint32_t& r0, uint32_t& r1, uint32_t& r2, uint32_t& r3,
                                        uint32_t addr) {
    asm volatile("ldmatrix.sync.aligned.m8n8.x4.shared.b16 {%0,%1,%2,%3}, [%4];"
                 : "=r"(r0), "=r"(r1), "=r"(r2), "=r"(r3) : "r"(addr));
}
__device__ __forceinline__ void mma_bf16(float* d, const uint32_t* a, const uint32_t* b) {
    asm volatile("mma.sync.aligned.m16n8k16.row.col.f32.bf16.bf16.f32 "
                 "{%0,%1,%2,%3}, {%4,%5,%6,%7}, {%8,%9}, {%0,%1,%2,%3};"
                 : "+f"(d[0]), "+f"(d[1]), "+f"(d[2]), "+f"(d[3])
                 : "r"(a[0]), "r"(a[1]), "r"(a[2]), "r"(a[3]), "r"(b[0]), "r"(b[1]));
}

// ============ kernel 0: h[d][t] = irfft(W_d)[t] — one block per d ============
__global__ void k_build_h(const float* __restrict__ cw) {
    __shared__ float ct[288], st[288];
    int t = threadIdx.x;  // 288 threads
    int d = blockIdx.x;   // 16 blocks
    float ang = 6.283185307179586f * (float)t * (1.0f / 288.0f);
    ct[t] = cosf(ang);
    st[t] = sinf(ang);
    __syncthreads();
    float wr0  = cw[(0 * 16 + d) * 2];
    float wnyq = cw[(144 * 16 + d) * 2];
    float acc = wr0 + ((t & 1) ? -wnyq : wnyq);
    float s2 = 0.0f;
    int idx = 0;
    for (int k = 1; k <= 143; k++) {
        idx += t; if (idx >= 288) idx -= 288;
        float wr = cw[(k * 16 + d) * 2];
        float wi = cw[(k * 16 + d) * 2 + 1];
        s2 += wr * ct[idx] - wi * st[idx];
    }
    g_h[d * 288 + t] = (acc + 2.0f * s2) * (1.0f / 288.0f);
}

// ============ kernel 1: H bf16 circulant [d][m][k<=320], zero padded ============
__global__ void k_expand_Hb() {
    int m = blockIdx.x;      // 288
    int d = blockIdx.y;      // 16
    int j = threadIdx.x;     // 320
    float v = 0.0f;
    if (j < 288) {
        int t = m - j; if (t < 0) t += 288;
        v = g_h[d * 288 + t];
    }
    g_Hb[((size_t)d * 288 + m) * KP + j] = __float2bfloat16(v);
}

// ============ kernel 2: per-position producer ============
extern __shared__ float smem_dyn[];
__global__ void __launch_bounds__(256) k_main(
    const float* __restrict__ a_in, const float* __restrict__ pose,
    const float* __restrict__ mpose_w, const float* __restrict__ mpose_b,
    const float* __restrict__ cpose2_w, const float* __restrict__ cpose2_b,
    const float* __restrict__ ln_gamma, const float* __restrict__ ln_beta,
    const float* __restrict__ sp_w, const float* __restrict__ sp_b,
    float* __restrict__ out)
{
    float* s_pu  = smem_dyn;               // [288][20]  (16B-aligned rows)
    float* s_lg  = s_pu  + 288 * PUS;      // [288][17]
    float* s_gn  = s_lg  + 288 * 17;       // [288][17]
    float* s_cw  = s_gn  + 288 * 17;       // [16][17]
    float* s_cb  = s_cw  + 16 * 17;
    float* s_spw = s_cb  + 16;
    float* s_spb = s_spw + 81;
    float* s_gam = s_spb + 16;
    float* s_bet = s_gam + 32;
    float* s_au  = s_bet + 32;
    float* s_mu  = s_au  + 288;
    float* s_rs  = s_mu  + 144;
    float* s_red = s_rs  + 144;
    float* s_ars = s_red + 256;
    float* s_aus = s_ars + 16;

    const int tid = threadIdx.x;
    const int bl = blockIdx.x;
    const int b = bl / LL, l = bl % LL;
    const int y = l / HW, x = l % HW;

    {
        int Bi = tid >> 4, c = tid & 15;
        s_cw[Bi * 17 + c] = cpose2_w[tid];
        if (tid < 16)  s_cb[tid]  = cpose2_b[tid];
        if (tid < 81)  s_spw[tid] = sp_w[tid];
        if (tid < 9)   s_spb[tid] = sp_b[tid];
        if (tid < 32)  s_gam[tid] = ln_gamma[tid];
        if (tid >= 32 && tid < 64) s_bet[tid - 32] = ln_beta[tid - 32];
    }

    // S1: gather pu and au
    for (int idx = tid; idx < 4608; idx += 256) {
        int m = idx >> 4, c = idx & 15;
        int kk = m >> 5, ai = m & 31;
        int py = y + kk / 3 - 1, px = x + kk % 3 - 1;
        float v = 0.0f;
        if ((unsigned)py < 14u && (unsigned)px < 14u)
            v = pose[(((size_t)b * 512 + (size_t)ai * 16 + c) * 14 + py) * 14 + px];
        s_pu[m * PUS + c] = v;
    }
    for (int m = tid; m < 288; m += 256) {
        int kk = m >> 5, ai = m & 31;
        int py = y + kk / 3 - 1, px = x + kk % 3 - 1;
        float v = 0.0f;
        if ((unsigned)py < 14u && (unsigned)px < 14u)
            v = a_in[(((size_t)b * 32 + ai) * 14 + py) * 14 + px];
        s_au[m] = v;
    }
    __syncthreads();

    // S2: logits (vectorized pu reads)
    for (int idx = tid; idx < 4608; idx += 256) {
        int m = idx >> 4, Bi = idx & 15;
        const float4* pv4 = reinterpret_cast<const float4*>(s_pu + m * PUS);
        const float* pw = s_cw + Bi * 17;
        float4 p0 = pv4[0], p1 = pv4[1], p2 = pv4[2], p3 = pv4[3];
        float acc = s_cb[Bi];
        acc = fmaf(p0.x, pw[0],  acc); acc = fmaf(p0.y, pw[1],  acc);
        acc = fmaf(p0.z, pw[2],  acc); acc = fmaf(p0.w, pw[3],  acc);
        acc = fmaf(p1.x, pw[4],  acc); acc = fmaf(p1.y, pw[5],  acc);
        acc = fmaf(p1.z, pw[6],  acc); acc = fmaf(p1.w, pw[7],  acc);
        acc = fmaf(p2.x, pw[8],  acc); acc = fmaf(p2.y, pw[9],  acc);
        acc = fmaf(p2.z, pw[10], acc); acc = fmaf(p2.w, pw[11], acc);
        acc = fmaf(p3.x, pw[12], acc); acc = fmaf(p3.y, pw[13], acc);
        acc = fmaf(p3.z, pw[14], acc); acc = fmaf(p3.w, pw[15], acc);
        s_lg[m * 17 + Bi] = acc;
    }
    __syncthreads();

    // S3: LayerNorm over a
    if (tid < 144) {
        int kk = tid >> 4, Bi = tid & 15;
        float s = 0.0f, s2 = 0.0f;
        #pragma unroll 4
        for (int ai = 0; ai < 32; ai++) {
            float v = s_lg[(kk * 32 + ai) * 17 + Bi];
            s += v; s2 += v * v;
        }
        float mu = s * (1.0f / 32.0f);
        float var = s2 * (1.0f / 32.0f) - mu * mu;
        s_mu[tid] = mu;
        s_rs[tid] = rsqrtf(var + 1e-5f);
    }
    __syncthreads();
    for (int idx = tid; idx < 4608; idx += 256) {
        int m = idx >> 4, Bi = idx & 15;
        int kk = m >> 5, ai = m & 31;
        float v = s_lg[m * 17 + Bi];
        s_gn[m * 17 + Bi] = (v - s_mu[kk * 16 + Bi]) * s_rs[kk * 16 + Bi] * s_gam[ai] + s_bet[ai];
    }
    __syncthreads();

    // S4: spatial gate
    for (int idx = tid; idx < 4608; idx += 256) {
        int m = idx >> 4, Bi = idx & 15;
        int o = m >> 5, ai = m & 31;
        float acc = s_spb[o];
        #pragma unroll
        for (int i = 0; i < 9; i++)
            acc = fmaf(s_spw[o * 9 + i], s_gn[(i * 32 + ai) * 17 + Bi], acc);
        s_lg[m * 17 + Bi] = 2.0f * s_lg[m * 17 + Bi] + gelu_fast(acc);
    }
    __syncthreads();

    // S5: softmax over Bi; au sum
    for (int m = tid; m < 288; m += 256) {
        float* row = s_lg + m * 17;
        float mx = row[0];
        #pragma unroll
        for (int i = 1; i < 16; i++) mx = fmaxf(mx, row[i]);
        float s = 0.0f;
        #pragma unroll
        for (int i = 0; i < 16; i++) { float e = __expf(row[i] - mx); row[i] = e; s += e; }
        float inv = 1.0f / s;
        #pragma unroll
        for (int i = 0; i < 16; i++) row[i] *= inv;
    }
    if (tid < 32) {
        float p = 0.0f;
        for (int m = tid; m < 288; m += 32) p += s_au[m];
        #pragma unroll
        for (int o = 16; o; o >>= 1) p += __shfl_xor_sync(0xffffffffu, p, o);
        if (tid == 0) *s_aus = p;
    }
    __syncthreads();

    // S6: ar and ar_sum
    {
        int Bi = tid & 15, ck = tid >> 4;
        float p = 0.0f;
        #pragma unroll 2
        for (int r = 0; r < 18; r++) {
            int m = ck * 18 + r;
            float ar = s_au[m] * s_lg[m * 17 + Bi];
            s_gn[m * 17 + Bi] = ar;
            p += ar;
        }
        s_red[ck * 16 + Bi] = p;
    }
    __syncthreads();
    if (tid < 16) {
        float s = 0.0f;
        #pragma unroll
        for (int c = 0; c < 16; c++) s += s_red[c * 16 + tid];
        s_ars[tid] = s;
        out[((size_t)b * 16 + tid) * LL + l] = s / (*s_aus);
    }
    __syncthreads();

    // S7: coeff; write C[m][col]
    for (int idx = tid; idx < 4608; idx += 256) {
        int m = idx >> 4, Bi = idx & 15;
        float cf = s_gn[m * 17 + Bi] / s_ars[Bi];
        s_gn[m * 17 + Bi] = cf;
        g_C[(size_t)m * NCOL + (size_t)bl * 16 + Bi] = cf;
    }
    __syncthreads();

    // S8: p = gelu(pu@W^T+b); po_base = sum coeff*p; write P bf16 FLAT [d][col][k].
    {
        int Bi = tid & 15, d = tid >> 4;
        int e = Bi * 16 + d;
        float W[16];
        #pragma unroll
        for (int c = 0; c < 16; c++) W[c] = mpose_w[e * 16 + c];
        float bs = mpose_b[e];
        float acc = 0.0f;
        uint4* Pd4 = reinterpret_cast<uint4*>(
            g_Pb + ((size_t)d * NCOL + (size_t)bl * 16 + Bi) * KP);
        for (int g = 0; g < 36; g++) {            // 36 * 8 = 288 m-values
            uint32_t pk[4];
            #pragma unroll
            for (int pp = 0; pp < 4; pp++) {
                float vv[2];
                #pragma unroll
                for (int h = 0; h < 2; h++) {
                    int m = g * 8 + pp * 2 + h;
                    const float4* pv4 = reinterpret_cast<const float4*>(s_pu + m * PUS);
                    float4 p0 = pv4[0], p1 = pv4[1], p2 = pv4[2], p3 = pv4[3];
                    float v = bs;
                    v = fmaf(p0.x, W[0],  v); v = fmaf(p0.y, W[1],  v);
                    v = fmaf(p0.z, W[2],  v); v = fmaf(p0.w, W[3],  v);
                    v = fmaf(p1.x, W[4],  v); v = fmaf(p1.y, W[5],  v);
                    v = fmaf(p1.z, W[6],  v); v = fmaf(p1.w, W[7],  v);
                    v = fmaf(p2.x, W[8],  v); v = fmaf(p2.y, W[9],  v);
                    v = fmaf(p2.z, W[10], v); v = fmaf(p2.w, W[11], v);
                    v = fmaf(p3.x, W[12], v); v = fmaf(p3.y, W[13], v);
                    v = fmaf(p3.z, W[14], v); v = fmaf(p3.w, W[15], v);
                    float pval = gelu_fast(v);
                    acc = fmaf(s_gn[m * 17 + Bi], pval, acc);
                    vv[h] = pval;
                }
                __nv_bfloat162 h2 = __floats2bfloat162_rn(vv[0], vv[1]);
                pk[pp] = *reinterpret_cast<uint32_t*>(&h2);
            }
            Pd4[g] = make_uint4(pk[0], pk[1], pk[2], pk[3]);
        }
        // zero pad k = 288..319
        uint4 z = make_uint4(0, 0, 0, 0);
        Pd4[36] = z; Pd4[37] = z; Pd4[38] = z; Pd4[39] = z;
        out[12544 + (size_t)b * 50176 + (size_t)e * LL + l] = acc;
    }
}

// ============ kernel 3: mma.sync bf16 circulant GEMM + fused coeff reduction ============
// grid (49 col-tiles, 3 m-tiles, 16 d), 256 threads (8 warps: 2 m-warps x 4 n-warps).
// Tile: m=96, col=256. Per warp: 48 rows (3 A frags) x 64 cols (8 B frags) -> 24 mma /
// 7 ldsm_x4 per ks (ratio 3.43 vs 2.4 before) to cut L1 (81% busy in R8).
#define SA_STG 12288            // 96 rows x 128B
#define SB_STG 32768            // 256 rows x 128B
#define GEMM_SMEM (2 * SA_STG + 2 * SB_STG)

__global__ void __launch_bounds__(256, 2) k_gemm_mma(float* __restrict__ out) {
    extern __shared__ __align__(128) char smemc[];
    const uint32_t sb = smem_u32(smemc);
    const int tid  = threadIdx.x;
    const int lane = tid & 31;
    const int wid  = tid >> 5;
    const int wm   = wid >> 2;          // 0..1  (m-warp, 48 rows each)
    const int wn   = wid & 3;           // 0..3  (n-warp, 64 cols each)

    const int d    = blockIdx.z;
    const int m0   = blockIdx.y * 96;
    const int col0 = blockIdx.x * 256;

    const __nv_bfloat16* Hg = g_Hb + ((size_t)d * 288 + m0) * KP;
    const __nv_bfloat16* Pg = g_Pb + ((size_t)d * NCOL + col0) * KP;

    float acc[3][8][4];
    #pragma unroll
    for (int r = 0; r < 3; r++)
        #pragma unroll
        for (int q = 0; q < 8; q++)
            #pragma unroll
            for (int i = 0; i < 4; i++) acc[r][q][i] = 0.0f;

    // ---- chunk loader: chunk c (k in [c*64, c*64+64)) into stage s ----
    auto load_chunk = [&](int c, int s) {
        uint32_t abase = sb + s * SA_STG;
        uint32_t bbase = sb + 2 * SA_STG + s * SB_STG;
        #pragma unroll
        for (int it = 0; it < 3; it++) {          // 96 rows x 8 chunks = 768
            int i = tid + it * 256;
            int row = i >> 3, u = i & 7;
            cp_async16(abase + row * 128 + ((u ^ (row & 7)) << 4),
                       Hg + (size_t)row * KP + c * 64 + u * 8);
        }
        #pragma unroll
        for (int it = 0; it < 8; it++) {          // 256 rows x 8 chunks = 2048
            int i = tid + it * 256;
            int row = i >> 3, u = i & 7;
            cp_async16(bbase + row * 128 + ((u ^ (row & 7)) << 4),
                       Pg + (size_t)row * KP + c * 64 + u * 8);
        }
        CP_COMMIT();
    };

    load_chunk(0, 0);

    // per-lane ldmatrix address components
    const int a_row_l = wm * 48 + (lane & 15);          // + r*16
    const int a_chalf = lane >> 4;                      // k-half select
    // B loads paired: one ldsm_x4 covers 16 rows (2 n-frags x 2 k-halves)
    const int b_row_l = wn * 64 + ((lane >> 4) << 3) + (lane & 7);   // + bp*16
    const int b_chalf = (lane >> 3) & 1;

    for (int c = 0; c < 5; c++) {
        if (c < 4) load_chunk(c + 1, (c + 1) & 1);
        if (c < 4) CP_WAIT(1); else CP_WAIT(0);
        __syncthreads();

        uint32_t Ab = sb + (c & 1) * SA_STG;
        uint32_t Bb = sb + 2 * SA_STG + (c & 1) * SB_STG;

        #pragma unroll
        for (int ks = 0; ks < 4; ks++) {
            uint32_t a[3][4], bfrag[8][2];
            #pragma unroll
            for (int r = 0; r < 3; r++) {
                int row = a_row_l + r * 16;
                int c16 = ks * 2 + a_chalf;
                ldsm_x4(a[r][0], a[r][1], a[r][2], a[r][3],
                        Ab + row * 128 + (((c16 ^ (row & 7)) & 7) << 4));
            }
            #pragma unroll
            for (int bp = 0; bp < 4; bp++) {
                int row = b_row_l + bp * 16;
                int c16 = ks * 2 + b_chalf;
                ldsm_x4(bfrag[bp * 2][0], bfrag[bp * 2][1],
                        bfrag[bp * 2 + 1][0], bfrag[bp * 2 + 1][1],
                        Bb + row * 128 + (((c16 ^ (row & 7)) & 7) << 4));
            }
            #pragma unroll
            for (int r = 0; r < 3; r++)
                #pragma unroll
                for (int q = 0; q < 8; q++)
                    mma_bf16(acc[r][q], a[r], bfrag[q]);
        }
        __syncthreads();
    }

    // ---- fused epilogue: s[col] = sum_m C[m,col] * D[m,col] ----
    float s[16];
    #pragma unroll
    for (int j = 0; j < 16; j++) s[j] = 0.0f;
    const int colb = col0 + wn * 64 + ((lane & 3) << 1);
    #pragma unroll
    for (int r = 0; r < 3; r++) {
        #pragma unroll
        for (int half = 0; half < 2; half++) {
            int m = m0 + wm * 48 + r * 16 + (lane >> 2) + half * 8;
            const float* Crow = g_C + (size_t)m * NCOL;
            #pragma unroll
            for (int q = 0; q < 8; q++) {
                s[q * 2 + 0] = fmaf(Crow[colb + q * 8 + 0], acc[r][q][half * 2 + 0], s[q * 2 + 0]);
                s[q * 2 + 1] = fmaf(Crow[colb + q * 8 + 1], acc[r][q][half * 2 + 1], s[q * 2 + 1]);
            }
        }
    }
    #pragma unroll
    for (int off = 4; off < 32; off <<= 1)
        #pragma unroll
        for (int j = 0; j < 16; j++) s[j] += __shfl_xor_sync(0xffffffffu, s[j], off);

    if (lane < 4) {
        #pragma unroll
        for (int q = 0; q < 8; q++) {
            #pragma unroll
            for (int j = 0; j < 2; j++) {
                int col = col0 + wn * 64 + q * 8 + lane * 2 + j;
                int bl = col >> 4, Bi = col & 15;
                int bb = bl / LL, ll = bl % LL;
                atomicAdd(&out[12544 + (size_t)bb * 50176 + (size_t)(Bi * 16 + d) * LL + ll],
                          s[q * 2 + j]);
            }
        }
    }
}

// ---------------- launch ----------------
extern "C" void kernel_launch(void* const* d_in, const int* in_sizes, int n_in,
                              void* d_out, int out_size) {
    const float* a     = (const float*)d_in[0];
    const float* pose  = (const float*)d_in[1];
    const float* mw    = (const float*)d_in[2];
    const float* mb    = (const float*)d_in[3];
    const float* cw2   = (const float*)d_in[4];
    const float* cb2   = (const float*)d_in[5];
    const float* cplx  = (const float*)d_in[6];
    const float* gam   = (const float*)d_in[7];
    const float* bet   = (const float*)d_in[8];
    const float* spw   = (const float*)d_in[9];
    const float* spb   = (const float*)d_in[10];
    float* out = (float*)d_out;

    size_t smem_floats = (size_t)288 * PUS + 2 * 288 * 17 + 16 * 17 + 16 + 81 + 16 + 32 + 32 + 288 + 144 + 144 + 256 + 16 + 1;
    size_t smem_bytes = smem_floats * sizeof(float);
    cudaFuncSetAttribute(k_main, cudaFuncAttributeMaxDynamicSharedMemorySize, (int)smem_bytes);
    cudaFuncSetAttribute(k_gemm_mma, cudaFuncAttributeMaxDynamicSharedMemorySize, GEMM_SMEM);

    k_build_h<<<16, 288>>>(cplx);
    k_expand_Hb<<<dim3(288, 16), 320>>>();
    k_main<<<NBL, 256, smem_bytes>>>(a, pose, mw, mb, cw2, cb2, gam, bet, spw, spb, out);
    k_gemm_mma<<<dim3(NCOL / 256, 288 / 96, 16), 256, GEMM_SMEM>>>(out);
}

// round 10
// speedup vs baseline: 1.2708x; 1.1136x over previous
#include <cuda_runtime.h>
#include <cuda_bf16.h>
#include <math.h>
#include <stdint.h>

// ---------------- problem constants ----------------
#define AA    32
#define CC    16
#define KKn   9
#define KKA   288
#define NB    16      // Bc
#define ND    16      // D
#define NE    256     // Bc*D
#define HW    14
#define LL    196
#define NBSZ  4
#define NBL   784     // NBSZ*LL
#define NCOL  12544   // NBL*NB
#define KKA2  145
#define KP    320     // padded K for tensor GEMM (5 x 64)
#define PUS   20      // s_pu row stride (floats): 80B, 16B-aligned for LDS.128

// ---------------- scratch (static device mem; no allocs allowed) ----------------
__device__ float g_h[16 * 288];                                        //  18 KB
__device__ __align__(1024) __nv_bfloat16 g_Hb[(size_t)16 * 288 * KP];  //  2.95 MB  H circulant bf16 [d][m][k]
__device__ __align__(1024) __nv_bfloat16 g_Pb[(size_t)16 * NCOL * KP]; //  128 MB   P bf16 [d][col][k] (FLAT)
__device__ float g_C[(size_t)288 * NCOL];                              //  14.4 MB  coeff [m][col]

// fast exact-gelu via Abramowitz-Stegun 7.1.26 erf (|abs err| <= 1.5e-7)
__device__ __forceinline__ float gelu_fast(float v) {
    float x  = v * 0.70710678118654752f;
    float ax = fabsf(x);
    float t  = __fdividef(1.0f, fmaf(0.3275911f, ax, 1.0f));
    float poly = t * fmaf(t, fmaf(t, fmaf(t, fmaf(t, 1.061405429f, -1.453152027f),
                                          1.421413741f), -0.284496736f), 0.254829592f);
    float r  = 1.0f - poly * __expf(-ax * ax);
    float erfv = copysignf(r, x);
    return 0.5f * v * (1.0f + erfv);
}

// ---------------- PTX helpers (sm_100 baseline: cp.async / ldmatrix / mma.sync) ----------------
__device__ __forceinline__ uint32_t smem_u32(const void* p) {
    uint32_t a;
    asm("{ .reg .u64 t; cvta.to.shared.u64 t, %1; cvt.u32.u64 %0, t; }" : "=r"(a) : "l"(p));
    return a;
}
__device__ __forceinline__ void cp_async16(uint32_t saddr, const void* gaddr) {
    asm volatile("cp.async.cg.shared.global [%0], [%1], 16;" :: "r"(saddr), "l"(gaddr) : "memory");
}
#define CP_COMMIT() asm volatile("cp.async.commit_group;" ::: "memory")
#define CP_WAIT(n)  asm volatile("cp.async.wait_group %0;" :: "n"(n) : "memory")

__device__ __forceinline__ void ldsm_x4(uint32_t& r0, uint32_t& r1, uint32_t& r2, uint32_t& r3,
                                        uint32_t addr) {
    asm volatile("ldmatrix.sync.aligned.m8n8.x4.shared.b16 {%0,%1,%2,%3}, [%4];"
                 : "=r"(r0), "=r"(r1), "=r"(r2), "=r"(r3) : "r"(addr));
}
__device__ __forceinline__ void mma_bf16(float* d, const uint32_t* a, const uint32_t* b) {
    asm volatile("mma.sync.aligned.m16n8k16.row.col.f32.bf16.bf16.f32 "
                 "{%0,%1,%2,%3}, {%4,%5,%6,%7}, {%8,%9}, {%0,%1,%2,%3};"
                 : "+f"(d[0]), "+f"(d[1]), "+f"(d[2]), "+f"(d[3])
                 : "r"(a[0]), "r"(a[1]), "r"(a[2]), "r"(a[3]), "r"(b[0]), "r"(b[1]));
}

// ============ kernel 0: h[d][t] = irfft(W_d)[t] — one block per d ============
__global__ void k_build_h(const float* __restrict__ cw) {
    __shared__ float ct[288], st[288];
    int t = threadIdx.x;  // 288 threads
    int d = blockIdx.x;   // 16 blocks
    float ang = 6.283185307179586f * (float)t * (1.0f / 288.0f);
    ct[t] = cosf(ang);
    st[t] = sinf(ang);
    __syncthreads();
    float wr0  = cw[(0 * 16 + d) * 2];
    float wnyq = cw[(144 * 16 + d) * 2];
    float acc = wr0 + ((t & 1) ? -wnyq : wnyq);
    float s2 = 0.0f;
    int idx = 0;
    for (int k = 1; k <= 143; k++) {
        idx += t; if (idx >= 288) idx -= 288;
        float wr = cw[(k * 16 + d) * 2];
        float wi = cw[(k * 16 + d) * 2 + 1];
        s2 += wr * ct[idx] - wi * st[idx];
    }
    g_h[d * 288 + t] = (acc + 2.0f * s2) * (1.0f / 288.0f);
}

// ============ kernel 1: H bf16 circulant [d][m][k<=320], zero padded ============
__global__ void k_expand_Hb() {
    int m = blockIdx.x;      // 288
    int d = blockIdx.y;      // 16
    int j = threadIdx.x;     // 320
    float v = 0.0f;
    if (j < 288) {
        int t = m - j; if (t < 0) t += 288;
        v = g_h[d * 288 + t];
    }
    g_Hb[((size_t)d * 288 + m) * KP + j] = __float2bfloat16(v);
}

// ============ kernel 2: per-position producer ============
extern __shared__ float smem_dyn[];
__global__ void __launch_bounds__(256) k_main(
    const float* __restrict__ a_in, const float* __restrict__ pose,
    const float* __restrict__ mpose_w, const float* __restrict__ mpose_b,
    const float* __restrict__ cpose2_w, const float* __restrict__ cpose2_b,
    const float* __restrict__ ln_gamma, const float* __restrict__ ln_beta,
    const float* __restrict__ sp_w, const float* __restrict__ sp_b,
    float* __restrict__ out)
{
    float* s_pu  = smem_dyn;               // [288][20]  (16B-aligned rows)
    float* s_lg  = s_pu  + 288 * PUS;      // [288][17]
    float* s_gn  = s_lg  + 288 * 17;       // [288][17]
    float* s_cw  = s_gn  + 288 * 17;       // [16][17]
    float* s_cb  = s_cw  + 16 * 17;
    float* s_spw = s_cb  + 16;
    float* s_spb = s_spw + 81;
    float* s_gam = s_spb + 16;
    float* s_bet = s_gam + 32;
    float* s_au  = s_bet + 32;
    float* s_mu  = s_au  + 288;
    float* s_rs  = s_mu  + 144;
    float* s_red = s_rs  + 144;
    float* s_ars = s_red + 256;
    float* s_aus = s_ars + 16;

    const int tid = threadIdx.x;
    const int bl = blockIdx.x;
    const int b = bl / LL, l = bl % LL;
    const int y = l / HW, x = l % HW;

    {
        int Bi = tid >> 4, c = tid & 15;
        s_cw[Bi * 17 + c] = cpose2_w[tid];
        if (tid < 16)  s_cb[tid]  = cpose2_b[tid];
        if (tid < 81)  s_spw[tid] = sp_w[tid];
        if (tid < 9)   s_spb[tid] = sp_b[tid];
        if (tid < 32)  s_gam[tid] = ln_gamma[tid];
        if (tid >= 32 && tid < 64) s_bet[tid - 32] = ln_beta[tid - 32];
    }

    // S1: gather pu and au
    for (int idx = tid; idx < 4608; idx += 256) {
        int m = idx >> 4, c = idx & 15;
        int kk = m >> 5, ai = m & 31;
        int py = y + kk / 3 - 1, px = x + kk % 3 - 1;
        float v = 0.0f;
        if ((unsigned)py < 14u && (unsigned)px < 14u)
            v = pose[(((size_t)b * 512 + (size_t)ai * 16 + c) * 14 + py) * 14 + px];
        s_pu[m * PUS + c] = v;
    }
    for (int m = tid; m < 288; m += 256) {
        int kk = m >> 5, ai = m & 31;
        int py = y + kk / 3 - 1, px = x + kk % 3 - 1;
        float v = 0.0f;
        if ((unsigned)py < 14u && (unsigned)px < 14u)
            v = a_in[(((size_t)b * 32 + ai) * 14 + py) * 14 + px];
        s_au[m] = v;
    }
    __syncthreads();

    // S2: logits (vectorized pu reads)
    for (int idx = tid; idx < 4608; idx += 256) {
        int m = idx >> 4, Bi = idx & 15;
        const float4* pv4 = reinterpret_cast<const float4*>(s_pu + m * PUS);
        const float* pw = s_cw + Bi * 17;
        float4 p0 = pv4[0], p1 = pv4[1], p2 = pv4[2], p3 = pv4[3];
        float acc = s_cb[Bi];
        acc = fmaf(p0.x, pw[0],  acc); acc = fmaf(p0.y, pw[1],  acc);
        acc = fmaf(p0.z, pw[2],  acc); acc = fmaf(p0.w, pw[3],  acc);
        acc = fmaf(p1.x, pw[4],  acc); acc = fmaf(p1.y, pw[5],  acc);
        acc = fmaf(p1.z, pw[6],  acc); acc = fmaf(p1.w, pw[7],  acc);
        acc = fmaf(p2.x, pw[8],  acc); acc = fmaf(p2.y, pw[9],  acc);
        acc = fmaf(p2.z, pw[10], acc); acc = fmaf(p2.w, pw[11], acc);
        acc = fmaf(p3.x, pw[12], acc); acc = fmaf(p3.y, pw[13], acc);
        acc = fmaf(p3.z, pw[14], acc); acc = fmaf(p3.w, pw[15], acc);
        s_lg[m * 17 + Bi] = acc;
    }
    __syncthreads();

    // S3: LayerNorm over a
    if (tid < 144) {
        int kk = tid >> 4, Bi = tid & 15;
        float s = 0.0f, s2 = 0.0f;
        #pragma unroll 4
        for (int ai = 0; ai < 32; ai++) {
            float v = s_lg[(kk * 32 + ai) * 17 + Bi];
            s += v; s2 += v * v;
        }
        float mu = s * (1.0f / 32.0f);
        float var = s2 * (1.0f / 32.0f) - mu * mu;
        s_mu[tid] = mu;
        s_rs[tid] = rsqrtf(var + 1e-5f);
    }
    __syncthreads();
    for (int idx = tid; idx < 4608; idx += 256) {
        int m = idx >> 4, Bi = idx & 15;
        int kk = m >> 5, ai = m & 31;
        float v = s_lg[m * 17 + Bi];
        s_gn[m * 17 + Bi] = (v - s_mu[kk * 16 + Bi]) * s_rs[kk * 16 + Bi] * s_gam[ai] + s_bet[ai];
    }
    __syncthreads();

    // S4: spatial gate
    for (int idx = tid; idx < 4608; idx += 256) {
        int m = idx >> 4, Bi = idx & 15;
        int o = m >> 5, ai = m & 31;
        float acc = s_spb[o];
        #pragma unroll
        for (int i = 0; i < 9; i++)
            acc = fmaf(s_spw[o * 9 + i], s_gn[(i * 32 + ai) * 17 + Bi], acc);
        s_lg[m * 17 + Bi] = 2.0f * s_lg[m * 17 + Bi] + gelu_fast(acc);
    }
    __syncthreads();

    // S5: softmax over Bi; au sum
    for (int m = tid; m < 288; m += 256) {
        float* row = s_lg + m * 17;
        float mx = row[0];
        #pragma unroll
        for (int i = 1; i < 16; i++) mx = fmaxf(mx, row[i]);
        float s = 0.0f;
        #pragma unroll
        for (int i = 0; i < 16; i++) { float e = __expf(row[i] - mx); row[i] = e; s += e; }
        float inv = 1.0f / s;
        #pragma unroll
        for (int i = 0; i < 16; i++) row[i] *= inv;
    }
    if (tid < 32) {
        float p = 0.0f;
        for (int m = tid; m < 288; m += 32) p += s_au[m];
        #pragma unroll
        for (int o = 16; o; o >>= 1) p += __shfl_xor_sync(0xffffffffu, p, o);
        if (tid == 0) *s_aus = p;
    }
    __syncthreads();

    // S6: ar and ar_sum
    {
        int Bi = tid & 15, ck = tid >> 4;
        float p = 0.0f;
        #pragma unroll 2
        for (int r = 0; r < 18; r++) {
            int m = ck * 18 + r;
            float ar = s_au[m] * s_lg[m * 17 + Bi];
            s_gn[m * 17 + Bi] = ar;
            p += ar;
        }
        s_red[ck * 16 + Bi] = p;
    }
    __syncthreads();
    if (tid < 16) {
        float s = 0.0f;
        #pragma unroll
        for (int c = 0; c < 16; c++) s += s_red[c * 16 + tid];
        s_ars[tid] = s;
        out[((size_t)b * 16 + tid) * LL + l] = s / (*s_aus);
    }
    __syncthreads();

    // S7: coeff; write C[m][col]
    for (int idx = tid; idx < 4608; idx += 256) {
        int m = idx >> 4, Bi = idx & 15;
        float cf = s_gn[m * 17 + Bi] / s_ars[Bi];
        s_gn[m * 17 + Bi] = cf;
        g_C[(size_t)m * NCOL + (size_t)bl * 16 + Bi] = cf;
    }
    __syncthreads();

    // S8: p = gelu(pu@W^T+b); po_base = sum coeff*p; write P bf16 FLAT [d][col][k].
    {
        int Bi = tid & 15, d = tid >> 4;
        int e = Bi * 16 + d;
        float W[16];
        #pragma unroll
        for (int c = 0; c < 16; c++) W[c] = mpose_w[e * 16 + c];
        float bs = mpose_b[e];
        float acc = 0.0f;
        uint4* Pd4 = reinterpret_cast<uint4*>(
            g_Pb + ((size_t)d * NCOL + (size_t)bl * 16 + Bi) * KP);
        for (int g = 0; g < 36; g++) {            // 36 * 8 = 288 m-values
            uint32_t pk[4];
            #pragma unroll
            for (int pp = 0; pp < 4; pp++) {
                float vv[2];
                #pragma unroll
                for (int h = 0; h < 2; h++) {
                    int m = g * 8 + pp * 2 + h;
                    const float4* pv4 = reinterpret_cast<const float4*>(s_pu + m * PUS);
                    float4 p0 = pv4[0], p1 = pv4[1], p2 = pv4[2], p3 = pv4[3];
                    float v = bs;
                    v = fmaf(p0.x, W[0],  v); v = fmaf(p0.y, W[1],  v);
                    v = fmaf(p0.z, W[2],  v); v = fmaf(p0.w, W[3],  v);
                    v = fmaf(p1.x, W[4],  v); v = fmaf(p1.y, W[5],  v);
                    v = fmaf(p1.z, W[6],  v); v = fmaf(p1.w, W[7],  v);
                    v = fmaf(p2.x, W[8],  v); v = fmaf(p2.y, W[9],  v);
                    v = fmaf(p2.z, W[10], v); v = fmaf(p2.w, W[11], v);
                    v = fmaf(p3.x, W[12], v); v = fmaf(p3.y, W[13], v);
                    v = fmaf(p3.z, W[14], v); v = fmaf(p3.w, W[15], v);
                    float pval = gelu_fast(v);
                    acc = fmaf(s_gn[m * 17 + Bi], pval, acc);
                    vv[h] = pval;
                }
                __nv_bfloat162 h2 = __floats2bfloat162_rn(vv[0], vv[1]);
                pk[pp] = *reinterpret_cast<uint32_t*>(&h2);
            }
            Pd4[g] = make_uint4(pk[0], pk[1], pk[2], pk[3]);
        }
        // zero pad k = 288..319
        uint4 z = make_uint4(0, 0, 0, 0);
        Pd4[36] = z; Pd4[37] = z; Pd4[38] = z; Pd4[39] = z;
        out[12544 + (size_t)b * 50176 + (size_t)e * LL + l] = acc;
    }
}

// ============ kernel 3: mma.sync bf16 circulant GEMM + fused coeff reduction ============
// EXACT R5/R8 configuration (measured 153-155 us three times): grid (98,3,16),
// tile m=96 x col=128, launch_bounds(256,2), paired B ldsm_x4.
#define SA_STG 12288            // 96 rows x 128B
#define SB_STG 16384            // 128 rows x 128B
#define GEMM_SMEM (2 * SA_STG + 2 * SB_STG)

__global__ void __launch_bounds__(256, 2) k_gemm_mma(float* __restrict__ out) {
    extern __shared__ __align__(128) char smemc[];
    const uint32_t sb = smem_u32(smemc);
    const int tid  = threadIdx.x;
    const int lane = tid & 31;
    const int wid  = tid >> 5;
    const int wm   = wid >> 2;          // 0..1  (m-warp, 48 rows each)
    const int wn   = wid & 3;           // 0..3  (n-warp, 32 cols each)

    const int d    = blockIdx.z;
    const int m0   = blockIdx.y * 96;
    const int col0 = blockIdx.x * 128;

    const __nv_bfloat16* Hg = g_Hb + ((size_t)d * 288 + m0) * KP;
    const __nv_bfloat16* Pg = g_Pb + ((size_t)d * NCOL + col0) * KP;

    float acc[3][4][4];
    #pragma unroll
    for (int r = 0; r < 3; r++)
        #pragma unroll
        for (int q = 0; q < 4; q++)
            #pragma unroll
            for (int i = 0; i < 4; i++) acc[r][q][i] = 0.0f;

    // ---- chunk loader: chunk c (k in [c*64, c*64+64)) into stage s ----
    auto load_chunk = [&](int c, int s) {
        uint32_t abase = sb + s * SA_STG;
        uint32_t bbase = sb + 2 * SA_STG + s * SB_STG;
        #pragma unroll
        for (int it = 0; it < 3; it++) {          // 96 rows x 8 chunks = 768
            int i = tid + it * 256;
            int row = i >> 3, u = i & 7;
            cp_async16(abase + row * 128 + ((u ^ (row & 7)) << 4),
                       Hg + (size_t)row * KP + c * 64 + u * 8);
        }
        #pragma unroll
        for (int it = 0; it < 4; it++) {          // 128 rows x 8 chunks = 1024
            int i = tid + it * 256;
            int row = i >> 3, u = i & 7;
            cp_async16(bbase + row * 128 + ((u ^ (row & 7)) << 4),
                       Pg + (size_t)row * KP + c * 64 + u * 8);
        }
        CP_COMMIT();
    };

    load_chunk(0, 0);

    // per-lane ldmatrix address components
    const int a_row_l = wm * 48 + (lane & 15);          // + r*16
    const int a_chalf = lane >> 4;                      // k-half select
    // B loads paired: one ldsm_x4 covers q-pair (2 n-fragments x 2 k-halves)
    const int b_row_l = wn * 32 + ((lane >> 4) << 3) + (lane & 7);   // + qp*16
    const int b_chalf = (lane >> 3) & 1;

    for (int c = 0; c < 5; c++) {
        if (c < 4) load_chunk(c + 1, (c + 1) & 1);
        if (c < 4) CP_WAIT(1); else CP_WAIT(0);
        __syncthreads();

        uint32_t Ab = sb + (c & 1) * SA_STG;
        uint32_t Bb = sb + 2 * SA_STG + (c & 1) * SB_STG;

        #pragma unroll
        for (int ks = 0; ks < 4; ks++) {
            uint32_t a[3][4], bfrag[4][2];
            #pragma unroll
            for (int r = 0; r < 3; r++) {
                int row = a_row_l + r * 16;
                int c16 = ks * 2 + a_chalf;
                ldsm_x4(a[r][0], a[r][1], a[r][2], a[r][3],
                        Ab + row * 128 + (((c16 ^ (row & 7)) & 7) << 4));
            }
            #pragma unroll
            for (int qp = 0; qp < 2; qp++) {
                int row = b_row_l + qp * 16;
                int c16 = ks * 2 + b_chalf;
                ldsm_x4(bfrag[qp * 2][0], bfrag[qp * 2][1],
                        bfrag[qp * 2 + 1][0], bfrag[qp * 2 + 1][1],
                        Bb + row * 128 + (((c16 ^ (row & 7)) & 7) << 4));
            }
            #pragma unroll
            for (int r = 0; r < 3; r++)
                #pragma unroll
                for (int q = 0; q < 4; q++)
                    mma_bf16(acc[r][q], a[r], bfrag[q]);
        }
        __syncthreads();
    }

    // ---- fused epilogue: s[col] = sum_m C[m,col] * D[m,col] ----
    float s[8];
    #pragma unroll
    for (int j = 0; j < 8; j++) s[j] = 0.0f;
    const int colb = col0 + wn * 32 + ((lane & 3) << 1);
    #pragma unroll
    for (int r = 0; r < 3; r++) {
        #pragma unroll
        for (int half = 0; half < 2; half++) {
            int m = m0 + wm * 48 + r * 16 + (lane >> 2) + half * 8;
            const float* Crow = g_C + (size_t)m * NCOL;
            #pragma unroll
            for (int q = 0; q < 4; q++) {
                s[q * 2 + 0] = fmaf(Crow[colb + q * 8 + 0], acc[r][q][half * 2 + 0], s[q * 2 + 0]);
                s[q * 2 + 1] = fmaf(Crow[colb + q * 8 + 1], acc[r][q][half * 2 + 1], s[q * 2 + 1]);
            }
        }
    }
    #pragma unroll
    for (int off = 4; off < 32; off <<= 1)
        #pragma unroll
        for (int j = 0; j < 8; j++) s[j] += __shfl_xor_sync(0xffffffffu, s[j], off);

    if (lane < 4) {
        #pragma unroll
        for (int q = 0; q < 4; q++) {
            #pragma unroll
            for (int j = 0; j < 2; j++) {
                int col = col0 + wn * 32 + q * 8 + lane * 2 + j;
                int bl = col >> 4, Bi = col & 15;
                int bb = bl / LL, ll = bl % LL;
                atomicAdd(&out[12544 + (size_t)bb * 50176 + (size_t)(Bi * 16 + d) * LL + ll],
                          s[q * 2 + j]);
            }
        }
    }
}

// ---------------- launch ----------------
extern "C" void kernel_launch(void* const* d_in, const int* in_sizes, int n_in,
                              void* d_out, int out_size) {
    const float* a     = (const float*)d_in[0];
    const float* pose  = (const float*)d_in[1];
    const float* mw    = (const float*)d_in[2];
    const float* mb    = (const float*)d_in[3];
    const float* cw2   = (const float*)d_in[4];
    const float* cb2   = (const float*)d_in[5];
    const float* cplx  = (const float*)d_in[6];
    const float* gam   = (const float*)d_in[7];
    const float* bet   = (const float*)d_in[8];
    const float* spw   = (const float*)d_in[9];
    const float* spb   = (const float*)d_in[10];
    float* out = (float*)d_out;

    size_t smem_floats = (size_t)288 * PUS + 2 * 288 * 17 + 16 * 17 + 16 + 81 + 16 + 32 + 32 + 288 + 144 + 144 + 256 + 16 + 1;
    size_t smem_bytes = smem_floats * sizeof(float);
    cudaFuncSetAttribute(k_main, cudaFuncAttributeMaxDynamicSharedMemorySize, (int)smem_bytes);
    cudaFuncSetAttribute(k_gemm_mma, cudaFuncAttributeMaxDynamicSharedMemorySize, GEMM_SMEM);

    k_build_h<<<16, 288>>>(cplx);
    k_expand_Hb<<<dim3(288, 16), 320>>>();
    k_main<<<NBL, 256, smem_bytes>>>(a, pose, mw, mb, cw2, cb2, gam, bet, spw, spb, out);
    k_gemm_mma<<<dim3(NCOL / 128, 288 / 96, 16), 256, GEMM_SMEM>>>(out);
}

// round 11
// speedup vs baseline: 1.3250x; 1.0426x over previous
#include <cuda_runtime.h>
#include <cuda_bf16.h>
#include <math.h>
#include <stdint.h>

// ---------------- problem constants ----------------
#define AA    32
#define CC    16
#define KKn   9
#define KKA   288
#define NB    16      // Bc
#define ND    16      // D
#define NE    256     // Bc*D
#define HW    14
#define LL    196
#define NBSZ  4
#define NBL   784     // NBSZ*LL
#define NCOL  12544   // NBL*NB
#define KKA2  145
#define KP    288     // K for tensor GEMM (4 x 64 + 1 x 32, no padding)
#define PUS   20      // s_pu row stride (floats): 80B, 16B-aligned for LDS.128

// ---------------- scratch (static device mem; no allocs allowed) ----------------
__device__ float g_h[16 * 288];                                        //  18 KB
__device__ __align__(1024) __nv_bfloat16 g_Hb[(size_t)16 * 288 * KP];  //  2.65 MB  H circulant bf16 [d][m][k]
__device__ __align__(1024) __nv_bfloat16 g_Pb[(size_t)16 * NCOL * KP]; //  115.7 MB P bf16 [d][col][k] (FLAT)
__device__ float g_C[(size_t)288 * NCOL];                              //  14.4 MB  coeff [m][col]

// fast exact-gelu via Abramowitz-Stegun 7.1.26 erf (|abs err| <= 1.5e-7)
__device__ __forceinline__ float gelu_fast(float v) {
    float x  = v * 0.70710678118654752f;
    float ax = fabsf(x);
    float t  = __fdividef(1.0f, fmaf(0.3275911f, ax, 1.0f));
    float poly = t * fmaf(t, fmaf(t, fmaf(t, fmaf(t, 1.061405429f, -1.453152027f),
                                          1.421413741f), -0.284496736f), 0.254829592f);
    float r  = 1.0f - poly * __expf(-ax * ax);
    float erfv = copysignf(r, x);
    return 0.5f * v * (1.0f + erfv);
}

// ---------------- PTX helpers (sm_100 baseline: cp.async / ldmatrix / mma.sync) ----------------
__device__ __forceinline__ uint32_t smem_u32(const void* p) {
    uint32_t a;
    asm("{ .reg .u64 t; cvta.to.shared.u64 t, %1; cvt.u32.u64 %0, t; }" : "=r"(a) : "l"(p));
    return a;
}
__device__ __forceinline__ void cp_async16(uint32_t saddr, const void* gaddr) {
    asm volatile("cp.async.cg.shared.global [%0], [%1], 16;" :: "r"(saddr), "l"(gaddr) : "memory");
}
#define CP_COMMIT() asm volatile("cp.async.commit_group;" ::: "memory")
#define CP_WAIT(n)  asm volatile("cp.async.wait_group %0;" :: "n"(n) : "memory")

__device__ __forceinline__ void ldsm_x4(uint32_t& r0, uint32_t& r1, uint32_t& r2, uint32_t& r3,
                                        uint32_t addr) {
    asm volatile("ldmatrix.sync.aligned.m8n8.x4.shared.b16 {%0,%1,%2,%3}, [%4];"
                 : "=r"(r0), "=r"(r1), "=r"(r2), "=r"(r3) : "r"(addr));
}
__device__ __forceinline__ void mma_bf16(float* d, const uint32_t* a, const uint32_t* b) {
    asm volatile("mma.sync.aligned.m16n8k16.row.col.f32.bf16.bf16.f32 "
                 "{%0,%1,%2,%3}, {%4,%5,%6,%7}, {%8,%9}, {%0,%1,%2,%3};"
                 : "+f"(d[0]), "+f"(d[1]), "+f"(d[2]), "+f"(d[3])
                 : "r"(a[0]), "r"(a[1]), "r"(a[2]), "r"(a[3]), "r"(b[0]), "r"(b[1]));
}

// ============ kernel 0: h[d][t] = irfft(W_d)[t] — one block per d ============
__global__ void k_build_h(const float* __restrict__ cw) {
    __shared__ float ct[288], st[288];
    int t = threadIdx.x;  // 288 threads
    int d = blockIdx.x;   // 16 blocks
    float ang = 6.283185307179586f * (float)t * (1.0f / 288.0f);
    ct[t] = cosf(ang);
    st[t] = sinf(ang);
    __syncthreads();
    float wr0  = cw[(0 * 16 + d) * 2];
    float wnyq = cw[(144 * 16 + d) * 2];
    float acc = wr0 + ((t & 1) ? -wnyq : wnyq);
    float s2 = 0.0f;
    int idx = 0;
    for (int k = 1; k <= 143; k++) {
        idx += t; if (idx >= 288) idx -= 288;
        float wr = cw[(k * 16 + d) * 2];
        float wi = cw[(k * 16 + d) * 2 + 1];
        s2 += wr * ct[idx] - wi * st[idx];
    }
    g_h[d * 288 + t] = (acc + 2.0f * s2) * (1.0f / 288.0f);
}

// ============ kernel 1: H bf16 circulant [d][m][k<288] ============
__global__ void k_expand_Hb() {
    int m = blockIdx.x;      // 288
    int d = blockIdx.y;      // 16
    int j = threadIdx.x;     // 288
    int t = m - j; if (t < 0) t += 288;
    g_Hb[((size_t)d * 288 + m) * KP + j] = __float2bfloat16(g_h[d * 288 + t]);
}

// ============ kernel 2: per-position producer ============
extern __shared__ float smem_dyn[];
__global__ void __launch_bounds__(256, 3) k_main(
    const float* __restrict__ a_in, const float* __restrict__ pose,
    const float* __restrict__ mpose_w, const float* __restrict__ mpose_b,
    const float* __restrict__ cpose2_w, const float* __restrict__ cpose2_b,
    const float* __restrict__ ln_gamma, const float* __restrict__ ln_beta,
    const float* __restrict__ sp_w, const float* __restrict__ sp_b,
    float* __restrict__ out)
{
    float* s_pu  = smem_dyn;               // [288][20]  (16B-aligned rows)
    float* s_lg  = s_pu  + 288 * PUS;      // [288][17]
    float* s_gn  = s_lg  + 288 * 17;       // [288][17]
    float* s_cw  = s_gn  + 288 * 17;       // [16][17]
    float* s_cb  = s_cw  + 16 * 17;
    float* s_spw = s_cb  + 16;
    float* s_spb = s_spw + 81;
    float* s_gam = s_spb + 16;
    float* s_bet = s_gam + 32;
    float* s_au  = s_bet + 32;
    float* s_mu  = s_au  + 288;
    float* s_rs  = s_mu  + 144;
    float* s_red = s_rs  + 144;
    float* s_ars = s_red + 256;
    float* s_aus = s_ars + 16;

    const int tid = threadIdx.x;
    const int bl = blockIdx.x;
    const int b = bl / LL, l = bl % LL;
    const int y = l / HW, x = l % HW;

    {
        int Bi = tid >> 4, c = tid & 15;
        s_cw[Bi * 17 + c] = cpose2_w[tid];
        if (tid < 16)  s_cb[tid]  = cpose2_b[tid];
        if (tid < 81)  s_spw[tid] = sp_w[tid];
        if (tid < 9)   s_spb[tid] = sp_b[tid];
        if (tid < 32)  s_gam[tid] = ln_gamma[tid];
        if (tid >= 32 && tid < 64) s_bet[tid - 32] = ln_beta[tid - 32];
    }

    // S1: gather pu and au
    for (int idx = tid; idx < 4608; idx += 256) {
        int m = idx >> 4, c = idx & 15;
        int kk = m >> 5, ai = m & 31;
        int py = y + kk / 3 - 1, px = x + kk % 3 - 1;
        float v = 0.0f;
        if ((unsigned)py < 14u && (unsigned)px < 14u)
            v = pose[(((size_t)b * 512 + (size_t)ai * 16 + c) * 14 + py) * 14 + px];
        s_pu[m * PUS + c] = v;
    }
    for (int m = tid; m < 288; m += 256) {
        int kk = m >> 5, ai = m & 31;
        int py = y + kk / 3 - 1, px = x + kk % 3 - 1;
        float v = 0.0f;
        if ((unsigned)py < 14u && (unsigned)px < 14u)
            v = a_in[(((size_t)b * 32 + ai) * 14 + py) * 14 + px];
        s_au[m] = v;
    }
    __syncthreads();

    // S2: logits (vectorized pu reads)
    for (int idx = tid; idx < 4608; idx += 256) {
        int m = idx >> 4, Bi = idx & 15;
        const float4* pv4 = reinterpret_cast<const float4*>(s_pu + m * PUS);
        const float* pw = s_cw + Bi * 17;
        float4 p0 = pv4[0], p1 = pv4[1], p2 = pv4[2], p3 = pv4[3];
        float acc = s_cb[Bi];
        acc = fmaf(p0.x, pw[0],  acc); acc = fmaf(p0.y, pw[1],  acc);
        acc = fmaf(p0.z, pw[2],  acc); acc = fmaf(p0.w, pw[3],  acc);
        acc = fmaf(p1.x, pw[4],  acc); acc = fmaf(p1.y, pw[5],  acc);
        acc = fmaf(p1.z, pw[6],  acc); acc = fmaf(p1.w, pw[7],  acc);
        acc = fmaf(p2.x, pw[8],  acc); acc = fmaf(p2.y, pw[9],  acc);
        acc = fmaf(p2.z, pw[10], acc); acc = fmaf(p2.w, pw[11], acc);
        acc = fmaf(p3.x, pw[12], acc); acc = fmaf(p3.y, pw[13], acc);
        acc = fmaf(p3.z, pw[14], acc); acc = fmaf(p3.w, pw[15], acc);
        s_lg[m * 17 + Bi] = acc;
    }
    __syncthreads();

    // S3: LayerNorm over a
    if (tid < 144) {
        int kk = tid >> 4, Bi = tid & 15;
        float s = 0.0f, s2 = 0.0f;
        #pragma unroll 4
        for (int ai = 0; ai < 32; ai++) {
            float v = s_lg[(kk * 32 + ai) * 17 + Bi];
            s += v; s2 += v * v;
        }
        float mu = s * (1.0f / 32.0f);
        float var = s2 * (1.0f / 32.0f) - mu * mu;
        s_mu[tid] = mu;
        s_rs[tid] = rsqrtf(var + 1e-5f);
    }
    __syncthreads();
    for (int idx = tid; idx < 4608; idx += 256) {
        int m = idx >> 4, Bi = idx & 15;
        int kk = m >> 5, ai = m & 31;
        float v = s_lg[m * 17 + Bi];
        s_gn[m * 17 + Bi] = (v - s_mu[kk * 16 + Bi]) * s_rs[kk * 16 + Bi] * s_gam[ai] + s_bet[ai];
    }
    __syncthreads();

    // S4: spatial gate
    for (int idx = tid; idx < 4608; idx += 256) {
        int m = idx >> 4, Bi = idx & 15;
        int o = m >> 5, ai = m & 31;
        float acc = s_spb[o];
        #pragma unroll
        for (int i = 0; i < 9; i++)
            acc = fmaf(s_spw[o * 9 + i], s_gn[(i * 32 + ai) * 17 + Bi], acc);
        s_lg[m * 17 + Bi] = 2.0f * s_lg[m * 17 + Bi] + gelu_fast(acc);
    }
    __syncthreads();

    // S5: softmax over Bi; au sum
    for (int m = tid; m < 288; m += 256) {
        float* row = s_lg + m * 17;
        float mx = row[0];
        #pragma unroll
        for (int i = 1; i < 16; i++) mx = fmaxf(mx, row[i]);
        float s = 0.0f;
        #pragma unroll
        for (int i = 0; i < 16; i++) { float e = __expf(row[i] - mx); row[i] = e; s += e; }
        float inv = 1.0f / s;
        #pragma unroll
        for (int i = 0; i < 16; i++) row[i] *= inv;
    }
    if (tid < 32) {
        float p = 0.0f;
        for (int m = tid; m < 288; m += 32) p += s_au[m];
        #pragma unroll
        for (int o = 16; o; o >>= 1) p += __shfl_xor_sync(0xffffffffu, p, o);
        if (tid == 0) *s_aus = p;
    }
    __syncthreads();

    // S6: ar and ar_sum
    {
        int Bi = tid & 15, ck = tid >> 4;
        float p = 0.0f;
        #pragma unroll 2
        for (int r = 0; r < 18; r++) {
            int m = ck * 18 + r;
            float ar = s_au[m] * s_lg[m * 17 + Bi];
            s_gn[m * 17 + Bi] = ar;
            p += ar;
        }
        s_red[ck * 16 + Bi] = p;
    }
    __syncthreads();
    if (tid < 16) {
        float s = 0.0f;
        #pragma unroll
        for (int c = 0; c < 16; c++) s += s_red[c * 16 + tid];
        s_ars[tid] = s;
        out[((size_t)b * 16 + tid) * LL + l] = s / (*s_aus);
    }
    __syncthreads();

    // S7: coeff; write C[m][col]
    for (int idx = tid; idx < 4608; idx += 256) {
        int m = idx >> 4, Bi = idx & 15;
        float cf = s_gn[m * 17 + Bi] / s_ars[Bi];
        s_gn[m * 17 + Bi] = cf;
        g_C[(size_t)m * NCOL + (size_t)bl * 16 + Bi] = cf;
    }
    __syncthreads();

    // S8: p = gelu(pu@W^T+b); po_base = sum coeff*p; write P bf16 FLAT [d][col][k], no pad.
    {
        int Bi = tid & 15, d = tid >> 4;
        int e = Bi * 16 + d;
        float W[16];
        #pragma unroll
        for (int c = 0; c < 16; c++) W[c] = mpose_w[e * 16 + c];
        float bs = mpose_b[e];
        float acc = 0.0f;
        uint4* Pd4 = reinterpret_cast<uint4*>(
            g_Pb + ((size_t)d * NCOL + (size_t)bl * 16 + Bi) * KP);
        for (int g = 0; g < 36; g++) {            // 36 * 8 = 288 m-values
            uint32_t pk[4];
            #pragma unroll
            for (int pp = 0; pp < 4; pp++) {
                float vv[2];
                #pragma unroll
                for (int h = 0; h < 2; h++) {
                    int m = g * 8 + pp * 2 + h;
                    const float4* pv4 = reinterpret_cast<const float4*>(s_pu + m * PUS);
                    float4 p0 = pv4[0], p1 = pv4[1], p2 = pv4[2], p3 = pv4[3];
                    float v = bs;
                    v = fmaf(p0.x, W[0],  v); v = fmaf(p0.y, W[1],  v);
                    v = fmaf(p0.z, W[2],  v); v = fmaf(p0.w, W[3],  v);
                    v = fmaf(p1.x, W[4],  v); v = fmaf(p1.y, W[5],  v);
                    v = fmaf(p1.z, W[6],  v); v = fmaf(p1.w, W[7],  v);
                    v = fmaf(p2.x, W[8],  v); v = fmaf(p2.y, W[9],  v);
                    v = fmaf(p2.z, W[10], v); v = fmaf(p2.w, W[11], v);
                    v = fmaf(p3.x, W[12], v); v = fmaf(p3.y, W[13], v);
                    v = fmaf(p3.z, W[14], v); v = fmaf(p3.w, W[15], v);
                    float pval = gelu_fast(v);
                    acc = fmaf(s_gn[m * 17 + Bi], pval, acc);
                    vv[h] = pval;
                }
                __nv_bfloat162 h2 = __floats2bfloat162_rn(vv[0], vv[1]);
                pk[pp] = *reinterpret_cast<uint32_t*>(&h2);
            }
            Pd4[g] = make_uint4(pk[0], pk[1], pk[2], pk[3]);
        }
        out[12544 + (size_t)b * 50176 + (size_t)e * LL + l] = acc;
    }
}

// ============ kernel 3: mma.sync bf16 circulant GEMM + fused coeff reduction ============
// R5/R8 tile (m=96 x col=128, 2 CTA/SM) with K=288 split as 4x64 + 1x32 (tail peeled).
#define SA_STG 12288            // 96 rows x 128B
#define SB_STG 16384            // 128 rows x 128B
#define GEMM_SMEM (2 * SA_STG + 2 * SB_STG)

__global__ void __launch_bounds__(256, 2) k_gemm_mma(float* __restrict__ out) {
    extern __shared__ __align__(128) char smemc[];
    const uint32_t sb = smem_u32(smemc);
    const int tid  = threadIdx.x;
    const int lane = tid & 31;
    const int wid  = tid >> 5;
    const int wm   = wid >> 2;          // 0..1  (m-warp, 48 rows each)
    const int wn   = wid & 3;           // 0..3  (n-warp, 32 cols each)

    const int d    = blockIdx.z;
    const int m0   = blockIdx.y * 96;
    const int col0 = blockIdx.x * 128;

    const __nv_bfloat16* Hg = g_Hb + ((size_t)d * 288 + m0) * KP;
    const __nv_bfloat16* Pg = g_Pb + ((size_t)d * NCOL + col0) * KP;

    float acc[3][4][4];
    #pragma unroll
    for (int r = 0; r < 3; r++)
        #pragma unroll
        for (int q = 0; q < 4; q++)
            #pragma unroll
            for (int i = 0; i < 4; i++) acc[r][q][i] = 0.0f;

    // ---- 64-wide chunk loader: chunk c (k in [c*64, c*64+64)) into stage s ----
    auto load_chunk64 = [&](int c, int s) {
        uint32_t abase = sb + s * SA_STG;
        uint32_t bbase = sb + 2 * SA_STG + s * SB_STG;
        #pragma unroll
        for (int it = 0; it < 3; it++) {          // 96 rows x 8 chunks = 768
            int i = tid + it * 256;
            int row = i >> 3, u = i & 7;
            cp_async16(abase + row * 128 + ((u ^ (row & 7)) << 4),
                       Hg + (size_t)row * KP + c * 64 + u * 8);
        }
        #pragma unroll
        for (int it = 0; it < 4; it++) {          // 128 rows x 8 chunks = 1024
            int i = tid + it * 256;
            int row = i >> 3, u = i & 7;
            cp_async16(bbase + row * 128 + ((u ^ (row & 7)) << 4),
                       Pg + (size_t)row * KP + c * 64 + u * 8);
        }
        CP_COMMIT();
    };
    // ---- 32-wide tail loader: k in [256, 288) into stage s ----
    auto load_chunk32 = [&](int s) {
        uint32_t abase = sb + s * SA_STG;
        uint32_t bbase = sb + 2 * SA_STG + s * SB_STG;
        #pragma unroll
        for (int it = 0; it < 2; it++) {          // 96 rows x 4 chunks = 384
            int i = tid + it * 256;
            if (i < 384) {
                int row = i >> 2, u = i & 3;
                cp_async16(abase + row * 128 + ((u ^ (row & 7)) << 4),
                           Hg + (size_t)row * KP + 256 + u * 8);
            }
        }
        #pragma unroll
        for (int it = 0; it < 2; it++) {          // 128 rows x 4 chunks = 512
            int i = tid + it * 256;
            int row = i >> 2, u = i & 3;
            cp_async16(bbase + row * 128 + ((u ^ (row & 7)) << 4),
                       Pg + (size_t)row * KP + 256 + u * 8);
        }
        CP_COMMIT();
    };

    load_chunk64(0, 0);

    // per-lane ldmatrix address components
    const int a_row_l = wm * 48 + (lane & 15);          // + r*16
    const int a_chalf = lane >> 4;                      // k-half select
    // B loads paired: one ldsm_x4 covers q-pair (2 n-fragments x 2 k-halves)
    const int b_row_l = wn * 32 + ((lane >> 4) << 3) + (lane & 7);   // + qp*16
    const int b_chalf = (lane >> 3) & 1;

    #pragma unroll
    for (int c = 0; c < 4; c++) {
        if (c < 3) load_chunk64(c + 1, (c + 1) & 1);
        else       load_chunk32(0);               // chunk 4 -> stage 0
        CP_WAIT(1);
        __syncthreads();

        uint32_t Ab = sb + (c & 1) * SA_STG;
        uint32_t Bb = sb + 2 * SA_STG + (c & 1) * SB_STG;

        #pragma unroll
        for (int ks = 0; ks < 4; ks++) {
            uint32_t a[3][4], bfrag[4][2];
            #pragma unroll
            for (int r = 0; r < 3; r++) {
                int row = a_row_l + r * 16;
                int c16 = ks * 2 + a_chalf;
                ldsm_x4(a[r][0], a[r][1], a[r][2], a[r][3],
                        Ab + row * 128 + (((c16 ^ (row & 7)) & 7) << 4));
            }
            #pragma unroll
            for (int qp = 0; qp < 2; qp++) {
                int row = b_row_l + qp * 16;
                int c16 = ks * 2 + b_chalf;
                ldsm_x4(bfrag[qp * 2][0], bfrag[qp * 2][1],
                        bfrag[qp * 2 + 1][0], bfrag[qp * 2 + 1][1],
                        Bb + row * 128 + (((c16 ^ (row & 7)) & 7) << 4));
            }
            #pragma unroll
            for (int r = 0; r < 3; r++)
                #pragma unroll
                for (int q = 0; q < 4; q++)
                    mma_bf16(acc[r][q], a[r], bfrag[q]);
        }
        __syncthreads();
    }

    // ---- tail chunk (k 256..287, 32 wide) in stage 0 ----
    CP_WAIT(0);
    __syncthreads();
    {
        uint32_t Ab = sb;
        uint32_t Bb = sb + 2 * SA_STG;
        #pragma unroll
        for (int ks = 0; ks < 2; ks++) {
            uint32_t a[3][4], bfrag[4][2];
            #pragma unroll
            for (int r = 0; r < 3; r++) {
                int row = a_row_l + r * 16;
                int c16 = ks * 2 + a_chalf;
                ldsm_x4(a[r][0], a[r][1], a[r][2], a[r][3],
                        Ab + row * 128 + (((c16 ^ (row & 7)) & 7) << 4));
            }
            #pragma unroll
            for (int qp = 0; qp < 2; qp++) {
                int row = b_row_l + qp * 16;
                int c16 = ks * 2 + b_chalf;
                ldsm_x4(bfrag[qp * 2][0], bfrag[qp * 2][1],
                        bfrag[qp * 2 + 1][0], bfrag[qp * 2 + 1][1],
                        Bb + row * 128 + (((c16 ^ (row & 7)) & 7) << 4));
            }
            #pragma unroll
            for (int r = 0; r < 3; r++)
                #pragma unroll
                for (int q = 0; q < 4; q++)
                    mma_bf16(acc[r][q], a[r], bfrag[q]);
        }
    }

    // ---- fused epilogue: s[col] = sum_m C[m,col] * D[m,col] ----
    float s[8];
    #pragma unroll
    for (int j = 0; j < 8; j++) s[j] = 0.0f;
    const int colb = col0 + wn * 32 + ((lane & 3) << 1);
    #pragma unroll
    for (int r = 0; r < 3; r++) {
        #pragma unroll
        for (int half = 0; half < 2; half++) {
            int m = m0 + wm * 48 + r * 16 + (lane >> 2) + half * 8;
            const float* Crow = g_C + (size_t)m * NCOL;
            #pragma unroll
            for (int q = 0; q < 4; q++) {
                s[q * 2 + 0] = fmaf(Crow[colb + q * 8 + 0], acc[r][q][half * 2 + 0], s[q * 2 + 0]);
                s[q * 2 + 1] = fmaf(Crow[colb + q * 8 + 1], acc[r][q][half * 2 + 1], s[q * 2 + 1]);
            }
        }
    }
    #pragma unroll
    for (int off = 4; off < 32; off <<= 1)
        #pragma unroll
        for (int j = 0; j < 8; j++) s[j] += __shfl_xor_sync(0xffffffffu, s[j], off);

    if (lane < 4) {
        #pragma unroll
        for (int q = 0; q < 4; q++) {
            #pragma unroll
            for (int j = 0; j < 2; j++) {
                int col = col0 + wn * 32 + q * 8 + lane * 2 + j;
                int bl = col >> 4, Bi = col & 15;
                int bb = bl / LL, ll = bl % LL;
                atomicAdd(&out[12544 + (size_t)bb * 50176 + (size_t)(Bi * 16 + d) * LL + ll],
                          s[q * 2 + j]);
            }
        }
    }
}

// ---------------- launch ----------------
extern "C" void kernel_launch(void* const* d_in, const int* in_sizes, int n_in,
                              void* d_out, int out_size) {
    const float* a     = (const float*)d_in[0];
    const float* pose  = (const float*)d_in[1];
    const float* mw    = (const float*)d_in[2];
    const float* mb    = (const float*)d_in[3];
    const float* cw2   = (const float*)d_in[4];
    const float* cb2   = (const float*)d_in[5];
    const float* cplx  = (const float*)d_in[6];
    const float* gam   = (const float*)d_in[7];
    const float* bet   = (const float*)d_in[8];
    const float* spw   = (const float*)d_in[9];
    const float* spb   = (const float*)d_in[10];
    float* out = (float*)d_out;

    size_t smem_floats = (size_t)288 * PUS + 2 * 288 * 17 + 16 * 17 + 16 + 81 + 16 + 32 + 32 + 288 + 144 + 144 + 256 + 16 + 1;
    size_t smem_bytes = smem_floats * sizeof(float);
    cudaFuncSetAttribute(k_main, cudaFuncAttributeMaxDynamicSharedMemorySize, (int)smem_bytes);
    cudaFuncSetAttribute(k_gemm_mma, cudaFuncAttributeMaxDynamicSharedMemorySize, GEMM_SMEM);

    k_build_h<<<16, 288>>>(cplx);
    k_expand_Hb<<<dim3(288, 16), 288>>>();
    k_main<<<NBL, 256, smem_bytes>>>(a, pose, mw, mb, cw2, cb2, gam, bet, spw, spb, out);
    k_gemm_mma<<<dim3(NCOL / 128, 288 / 96, 16), 256, GEMM_SMEM>>>(out);
}

// round 12
// speedup vs baseline: 1.4134x; 1.0667x over previous
#include <cuda_runtime.h>
#include <cuda_bf16.h>
#include <math.h>
#include <stdint.h>

// ---------------- problem constants ----------------
#define AA    32
#define CC    16
#define KKn   9
#define KKA   288
#define NB    16      // Bc
#define ND    16      // D
#define NE    256     // Bc*D
#define HW    14
#define LL    196
#define NBSZ  4
#define NBL   784     // NBSZ*LL
#define NCOL  12544   // NBL*NB
#define KKA2  145
#define KP    288     // K for tensor GEMM (4 x 64 + 1 x 32, no padding)

// ---------------- scratch (static device mem; no allocs allowed) ----------------
__device__ float g_h[16 * 288];                                        //  18 KB
__device__ __align__(1024) __nv_bfloat16 g_Hb[(size_t)16 * 288 * KP];  //  2.65 MB  H circulant bf16 [d][m][k]
__device__ __align__(1024) __nv_bfloat16 g_Pb[(size_t)16 * NCOL * KP]; //  115.7 MB P bf16 [d][col][k] (FLAT)
__device__ float g_C[(size_t)288 * NCOL];                              //  14.4 MB  coeff [m][col]

// fast exact-gelu via Abramowitz-Stegun 7.1.26 erf (|abs err| <= 1.5e-7)
__device__ __forceinline__ float gelu_fast(float v) {
    float x  = v * 0.70710678118654752f;
    float ax = fabsf(x);
    float t  = __fdividef(1.0f, fmaf(0.3275911f, ax, 1.0f));
    float poly = t * fmaf(t, fmaf(t, fmaf(t, fmaf(t, 1.061405429f, -1.453152027f),
                                          1.421413741f), -0.284496736f), 0.254829592f);
    float r  = 1.0f - poly * __expf(-ax * ax);
    float erfv = copysignf(r, x);
    return 0.5f * v * (1.0f + erfv);
}

// ---------------- PTX helpers ----------------
__device__ __forceinline__ uint32_t smem_u32(const void* p) {
    uint32_t a;
    asm("{ .reg .u64 t; cvta.to.shared.u64 t, %1; cvt.u32.u64 %0, t; }" : "=r"(a) : "l"(p));
    return a;
}
__device__ __forceinline__ void cp_async16(uint32_t saddr, const void* gaddr) {
    asm volatile("cp.async.cg.shared.global [%0], [%1], 16;" :: "r"(saddr), "l"(gaddr) : "memory");
}
#define CP_COMMIT() asm volatile("cp.async.commit_group;" ::: "memory")
#define CP_WAIT(n)  asm volatile("cp.async.wait_group %0;" :: "n"(n) : "memory")

__device__ __forceinline__ void ldsm_x4(uint32_t& r0, uint32_t& r1, uint32_t& r2, uint32_t& r3,
                                        uint32_t addr) {
    asm volatile("ldmatrix.sync.aligned.m8n8.x4.shared.b16 {%0,%1,%2,%3}, [%4];"
                 : "=r"(r0), "=r"(r1), "=r"(r2), "=r"(r3) : "r"(addr));
}
__device__ __forceinline__ void mma_bf16(float* d, const uint32_t* a, const uint32_t* b) {
    asm volatile("mma.sync.aligned.m16n8k16.row.col.f32.bf16.bf16.f32 "
                 "{%0,%1,%2,%3}, {%4,%5,%6,%7}, {%8,%9}, {%0,%1,%2,%3};"
                 : "+f"(d[0]), "+f"(d[1]), "+f"(d[2]), "+f"(d[3])
                 : "r"(a[0]), "r"(a[1]), "r"(a[2]), "r"(a[3]), "r"(b[0]), "r"(b[1]));
}

// packed f32x2 helpers (Blackwell family baseline, PTX-only)
__device__ __forceinline__ uint64_t pk2(float lo, float hi) {
    uint64_t r;
    asm("mov.b64 %0, {%1, %2};" : "=l"(r) : "f"(lo), "f"(hi));
    return r;
}
__device__ __forceinline__ void upk2(float& lo, float& hi, uint64_t v) {
    asm("mov.b64 {%0, %1}, %2;" : "=f"(lo), "=f"(hi) : "l"(v));
}
__device__ __forceinline__ void fma2(uint64_t& d, uint64_t a, uint64_t b) {
    asm("fma.rn.f32x2 %0, %1, %2, %0;" : "+l"(d) : "l"(a), "l"(b));
}

// ============ kernel 0: h[d][t] = irfft(W_d)[t] — one block per d ============
__global__ void k_build_h(const float* __restrict__ cw) {
    __shared__ float ct[288], st[288];
    int t = threadIdx.x;  // 288 threads
    int d = blockIdx.x;   // 16 blocks
    float ang = 6.283185307179586f * (float)t * (1.0f / 288.0f);
    ct[t] = cosf(ang);
    st[t] = sinf(ang);
    __syncthreads();
    float wr0  = cw[(0 * 16 + d) * 2];
    float wnyq = cw[(144 * 16 + d) * 2];
    float acc = wr0 + ((t & 1) ? -wnyq : wnyq);
    float s2 = 0.0f;
    int idx = 0;
    for (int k = 1; k <= 143; k++) {
        idx += t; if (idx >= 288) idx -= 288;
        float wr = cw[(k * 16 + d) * 2];
        float wi = cw[(k * 16 + d) * 2 + 1];
        s2 += wr * ct[idx] - wi * st[idx];
    }
    g_h[d * 288 + t] = (acc + 2.0f * s2) * (1.0f / 288.0f);
}

// ============ kernel 1: H bf16 circulant [d][m][k<288] ============
__global__ void k_expand_Hb() {
    int m = blockIdx.x;      // 288
    int d = blockIdx.y;      // 16
    int j = threadIdx.x;     // 288
    int t = m - j; if (t < 0) t += 288;
    g_Hb[((size_t)d * 288 + m) * KP + j] = __float2bfloat16(g_h[d * 288 + t]);
}

// ============ kernel 2: per-position producer ============
extern __shared__ float smem_dyn[];
__global__ void __launch_bounds__(256, 3) k_main(
    const float* __restrict__ a_in, const float* __restrict__ pose,
    const float* __restrict__ mpose_w, const float* __restrict__ mpose_b,
    const float* __restrict__ cpose2_w, const float* __restrict__ cpose2_b,
    const float* __restrict__ ln_gamma, const float* __restrict__ ln_beta,
    const float* __restrict__ sp_w, const float* __restrict__ sp_b,
    float* __restrict__ out)
{
    // s_pu pair-packed: [p=m/2][c] float2 {pu[2p][c], pu[2p+1][c]}, 32 floats/row (128B)
    float* s_pu  = smem_dyn;               // 4608
    float* s_lg  = s_pu  + 4608;           // [288][17]
    float* s_gn  = s_lg  + 4896;           // [288][17]
    float* s_cw2 = s_gn  + 4896;           // [16][18 float2] = 576 (padded rows, 144B)
    float* s_cb  = s_cw2 + 576;
    float* s_spw = s_cb  + 16;
    float* s_spb = s_spw + 81;
    float* s_gam = s_spb + 16;
    float* s_bet = s_gam + 32;
    float* s_au  = s_bet + 32;
    float* s_mu  = s_au  + 288;
    float* s_rs  = s_mu  + 144;
    float* s_red = s_rs  + 144;
    float* s_ars = s_red + 256;
    float* s_aus = s_ars + 16;

    const int tid = threadIdx.x;
    const int bl = blockIdx.x;
    const int b = bl / LL, l = bl % LL;
    const int y = l / HW, x = l % HW;

    {
        int Bi = tid >> 4, c = tid & 15;
        float v = cpose2_w[tid];
        s_cw2[Bi * 36 + c * 2]     = v;     // packed {w,w}
        s_cw2[Bi * 36 + c * 2 + 1] = v;
        if (tid < 16)  s_cb[tid]  = cpose2_b[tid];
        if (tid < 81)  s_spw[tid] = sp_w[tid];
        if (tid < 9)   s_spb[tid] = sp_b[tid];
        if (tid < 32)  s_gam[tid] = ln_gamma[tid];
        if (tid >= 32 && tid < 64) s_bet[tid - 32] = ln_beta[tid - 32];
    }

    // S1: gather pu (pair-packed) and au
    for (int idx = tid; idx < 4608; idx += 256) {
        int m = idx >> 4, c = idx & 15;
        int kk = m >> 5, ai = m & 31;
        int py = y + kk / 3 - 1, px = x + kk % 3 - 1;
        float v = 0.0f;
        if ((unsigned)py < 14u && (unsigned)px < 14u)
            v = pose[(((size_t)b * 512 + (size_t)ai * 16 + c) * 14 + py) * 14 + px];
        s_pu[(m >> 1) * 32 + (c << 1) + (m & 1)] = v;
    }
    for (int m = tid; m < 288; m += 256) {
        int kk = m >> 5, ai = m & 31;
        int py = y + kk / 3 - 1, px = x + kk % 3 - 1;
        float v = 0.0f;
        if ((unsigned)py < 14u && (unsigned)px < 14u)
            v = a_in[(((size_t)b * 32 + ai) * 14 + py) * 14 + px];
        s_au[m] = v;
    }
    __syncthreads();

    // S2: logits, m-pairs via fma.rn.f32x2 (Bi is loop-invariant per thread)
    {
        const int Bi = tid & 15;
        uint64_t w2[16];
        const uint64_t* cwp = reinterpret_cast<const uint64_t*>(s_cw2 + Bi * 36);
        #pragma unroll
        for (int c = 0; c < 16; c++) w2[c] = cwp[c];
        float cbv = s_cb[Bi];
        uint64_t cb2 = pk2(cbv, cbv);
        for (int idx = tid; idx < 2304; idx += 256) {
            int p = idx >> 4;
            const ulonglong2* pv = reinterpret_cast<const ulonglong2*>(s_pu + p * 32);
            uint64_t acc2 = cb2;
            #pragma unroll
            for (int c2 = 0; c2 < 8; c2++) {
                ulonglong2 u = pv[c2];
                fma2(acc2, u.x, w2[c2 * 2]);
                fma2(acc2, u.y, w2[c2 * 2 + 1]);
            }
            float lo, hi; upk2(lo, hi, acc2);
            s_lg[(2 * p) * 17 + Bi]     = lo;
            s_lg[(2 * p + 1) * 17 + Bi] = hi;
        }
    }
    __syncthreads();

    // S3: LayerNorm over a
    if (tid < 144) {
        int kk = tid >> 4, Bi = tid & 15;
        float s = 0.0f, s2 = 0.0f;
        #pragma unroll 4
        for (int ai = 0; ai < 32; ai++) {
            float v = s_lg[(kk * 32 + ai) * 17 + Bi];
            s += v; s2 += v * v;
        }
        float mu = s * (1.0f / 32.0f);
        float var = s2 * (1.0f / 32.0f) - mu * mu;
        s_mu[tid] = mu;
        s_rs[tid] = rsqrtf(var + 1e-5f);
    }
    __syncthreads();
    for (int idx = tid; idx < 4608; idx += 256) {
        int m = idx >> 4, Bi = idx & 15;
        int kk = m >> 5, ai = m & 31;
        float v = s_lg[m * 17 + Bi];
        s_gn[m * 17 + Bi] = (v - s_mu[kk * 16 + Bi]) * s_rs[kk * 16 + Bi] * s_gam[ai] + s_bet[ai];
    }
    __syncthreads();

    // S4: spatial gate
    for (int idx = tid; idx < 4608; idx += 256) {
        int m = idx >> 4, Bi = idx & 15;
        int o = m >> 5, ai = m & 31;
        float acc = s_spb[o];
        #pragma unroll
        for (int i = 0; i < 9; i++)
            acc = fmaf(s_spw[o * 9 + i], s_gn[(i * 32 + ai) * 17 + Bi], acc);
        s_lg[m * 17 + Bi] = 2.0f * s_lg[m * 17 + Bi] + gelu_fast(acc);
    }
    __syncthreads();

    // S5: softmax over Bi; au sum
    for (int m = tid; m < 288; m += 256) {
        float* row = s_lg + m * 17;
        float mx = row[0];
        #pragma unroll
        for (int i = 1; i < 16; i++) mx = fmaxf(mx, row[i]);
        float s = 0.0f;
        #pragma unroll
        for (int i = 0; i < 16; i++) { float e = __expf(row[i] - mx); row[i] = e; s += e; }
        float inv = 1.0f / s;
        #pragma unroll
        for (int i = 0; i < 16; i++) row[i] *= inv;
    }
    if (tid < 32) {
        float p = 0.0f;
        for (int m = tid; m < 288; m += 32) p += s_au[m];
        #pragma unroll
        for (int o = 16; o; o >>= 1) p += __shfl_xor_sync(0xffffffffu, p, o);
        if (tid == 0) *s_aus = p;
    }
    __syncthreads();

    // S6: ar and ar_sum
    {
        int Bi = tid & 15, ck = tid >> 4;
        float p = 0.0f;
        #pragma unroll 2
        for (int r = 0; r < 18; r++) {
            int m = ck * 18 + r;
            float ar = s_au[m] * s_lg[m * 17 + Bi];
            s_gn[m * 17 + Bi] = ar;
            p += ar;
        }
        s_red[ck * 16 + Bi] = p;
    }
    __syncthreads();
    if (tid < 16) {
        float s = 0.0f;
        #pragma unroll
        for (int c = 0; c < 16; c++) s += s_red[c * 16 + tid];
        s_ars[tid] = s;
        out[((size_t)b * 16 + tid) * LL + l] = s / (*s_aus);
    }
    __syncthreads();

    // S7: coeff; write C[m][col]
    for (int idx = tid; idx < 4608; idx += 256) {
        int m = idx >> 4, Bi = idx & 15;
        float cf = s_gn[m * 17 + Bi] / s_ars[Bi];
        s_gn[m * 17 + Bi] = cf;
        g_C[(size_t)m * NCOL + (size_t)bl * 16 + Bi] = cf;
    }
    __syncthreads();

    // S8: p = gelu(pu@W^T+b) via fma.rn.f32x2 m-pairs; po_base; P bf16 FLAT [d][col][k]
    {
        int Bi = tid & 15, d = tid >> 4;
        int e = Bi * 16 + d;
        uint64_t W2[16];
        #pragma unroll
        for (int c = 0; c < 16; c++) {
            float w = mpose_w[e * 16 + c];
            W2[c] = pk2(w, w);
        }
        float bsv = mpose_b[e];
        uint64_t bs2 = pk2(bsv, bsv);
        float acc = 0.0f;
        uint4* Pd4 = reinterpret_cast<uint4*>(
            g_Pb + ((size_t)d * NCOL + (size_t)bl * 16 + Bi) * KP);
        for (int g = 0; g < 36; g++) {            // 36 * 8 = 288 m-values
            uint32_t pkk[4];
            #pragma unroll
            for (int pp = 0; pp < 4; pp++) {
                int p = g * 4 + pp;               // m-pair (2p, 2p+1)
                const ulonglong2* pv = reinterpret_cast<const ulonglong2*>(s_pu + p * 32);
                uint64_t v2 = bs2;
                #pragma unroll
                for (int c2 = 0; c2 < 8; c2++) {
                    ulonglong2 u = pv[c2];
                    fma2(v2, u.x, W2[c2 * 2]);
                    fma2(v2, u.y, W2[c2 * 2 + 1]);
                }
                float v0, v1; upk2(v0, v1, v2);
                float p0 = gelu_fast(v0);
                float p1 = gelu_fast(v1);
                acc = fmaf(s_gn[(2 * p) * 17 + Bi],     p0, acc);
                acc = fmaf(s_gn[(2 * p + 1) * 17 + Bi], p1, acc);
                __nv_bfloat162 h2 = __floats2bfloat162_rn(p0, p1);
                pkk[pp] = *reinterpret_cast<uint32_t*>(&h2);
            }
            Pd4[g] = make_uint4(pkk[0], pkk[1], pkk[2], pkk[3]);
        }
        out[12544 + (size_t)b * 50176 + (size_t)e * LL + l] = acc;
    }
}

// ============ kernel 3: mma.sync bf16 circulant GEMM + fused coeff reduction ============
// R11 config (155 us): tile m=96 x col=128, 2 CTA/SM, K = 4x64 + 1x32 tail.
#define SA_STG 12288            // 96 rows x 128B
#define SB_STG 16384            // 128 rows x 128B
#define GEMM_SMEM (2 * SA_STG + 2 * SB_STG)

__global__ void __launch_bounds__(256, 2) k_gemm_mma(float* __restrict__ out) {
    extern __shared__ __align__(128) char smemc[];
    const uint32_t sb = smem_u32(smemc);
    const int tid  = threadIdx.x;
    const int lane = tid & 31;
    const int wid  = tid >> 5;
    const int wm   = wid >> 2;          // 0..1  (m-warp, 48 rows each)
    const int wn   = wid & 3;           // 0..3  (n-warp, 32 cols each)

    const int d    = blockIdx.z;
    const int m0   = blockIdx.y * 96;
    const int col0 = blockIdx.x * 128;

    const __nv_bfloat16* Hg = g_Hb + ((size_t)d * 288 + m0) * KP;
    const __nv_bfloat16* Pg = g_Pb + ((size_t)d * NCOL + col0) * KP;

    float acc[3][4][4];
    #pragma unroll
    for (int r = 0; r < 3; r++)
        #pragma unroll
        for (int q = 0; q < 4; q++)
            #pragma unroll
            for (int i = 0; i < 4; i++) acc[r][q][i] = 0.0f;

    auto load_chunk64 = [&](int c, int s) {
        uint32_t abase = sb + s * SA_STG;
        uint32_t bbase = sb + 2 * SA_STG + s * SB_STG;
        #pragma unroll
        for (int it = 0; it < 3; it++) {
            int i = tid + it * 256;
            int row = i >> 3, u = i & 7;
            cp_async16(abase + row * 128 + ((u ^ (row & 7)) << 4),
                       Hg + (size_t)row * KP + c * 64 + u * 8);
        }
        #pragma unroll
        for (int it = 0; it < 4; it++) {
            int i = tid + it * 256;
            int row = i >> 3, u = i & 7;
            cp_async16(bbase + row * 128 + ((u ^ (row & 7)) << 4),
                       Pg + (size_t)row * KP + c * 64 + u * 8);
        }
        CP_COMMIT();
    };
    auto load_chunk32 = [&](int s) {
        uint32_t abase = sb + s * SA_STG;
        uint32_t bbase = sb + 2 * SA_STG + s * SB_STG;
        #pragma unroll
        for (int it = 0; it < 2; it++) {
            int i = tid + it * 256;
            if (i < 384) {
                int row = i >> 2, u = i & 3;
                cp_async16(abase + row * 128 + ((u ^ (row & 7)) << 4),
                           Hg + (size_t)row * KP + 256 + u * 8);
            }
        }
        #pragma unroll
        for (int it = 0; it < 2; it++) {
            int i = tid + it * 256;
            int row = i >> 2, u = i & 3;
            cp_async16(bbase + row * 128 + ((u ^ (row & 7)) << 4),
                       Pg + (size_t)row * KP + 256 + u * 8);
        }
        CP_COMMIT();
    };

    load_chunk64(0, 0);

    const int a_row_l = wm * 48 + (lane & 15);
    const int a_chalf = lane >> 4;
    const int b_row_l = wn * 32 + ((lane >> 4) << 3) + (lane & 7);
    const int b_chalf = (lane >> 3) & 1;

    #pragma unroll
    for (int c = 0; c < 4; c++) {
        if (c < 3) load_chunk64(c + 1, (c + 1) & 1);
        else       load_chunk32(0);
        CP_WAIT(1);
        __syncthreads();

        uint32_t Ab = sb + (c & 1) * SA_STG;
        uint32_t Bb = sb + 2 * SA_STG + (c & 1) * SB_STG;

        #pragma unroll
        for (int ks = 0; ks < 4; ks++) {
            uint32_t a[3][4], bfrag[4][2];
            #pragma unroll
            for (int r = 0; r < 3; r++) {
                int row = a_row_l + r * 16;
                int c16 = ks * 2 + a_chalf;
                ldsm_x4(a[r][0], a[r][1], a[r][2], a[r][3],
                        Ab + row * 128 + (((c16 ^ (row & 7)) & 7) << 4));
            }
            #pragma unroll
            for (int qp = 0; qp < 2; qp++) {
                int row = b_row_l + qp * 16;
                int c16 = ks * 2 + b_chalf;
                ldsm_x4(bfrag[qp * 2][0], bfrag[qp * 2][1],
                        bfrag[qp * 2 + 1][0], bfrag[qp * 2 + 1][1],
                        Bb + row * 128 + (((c16 ^ (row & 7)) & 7) << 4));
            }
            #pragma unroll
            for (int r = 0; r < 3; r++)
                #pragma unroll
                for (int q = 0; q < 4; q++)
                    mma_bf16(acc[r][q], a[r], bfrag[q]);
        }
        __syncthreads();
    }

    // tail chunk (k 256..287) in stage 0
    CP_WAIT(0);
    __syncthreads();
    {
        uint32_t Ab = sb;
        uint32_t Bb = sb + 2 * SA_STG;
        #pragma unroll
        for (int ks = 0; ks < 2; ks++) {
            uint32_t a[3][4], bfrag[4][2];
            #pragma unroll
            for (int r = 0; r < 3; r++) {
                int row = a_row_l + r * 16;
                int c16 = ks * 2 + a_chalf;
                ldsm_x4(a[r][0], a[r][1], a[r][2], a[r][3],
                        Ab + row * 128 + (((c16 ^ (row & 7)) & 7) << 4));
            }
            #pragma unroll
            for (int qp = 0; qp < 2; qp++) {
                int row = b_row_l + qp * 16;
                int c16 = ks * 2 + b_chalf;
                ldsm_x4(bfrag[qp * 2][0], bfrag[qp * 2][1],
                        bfrag[qp * 2 + 1][0], bfrag[qp * 2 + 1][1],
                        Bb + row * 128 + (((c16 ^ (row & 7)) & 7) << 4));
            }
            #pragma unroll
            for (int r = 0; r < 3; r++)
                #pragma unroll
                for (int q = 0; q < 4; q++)
                    mma_bf16(acc[r][q], a[r], bfrag[q]);
        }
    }

    // fused epilogue: s[col] = sum_m C[m,col] * D[m,col]
    float s[8];
    #pragma unroll
    for (int j = 0; j < 8; j++) s[j] = 0.0f;
    const int colb = col0 + wn * 32 + ((lane & 3) << 1);
    #pragma unroll
    for (int r = 0; r < 3; r++) {
        #pragma unroll
        for (int half = 0; half < 2; half++) {
            int m = m0 + wm * 48 + r * 16 + (lane >> 2) + half * 8;
            const float* Crow = g_C + (size_t)m * NCOL;
            #pragma unroll
            for (int q = 0; q < 4; q++) {
                s[q * 2 + 0] = fmaf(Crow[colb + q * 8 + 0], acc[r][q][half * 2 + 0], s[q * 2 + 0]);
                s[q * 2 + 1] = fmaf(Crow[colb + q * 8 + 1], acc[r][q][half * 2 + 1], s[q * 2 + 1]);
            }
        }
    }
    #pragma unroll
    for (int off = 4; off < 32; off <<= 1)
        #pragma unroll
        for (int j = 0; j < 8; j++) s[j] += __shfl_xor_sync(0xffffffffu, s[j], off);

    if (lane < 4) {
        #pragma unroll
        for (int q = 0; q < 4; q++) {
            #pragma unroll
            for (int j = 0; j < 2; j++) {
                int col = col0 + wn * 32 + q * 8 + lane * 2 + j;
                int bl = col >> 4, Bi = col & 15;
                int bb = bl / LL, ll = bl % LL;
                atomicAdd(&out[12544 + (size_t)bb * 50176 + (size_t)(Bi * 16 + d) * LL + ll],
                          s[q * 2 + j]);
            }
        }
    }
}

// ---------------- launch ----------------
extern "C" void kernel_launch(void* const* d_in, const int* in_sizes, int n_in,
                              void* d_out, int out_size) {
    const float* a     = (const float*)d_in[0];
    const float* pose  = (const float*)d_in[1];
    const float* mw    = (const float*)d_in[2];
    const float* mb    = (const float*)d_in[3];
    const float* cw2   = (const float*)d_in[4];
    const float* cb2   = (const float*)d_in[5];
    const float* cplx  = (const float*)d_in[6];
    const float* gam   = (const float*)d_in[7];
    const float* bet   = (const float*)d_in[8];
    const float* spw   = (const float*)d_in[9];
    const float* spb   = (const float*)d_in[10];
    float* out = (float*)d_out;

    size_t smem_floats = (size_t)4608 + 4896 + 4896 + 576 + 16 + 81 + 16 + 32 + 32 + 288 + 144 + 144 + 256 + 16 + 1;
    size_t smem_bytes = smem_floats * sizeof(float);
    cudaFuncSetAttribute(k_main, cudaFuncAttributeMaxDynamicSharedMemorySize, (int)smem_bytes);
    cudaFuncSetAttribute(k_gemm_mma, cudaFuncAttributeMaxDynamicSharedMemorySize, GEMM_SMEM);

    k_build_h<<<16, 288>>>(cplx);
    k_expand_Hb<<<dim3(288, 16), 288>>>();
    k_main<<<NBL, 256, smem_bytes>>>(a, pose, mw, mb, cw2, cb2, gam, bet, spw, spb, out);
    k_gemm_mma<<<dim3(NCOL / 128, 288 / 96, 16), 256, GEMM_SMEM>>>(out);
}

// round 13
// speedup vs baseline: 1.4505x; 1.0263x over previous
#include <cuda_runtime.h>
#include <cuda_bf16.h>
#include <math.h>
#include <stdint.h>

// ---------------- problem constants ----------------
#define AA    32
#define CC    16
#define KKn   9
#define KKA   288
#define NB    16      // Bc
#define ND    16      // D
#define NE    256     // Bc*D
#define HW    14
#define LL    196
#define NBSZ  4
#define NBL   784     // NBSZ*LL
#define NCOL  12544   // NBL*NB
#define KKA2  145
#define KP    288     // K for tensor GEMM (4 x 64 + 1 x 32, no padding)

// ---------------- scratch (static device mem; no allocs allowed) ----------------
__device__ float g_h[16 * 288];                                        //  18 KB
__device__ __align__(1024) __nv_bfloat16 g_Hb[(size_t)16 * 288 * KP];  //  2.65 MB  H circulant bf16 [d][m][k]
__device__ __align__(1024) __nv_bfloat16 g_Pb[(size_t)16 * NCOL * KP]; //  115.7 MB P bf16 [d][col][k] (FLAT)
__device__ float g_C[(size_t)288 * NCOL];                              //  14.4 MB  coeff [m][col]
__device__ __align__(128) float g_poseT[(size_t)NBSZ * LL * 512];      //  1.6 MB   pose transposed [b][pix][ch]

// lean exact-gelu via Abramowitz-Stegun 7.1.26 erf (|abs err| <= 1.5e-7)
__device__ __forceinline__ float rcp_approx(float x) {
    float r; asm("rcp.approx.f32 %0, %1;" : "=f"(r) : "f"(x)); return r;
}
__device__ __forceinline__ float gelu_fast(float v) {
    float x  = v * 0.70710678118654752f;
    float ax = fabsf(x);
    float t  = rcp_approx(fmaf(0.3275911f, ax, 1.0f));
    float poly = t * fmaf(t, fmaf(t, fmaf(t, fmaf(t, 1.061405429f, -1.453152027f),
                                          1.421413741f), -0.284496736f), 0.254829592f);
    float e  = __expf(-ax * ax);
    float r  = fmaf(poly, -e, 1.0f);
    float erfv = copysignf(r, x);
    float hv = 0.5f * v;
    return fmaf(hv, erfv, hv);
}

// ---------------- PTX helpers ----------------
__device__ __forceinline__ uint32_t smem_u32(const void* p) {
    uint32_t a;
    asm("{ .reg .u64 t; cvta.to.shared.u64 t, %1; cvt.u32.u64 %0, t; }" : "=r"(a) : "l"(p));
    return a;
}
__device__ __forceinline__ void cp_async16(uint32_t saddr, const void* gaddr) {
    asm volatile("cp.async.cg.shared.global [%0], [%1], 16;" :: "r"(saddr), "l"(gaddr) : "memory");
}
#define CP_COMMIT() asm volatile("cp.async.commit_group;" ::: "memory")
#define CP_WAIT(n)  asm volatile("cp.async.wait_group %0;" :: "n"(n) : "memory")

__device__ __forceinline__ void ldsm_x4(uint32_t& r0, uint32_t& r1, uint32_t& r2, uint32_t& r3,
                                        uint32_t addr) {
    asm volatile("ldmatrix.sync.aligned.m8n8.x4.shared.b16 {%0,%1,%2,%3}, [%4];"
                 : "=r"(r0), "=r"(r1), "=r"(r2), "=r"(r3) : "r"(addr));
}
__device__ __forceinline__ void mma_bf16(float* d, const uint32_t* a, const uint32_t* b) {
    asm volatile("mma.sync.aligned.m16n8k16.row.col.f32.bf16.bf16.f32 "
                 "{%0,%1,%2,%3}, {%4,%5,%6,%7}, {%8,%9}, {%0,%1,%2,%3};"
                 : "+f"(d[0]), "+f"(d[1]), "+f"(d[2]), "+f"(d[3])
                 : "r"(a[0]), "r"(a[1]), "r"(a[2]), "r"(a[3]), "r"(b[0]), "r"(b[1]));
}

// packed f32x2 helpers (Blackwell family baseline, PTX-only)
__device__ __forceinline__ uint64_t pk2(float lo, float hi) {
    uint64_t r;
    asm("mov.b64 %0, {%1, %2};" : "=l"(r) : "f"(lo), "f"(hi));
    return r;
}
__device__ __forceinline__ void upk2(float& lo, float& hi, uint64_t v) {
    asm("mov.b64 {%0, %1}, %2;" : "=f"(lo), "=f"(hi) : "l"(v));
}
__device__ __forceinline__ void fma2(uint64_t& d, uint64_t a, uint64_t b) {
    asm("fma.rn.f32x2 %0, %1, %2, %0;" : "+l"(d) : "l"(a), "l"(b));
}

// ============ kernel 0: h[d][t] = irfft(W_d)[t] — one block per d ============
__global__ void k_build_h(const float* __restrict__ cw) {
    __shared__ float ct[288], st[288];
    int t = threadIdx.x;  // 288 threads
    int d = blockIdx.x;   // 16 blocks
    float ang = 6.283185307179586f * (float)t * (1.0f / 288.0f);
    ct[t] = cosf(ang);
    st[t] = sinf(ang);
    __syncthreads();
    float wr0  = cw[(0 * 16 + d) * 2];
    float wnyq = cw[(144 * 16 + d) * 2];
    float acc = wr0 + ((t & 1) ? -wnyq : wnyq);
    float s2 = 0.0f;
    int idx = 0;
    for (int k = 1; k <= 143; k++) {
        idx += t; if (idx >= 288) idx -= 288;
        float wr = cw[(k * 16 + d) * 2];
        float wi = cw[(k * 16 + d) * 2 + 1];
        s2 += wr * ct[idx] - wi * st[idx];
    }
    g_h[d * 288 + t] = (acc + 2.0f * s2) * (1.0f / 288.0f);
}

// ============ kernel 1: H bf16 circulant [d][m][k<288] ============
__global__ void k_expand_Hb() {
    int m = blockIdx.x;      // 288
    int d = blockIdx.y;      // 16
    int j = threadIdx.x;     // 288
    int t = m - j; if (t < 0) t += 288;
    g_Hb[((size_t)d * 288 + m) * KP + j] = __float2bfloat16(g_h[d * 288 + t]);
}

// ============ kernel 1b: transpose pose [b][512][196] -> g_poseT [b][196][512] ============
__global__ void k_transpose_pose(const float* __restrict__ pose) {
    __shared__ float tile[32][33];
    const int pix0 = blockIdx.x * 32;   // 7 tiles (196)
    const int ch0  = blockIdx.y * 32;   // 16 tiles (512)
    const int bb   = blockIdx.z;        // 4
    const int tx = threadIdx.x, ty = threadIdx.y;  // 32 x 8
    #pragma unroll
    for (int k = 0; k < 4; k++) {
        int ch = ch0 + ty + k * 8;
        int pix = pix0 + tx;
        float v = 0.0f;
        if (pix < LL) v = pose[((size_t)bb * 512 + ch) * LL + pix];
        tile[ty + k * 8][tx] = v;
    }
    __syncthreads();
    #pragma unroll
    for (int k = 0; k < 4; k++) {
        int pix = pix0 + ty + k * 8;
        int ch = ch0 + tx;
        if (pix < LL)
            g_poseT[((size_t)bb * LL + pix) * 512 + ch] = tile[tx][ty + k * 8];
    }
}

// ============ kernel 2: per-position producer ============
extern __shared__ float smem_dyn[];
__global__ void __launch_bounds__(256, 3) k_main(
    const float* __restrict__ a_in,
    const float* __restrict__ mpose_w, const float* __restrict__ mpose_b,
    const float* __restrict__ cpose2_w, const float* __restrict__ cpose2_b,
    const float* __restrict__ ln_gamma, const float* __restrict__ ln_beta,
    const float* __restrict__ sp_w, const float* __restrict__ sp_b,
    float* __restrict__ out)
{
    // s_pu pair-packed: [p=m/2][c] float2 {pu[2p][c], pu[2p+1][c]}, 32 floats/row (128B)
    float* s_pu  = smem_dyn;               // 4608
    float* s_lg  = s_pu  + 4608;           // [288][17]
    float* s_gn  = s_lg  + 4896;           // [288][17]
    float* s_cw2 = s_gn  + 4896;           // [16][18 float2] = 576
    float* s_cb  = s_cw2 + 576;
    float* s_spw = s_cb  + 16;
    float* s_spb = s_spw + 81;
    float* s_gam = s_spb + 16;
    float* s_bet = s_gam + 32;
    float* s_au  = s_bet + 32;
    float* s_mu  = s_au  + 288;
    float* s_rs  = s_mu  + 144;
    float* s_red = s_rs  + 144;
    float* s_ars = s_red + 256;
    float* s_aus = s_ars + 16;

    const int tid = threadIdx.x;
    const int bl = blockIdx.x;
    const int b = bl / LL, l = bl % LL;
    const int y = l / HW, x = l % HW;

    {
        int Bi = tid >> 4, c = tid & 15;
        float v = cpose2_w[tid];
        s_cw2[Bi * 36 + c * 2]     = v;     // packed {w,w}
        s_cw2[Bi * 36 + c * 2 + 1] = v;
        if (tid < 16)  s_cb[tid]  = cpose2_b[tid];
        if (tid < 81)  s_spw[tid] = sp_w[tid];
        if (tid < 9)   s_spb[tid] = sp_b[tid];
        if (tid < 32)  s_gam[tid] = ln_gamma[tid];
        if (tid >= 32 && tid < 64) s_bet[tid - 32] = ln_beta[tid - 32];
    }

    // S1: gather pu from transposed pose (coalesced: 9 pixels x 512 consecutive floats)
    {
        int ch = tid * 2;                   // ai = ch>>4, c = ch&15 (even)
        int ai = ch >> 4, c = ch & 15;
        #pragma unroll
        for (int kk = 0; kk < 9; kk++) {
            int py = y + kk / 3 - 1, px = x + kk % 3 - 1;
            float2 v = make_float2(0.0f, 0.0f);
            if ((unsigned)py < 14u && (unsigned)px < 14u)
                v = reinterpret_cast<const float2*>(
                        g_poseT + ((size_t)b * LL + py * 14 + px) * 512)[tid];
            int m = kk * 32 + ai;
            int base = (m >> 1) * 32 + (m & 1);
            s_pu[base + c * 2]       = v.x;
            s_pu[base + (c + 1) * 2] = v.y;
        }
    }
    for (int m = tid; m < 288; m += 256) {
        int kk = m >> 5, ai = m & 31;
        int py = y + kk / 3 - 1, px = x + kk % 3 - 1;
        float v = 0.0f;
        if ((unsigned)py < 14u && (unsigned)px < 14u)
            v = a_in[(((size_t)b * 32 + ai) * 14 + py) * 14 + px];
        s_au[m] = v;
    }
    __syncthreads();

    // S2: logits, m-pairs via fma.rn.f32x2 (Bi is loop-invariant per thread)
    {
        const int Bi = tid & 15;
        uint64_t w2[16];
        const uint64_t* cwp = reinterpret_cast<const uint64_t*>(s_cw2 + Bi * 36);
        #pragma unroll
        for (int c = 0; c < 16; c++) w2[c] = cwp[c];
        float cbv = s_cb[Bi];
        uint64_t cb2 = pk2(cbv, cbv);
        for (int idx = tid; idx < 2304; idx += 256) {
            int p = idx >> 4;
            const ulonglong2* pv = reinterpret_cast<const ulonglong2*>(s_pu + p * 32);
            uint64_t acc2 = cb2;
            #pragma unroll
            for (int c2 = 0; c2 < 8; c2++) {
                ulonglong2 u = pv[c2];
                fma2(acc2, u.x, w2[c2 * 2]);
                fma2(acc2, u.y, w2[c2 * 2 + 1]);
            }
            float lo, hi; upk2(lo, hi, acc2);
            s_lg[(2 * p) * 17 + Bi]     = lo;
            s_lg[(2 * p + 1) * 17 + Bi] = hi;
        }
    }
    __syncthreads();

    // S3: LayerNorm over a
    if (tid < 144) {
        int kk = tid >> 4, Bi = tid & 15;
        float s = 0.0f, s2 = 0.0f;
        #pragma unroll 4
        for (int ai = 0; ai < 32; ai++) {
            float v = s_lg[(kk * 32 + ai) * 17 + Bi];
            s += v; s2 += v * v;
        }
        float mu = s * (1.0f / 32.0f);
        float var = s2 * (1.0f / 32.0f) - mu * mu;
        s_mu[tid] = mu;
        s_rs[tid] = rsqrtf(var + 1e-5f);
    }
    __syncthreads();
    for (int idx = tid; idx < 4608; idx += 256) {
        int m = idx >> 4, Bi = idx & 15;
        int kk = m >> 5, ai = m & 31;
        float v = s_lg[m * 17 + Bi];
        s_gn[m * 17 + Bi] = (v - s_mu[kk * 16 + Bi]) * s_rs[kk * 16 + Bi] * s_gam[ai] + s_bet[ai];
    }
    __syncthreads();

    // S4: spatial gate
    for (int idx = tid; idx < 4608; idx += 256) {
        int m = idx >> 4, Bi = idx & 15;
        int o = m >> 5, ai = m & 31;
        float acc = s_spb[o];
        #pragma unroll
        for (int i = 0; i < 9; i++)
            acc = fmaf(s_spw[o * 9 + i], s_gn[(i * 32 + ai) * 17 + Bi], acc);
        s_lg[m * 17 + Bi] = 2.0f * s_lg[m * 17 + Bi] + gelu_fast(acc);
    }
    __syncthreads();

    // S5: softmax over Bi; au sum
    for (int m = tid; m < 288; m += 256) {
        float* row = s_lg + m * 17;
        float mx = row[0];
        #pragma unroll
        for (int i = 1; i < 16; i++) mx = fmaxf(mx, row[i]);
        float s = 0.0f;
        #pragma unroll
        for (int i = 0; i < 16; i++) { float e = __expf(row[i] - mx); row[i] = e; s += e; }
        float inv = 1.0f / s;
        #pragma unroll
        for (int i = 0; i < 16; i++) row[i] *= inv;
    }
    if (tid < 32) {
        float p = 0.0f;
        for (int m = tid; m < 288; m += 32) p += s_au[m];
        #pragma unroll
        for (int o = 16; o; o >>= 1) p += __shfl_xor_sync(0xffffffffu, p, o);
        if (tid == 0) *s_aus = p;
    }
    __syncthreads();

    // S6: ar and ar_sum
    {
        int Bi = tid & 15, ck = tid >> 4;
        float p = 0.0f;
        #pragma unroll 2
        for (int r = 0; r < 18; r++) {
            int m = ck * 18 + r;
            float ar = s_au[m] * s_lg[m * 17 + Bi];
            s_gn[m * 17 + Bi] = ar;
            p += ar;
        }
        s_red[ck * 16 + Bi] = p;
    }
    __syncthreads();
    if (tid < 16) {
        float s = 0.0f;
        #pragma unroll
        for (int c = 0; c < 16; c++) s += s_red[c * 16 + tid];
        s_ars[tid] = s;
        out[((size_t)b * 16 + tid) * LL + l] = s / (*s_aus);
    }
    __syncthreads();

    // S7: coeff; write C[m][col]
    for (int idx = tid; idx < 4608; idx += 256) {
        int m = idx >> 4, Bi = idx & 15;
        float cf = s_gn[m * 17 + Bi] / s_ars[Bi];
        s_gn[m * 17 + Bi] = cf;
        g_C[(size_t)m * NCOL + (size_t)bl * 16 + Bi] = cf;
    }
    __syncthreads();

    // S8: p = gelu(pu@W^T+b) via fma.rn.f32x2 m-pairs; po_base; P bf16 FLAT [d][col][k]
    {
        int Bi = tid & 15, d = tid >> 4;
        int e = Bi * 16 + d;
        uint64_t W2[16];
        #pragma unroll
        for (int c = 0; c < 16; c++) {
            float w = mpose_w[e * 16 + c];
            W2[c] = pk2(w, w);
        }
        float bsv = mpose_b[e];
        uint64_t bs2 = pk2(bsv, bsv);
        float acc = 0.0f;
        uint4* Pd4 = reinterpret_cast<uint4*>(
            g_Pb + ((size_t)d * NCOL + (size_t)bl * 16 + Bi) * KP);
        for (int g = 0; g < 36; g++) {            // 36 * 8 = 288 m-values
            uint32_t pkk[4];
            #pragma unroll
            for (int pp = 0; pp < 4; pp++) {
                int p = g * 4 + pp;               // m-pair (2p, 2p+1)
                const ulonglong2* pv = reinterpret_cast<const ulonglong2*>(s_pu + p * 32);
                uint64_t v2 = bs2;
                #pragma unroll
                for (int c2 = 0; c2 < 8; c2++) {
                    ulonglong2 u = pv[c2];
                    fma2(v2, u.x, W2[c2 * 2]);
                    fma2(v2, u.y, W2[c2 * 2 + 1]);
                }
                float v0, v1; upk2(v0, v1, v2);
                float p0 = gelu_fast(v0);
                float p1 = gelu_fast(v1);
                acc = fmaf(s_gn[(2 * p) * 17 + Bi],     p0, acc);
                acc = fmaf(s_gn[(2 * p + 1) * 17 + Bi], p1, acc);
                __nv_bfloat162 h2 = __floats2bfloat162_rn(p0, p1);
                pkk[pp] = *reinterpret_cast<uint32_t*>(&h2);
            }
            Pd4[g] = make_uint4(pkk[0], pkk[1], pkk[2], pkk[3]);
        }
        out[12544 + (size_t)b * 50176 + (size_t)e * LL + l] = acc;
    }
}

// ============ kernel 3: mma.sync bf16 circulant GEMM + fused coeff reduction ============
// R11/R12 config (155-156 us): tile m=96 x col=128, 2 CTA/SM, K = 4x64 + 1x32 tail.
#define SA_STG 12288            // 96 rows x 128B
#define SB_STG 16384            // 128 rows x 128B
#define GEMM_SMEM (2 * SA_STG + 2 * SB_STG)

__global__ void __launch_bounds__(256, 2) k_gemm_mma(float* __restrict__ out) {
    extern __shared__ __align__(128) char smemc[];
    const uint32_t sb = smem_u32(smemc);
    const int tid  = threadIdx.x;
    const int lane = tid & 31;
    const int wid  = tid >> 5;
    const int wm   = wid >> 2;          // 0..1  (m-warp, 48 rows each)
    const int wn   = wid & 3;           // 0..3  (n-warp, 32 cols each)

    const int d    = blockIdx.z;
    const int m0   = blockIdx.y * 96;
    const int col0 = blockIdx.x * 128;

    const __nv_bfloat16* Hg = g_Hb + ((size_t)d * 288 + m0) * KP;
    const __nv_bfloat16* Pg = g_Pb + ((size_t)d * NCOL + col0) * KP;

    float acc[3][4][4];
    #pragma unroll
    for (int r = 0; r < 3; r++)
        #pragma unroll
        for (int q = 0; q < 4; q++)
            #pragma unroll
            for (int i = 0; i < 4; i++) acc[r][q][i] = 0.0f;

    auto load_chunk64 = [&](int c, int s) {
        uint32_t abase = sb + s * SA_STG;
        uint32_t bbase = sb + 2 * SA_STG + s * SB_STG;
        #pragma unroll
        for (int it = 0; it < 3; it++) {
            int i = tid + it * 256;
            int row = i >> 3, u = i & 7;
            cp_async16(abase + row * 128 + ((u ^ (row & 7)) << 4),
                       Hg + (size_t)row * KP + c * 64 + u * 8);
        }
        #pragma unroll
        for (int it = 0; it < 4; it++) {
            int i = tid + it * 256;
            int row = i >> 3, u = i & 7;
            cp_async16(bbase + row * 128 + ((u ^ (row & 7)) << 4),
                       Pg + (size_t)row * KP + c * 64 + u * 8);
        }
        CP_COMMIT();
    };
    auto load_chunk32 = [&](int s) {
        uint32_t abase = sb + s * SA_STG;
        uint32_t bbase = sb + 2 * SA_STG + s * SB_STG;
        #pragma unroll
        for (int it = 0; it < 2; it++) {
            int i = tid + it * 256;
            if (i < 384) {
                int row = i >> 2, u = i & 3;
                cp_async16(abase + row * 128 + ((u ^ (row & 7)) << 4),
                           Hg + (size_t)row * KP + 256 + u * 8);
            }
        }
        #pragma unroll
        for (int it = 0; it < 2; it++) {
            int i = tid + it * 256;
            int row = i >> 2, u = i & 3;
            cp_async16(bbase + row * 128 + ((u ^ (row & 7)) << 4),
                       Pg + (size_t)row * KP + 256 + u * 8);
        }
        CP_COMMIT();
    };

    load_chunk64(0, 0);

    const int a_row_l = wm * 48 + (lane & 15);
    const int a_chalf = lane >> 4;
    const int b_row_l = wn * 32 + ((lane >> 4) << 3) + (lane & 7);
    const int b_chalf = (lane >> 3) & 1;

    #pragma unroll
    for (int c = 0; c < 4; c++) {
        if (c < 3) load_chunk64(c + 1, (c + 1) & 1);
        else       load_chunk32(0);
        CP_WAIT(1);
        __syncthreads();

        uint32_t Ab = sb + (c & 1) * SA_STG;
        uint32_t Bb = sb + 2 * SA_STG + (c & 1) * SB_STG;

        #pragma unroll
        for (int ks = 0; ks < 4; ks++) {
            uint32_t a[3][4], bfrag[4][2];
            #pragma unroll
            for (int r = 0; r < 3; r++) {
                int row = a_row_l + r * 16;
                int c16 = ks * 2 + a_chalf;
                ldsm_x4(a[r][0], a[r][1], a[r][2], a[r][3],
                        Ab + row * 128 + (((c16 ^ (row & 7)) & 7) << 4));
            }
            #pragma unroll
            for (int qp = 0; qp < 2; qp++) {
                int row = b_row_l + qp * 16;
                int c16 = ks * 2 + b_chalf;
                ldsm_x4(bfrag[qp * 2][0], bfrag[qp * 2][1],
                        bfrag[qp * 2 + 1][0], bfrag[qp * 2 + 1][1],
                        Bb + row * 128 + (((c16 ^ (row & 7)) & 7) << 4));
            }
            #pragma unroll
            for (int r = 0; r < 3; r++)
                #pragma unroll
                for (int q = 0; q < 4; q++)
                    mma_bf16(acc[r][q], a[r], bfrag[q]);
        }
        __syncthreads();
    }

    // tail chunk (k 256..287) in stage 0
    CP_WAIT(0);
    __syncthreads();
    {
        uint32_t Ab = sb;
        uint32_t Bb = sb + 2 * SA_STG;
        #pragma unroll
        for (int ks = 0; ks < 2; ks++) {
            uint32_t a[3][4], bfrag[4][2];
            #pragma unroll
            for (int r = 0; r < 3; r++) {
                int row = a_row_l + r * 16;
                int c16 = ks * 2 + a_chalf;
                ldsm_x4(a[r][0], a[r][1], a[r][2], a[r][3],
                        Ab + row * 128 + (((c16 ^ (row & 7)) & 7) << 4));
            }
            #pragma unroll
            for (int qp = 0; qp < 2; qp++) {
                int row = b_row_l + qp * 16;
                int c16 = ks * 2 + b_chalf;
                ldsm_x4(bfrag[qp * 2][0], bfrag[qp * 2][1],
                        bfrag[qp * 2 + 1][0], bfrag[qp * 2 + 1][1],
                        Bb + row * 128 + (((c16 ^ (row & 7)) & 7) << 4));
            }
            #pragma unroll
            for (int r = 0; r < 3; r++)
                #pragma unroll
                for (int q = 0; q < 4; q++)
                    mma_bf16(acc[r][q], a[r], bfrag[q]);
        }
    }

    // fused epilogue: s[col] = sum_m C[m,col] * D[m,col]
    float s[8];
    #pragma unroll
    for (int j = 0; j < 8; j++) s[j] = 0.0f;
    const int colb = col0 + wn * 32 + ((lane & 3) << 1);
    #pragma unroll
    for (int r = 0; r < 3; r++) {
        #pragma unroll
        for (int half = 0; half < 2; half++) {
            int m = m0 + wm * 48 + r * 16 + (lane >> 2) + half * 8;
            const float* Crow = g_C + (size_t)m * NCOL;
            #pragma unroll
            for (int q = 0; q < 4; q++) {
                s[q * 2 + 0] = fmaf(Crow[colb + q * 8 + 0], acc[r][q][half * 2 + 0], s[q * 2 + 0]);
                s[q * 2 + 1] = fmaf(Crow[colb + q * 8 + 1], acc[r][q][half * 2 + 1], s[q * 2 + 1]);
            }
        }
    }
    #pragma unroll
    for (int off = 4; off < 32; off <<= 1)
        #pragma unroll
        for (int j = 0; j < 8; j++) s[j] += __shfl_xor_sync(0xffffffffu, s[j], off);

    if (lane < 4) {
        #pragma unroll
        for (int q = 0; q < 4; q++) {
            #pragma unroll
            for (int j = 0; j < 2; j++) {
                int col = col0 + wn * 32 + q * 8 + lane * 2 + j;
                int bl = col >> 4, Bi = col & 15;
                int bb = bl / LL, ll = bl % LL;
                atomicAdd(&out[12544 + (size_t)bb * 50176 + (size_t)(Bi * 16 + d) * LL + ll],
                          s[q * 2 + j]);
            }
        }
    }
}

// ---------------- launch ----------------
extern "C" void kernel_launch(void* const* d_in, const int* in_sizes, int n_in,
                              void* d_out, int out_size) {
    const float* a     = (const float*)d_in[0];
    const float* pose  = (const float*)d_in[1];
    const float* mw    = (const float*)d_in[2];
    const float* mb    = (const float*)d_in[3];
    const float* cw2   = (const float*)d_in[4];
    const float* cb2   = (const float*)d_in[5];
    const float* cplx  = (const float*)d_in[6];
    const float* gam   = (const float*)d_in[7];
    const float* bet   = (const float*)d_in[8];
    const float* spw   = (const float*)d_in[9];
    const float* spb   = (const float*)d_in[10];
    float* out = (float*)d_out;

    size_t smem_floats = (size_t)4608 + 4896 + 4896 + 576 + 16 + 81 + 16 + 32 + 32 + 288 + 144 + 144 + 256 + 16 + 1;
    size_t smem_bytes = smem_floats * sizeof(float);
    cudaFuncSetAttribute(k_main, cudaFuncAttributeMaxDynamicSharedMemorySize, (int)smem_bytes);
    cudaFuncSetAttribute(k_gemm_mma, cudaFuncAttributeMaxDynamicSharedMemorySize, GEMM_SMEM);

    k_build_h<<<16, 288>>>(cplx);
    k_expand_Hb<<<dim3(288, 16), 288>>>();
    k_transpose_pose<<<dim3(7, 16, NBSZ), dim3(32, 8)>>>(pose);
    k_main<<<NBL, 256, smem_bytes>>>(a, mw, mb, cw2, cb2, gam, bet, spw, spb, out);
    k_gemm_mma<<<dim3(NCOL / 128, 288 / 96, 16), 256, GEMM_SMEM>>>(out);
}

// round 14
// speedup vs baseline: 1.4904x; 1.0275x over previous
#include <cuda_runtime.h>
#include <cuda_bf16.h>
#include <math.h>
#include <stdint.h>

// ---------------- problem constants ----------------
#define AA    32
#define CC    16
#define KKn   9
#define KKA   288
#define NB    16      // Bc
#define ND    16      // D
#define NE    256     // Bc*D
#define HW    14
#define LL    196
#define NBSZ  4
#define NBL   784     // NBSZ*LL
#define NCOL  12544   // NBL*NB
#define KKA2  145
#define KP    288     // K for tensor GEMM (4 x 64 + 1 x 32, no padding)

// ---------------- scratch (static device mem; no allocs allowed) ----------------
__device__ float g_h[16 * 288];                                        //  18 KB
__device__ __align__(1024) __nv_bfloat16 g_Hb[(size_t)16 * 288 * KP];  //  2.65 MB  H circulant bf16 [d][m][k]
__device__ __align__(1024) __nv_bfloat16 g_Pb[(size_t)16 * NCOL * KP]; //  115.7 MB P bf16 [d][col][k] (FLAT)
__device__ float g_C[(size_t)288 * NCOL];                              //  14.4 MB  coeff [m][col]
__device__ __align__(128) float g_poseT[(size_t)NBSZ * LL * 512];      //  1.6 MB   pose transposed [b][pix][ch]

// lean exact-gelu via Abramowitz-Stegun 7.1.26 erf (|abs err| <= 1.5e-7) — used in S4 gate
__device__ __forceinline__ float rcp_approx(float x) {
    float r; asm("rcp.approx.f32 %0, %1;" : "=f"(r) : "f"(x)); return r;
}
__device__ __forceinline__ float gelu_fast(float v) {
    float x  = v * 0.70710678118654752f;
    float ax = fabsf(x);
    float t  = rcp_approx(fmaf(0.3275911f, ax, 1.0f));
    float poly = t * fmaf(t, fmaf(t, fmaf(t, fmaf(t, 1.061405429f, -1.453152027f),
                                          1.421413741f), -0.284496736f), 0.254829592f);
    float e  = __expf(-ax * ax);
    float r  = fmaf(poly, -e, 1.0f);
    float erfv = copysignf(r, x);
    float hv = 0.5f * v;
    return fmaf(hv, erfv, hv);
}
// tanh-form gelu with HW tanh.approx (S8 bulk path: |v| <~ 1, error ~1e-4 abs)
__device__ __forceinline__ float gelu_tanh(float v) {
    float v2 = v * v;
    float s  = v * fmaf(v2, 0.03567740814f, 0.79788456080f);
    float t;
    asm("tanh.approx.f32 %0, %1;" : "=f"(t) : "f"(s));
    float hv = 0.5f * v;
    return fmaf(hv, t, hv);
}

// ---------------- PTX helpers ----------------
__device__ __forceinline__ uint32_t smem_u32(const void* p) {
    uint32_t a;
    asm("{ .reg .u64 t; cvta.to.shared.u64 t, %1; cvt.u32.u64 %0, t; }" : "=r"(a) : "l"(p));
    return a;
}
__device__ __forceinline__ void cp_async16(uint32_t saddr, const void* gaddr) {
    asm volatile("cp.async.cg.shared.global [%0], [%1], 16;" :: "r"(saddr), "l"(gaddr) : "memory");
}
#define CP_COMMIT() asm volatile("cp.async.commit_group;" ::: "memory")
#define CP_WAIT(n)  asm volatile("cp.async.wait_group %0;" :: "n"(n) : "memory")

__device__ __forceinline__ void ldsm_x4(uint32_t& r0, uint32_t& r1, uint32_t& r2, uint32_t& r3,
                                        uint32_t addr) {
    asm volatile("ldmatrix.sync.aligned.m8n8.x4.shared.b16 {%0,%1,%2,%3}, [%4];"
                 : "=r"(r0), "=r"(r1), "=r"(r2), "=r"(r3) : "r"(addr));
}
__device__ __forceinline__ void mma_bf16(float* d, const uint32_t* a, const uint32_t* b) {
    asm volatile("mma.sync.aligned.m16n8k16.row.col.f32.bf16.bf16.f32 "
                 "{%0,%1,%2,%3}, {%4,%5,%6,%7}, {%8,%9}, {%0,%1,%2,%3};"
                 : "+f"(d[0]), "+f"(d[1]), "+f"(d[2]), "+f"(d[3])
                 : "r"(a[0]), "r"(a[1]), "r"(a[2]), "r"(a[3]), "r"(b[0]), "r"(b[1]));
}

// packed f32x2 helpers (Blackwell family baseline, PTX-only)
__device__ __forceinline__ uint64_t pk2(float lo, float hi) {
    uint64_t r;
    asm("mov.b64 %0, {%1, %2};" : "=l"(r) : "f"(lo), "f"(hi));
    return r;
}
__device__ __forceinline__ void upk2(float& lo, float& hi, uint64_t v) {
    asm("mov.b64 {%0, %1}, %2;" : "=f"(lo), "=f"(hi) : "l"(v));
}
__device__ __forceinline__ void fma2(uint64_t& d, uint64_t a, uint64_t b) {
    asm("fma.rn.f32x2 %0, %1, %2, %0;" : "+l"(d) : "l"(a), "l"(b));
}

// ============ kernel 0: h[d][t] = irfft(W_d)[t] — one block per d ============
__global__ void k_build_h(const float* __restrict__ cw) {
    __shared__ float ct[288], st[288];
    int t = threadIdx.x;  // 288 threads
    int d = blockIdx.x;   // 16 blocks
    float ang = 6.283185307179586f * (float)t * (1.0f / 288.0f);
    ct[t] = cosf(ang);
    st[t] = sinf(ang);
    __syncthreads();
    float wr0  = cw[(0 * 16 + d) * 2];
    float wnyq = cw[(144 * 16 + d) * 2];
    float acc = wr0 + ((t & 1) ? -wnyq : wnyq);
    float s2 = 0.0f;
    int idx = 0;
    for (int k = 1; k <= 143; k++) {
        idx += t; if (idx >= 288) idx -= 288;
        float wr = cw[(k * 16 + d) * 2];
        float wi = cw[(k * 16 + d) * 2 + 1];
        s2 += wr * ct[idx] - wi * st[idx];
    }
    g_h[d * 288 + t] = (acc + 2.0f * s2) * (1.0f / 288.0f);
}

// ============ kernel 1: H bf16 circulant [d][m][k<288] ============
__global__ void k_expand_Hb() {
    int m = blockIdx.x;      // 288
    int d = blockIdx.y;      // 16
    int j = threadIdx.x;     // 288
    int t = m - j; if (t < 0) t += 288;
    g_Hb[((size_t)d * 288 + m) * KP + j] = __float2bfloat16(g_h[d * 288 + t]);
}

// ============ kernel 1b: transpose pose [b][512][196] -> g_poseT [b][196][512] ============
__global__ void k_transpose_pose(const float* __restrict__ pose) {
    __shared__ float tile[32][33];
    const int pix0 = blockIdx.x * 32;   // 7 tiles (196)
    const int ch0  = blockIdx.y * 32;   // 16 tiles (512)
    const int bb   = blockIdx.z;        // 4
    const int tx = threadIdx.x, ty = threadIdx.y;  // 32 x 8
    #pragma unroll
    for (int k = 0; k < 4; k++) {
        int ch = ch0 + ty + k * 8;
        int pix = pix0 + tx;
        float v = 0.0f;
        if (pix < LL) v = pose[((size_t)bb * 512 + ch) * LL + pix];
        tile[ty + k * 8][tx] = v;
    }
    __syncthreads();
    #pragma unroll
    for (int k = 0; k < 4; k++) {
        int pix = pix0 + ty + k * 8;
        int ch = ch0 + tx;
        if (pix < LL)
            g_poseT[((size_t)bb * LL + pix) * 512 + ch] = tile[tx][ty + k * 8];
    }
}

// ============ kernel 2: per-position producer ============
extern __shared__ float smem_dyn[];
__global__ void __launch_bounds__(256, 3) k_main(
    const float* __restrict__ a_in,
    const float* __restrict__ mpose_w, const float* __restrict__ mpose_b,
    const float* __restrict__ cpose2_w, const float* __restrict__ cpose2_b,
    const float* __restrict__ ln_gamma, const float* __restrict__ ln_beta,
    const float* __restrict__ sp_w, const float* __restrict__ sp_b,
    float* __restrict__ out)
{
    // s_pu pair-packed: [p=m/2][c] float2 {pu[2p][c], pu[2p+1][c]}, 32 floats/row (128B)
    float* s_pu  = smem_dyn;               // 4608
    float* s_lg  = s_pu  + 4608;           // [288][17]
    float* s_gn  = s_lg  + 4896;           // [288][17]
    float* s_cw2 = s_gn  + 4896;           // [16][18 float2] = 576
    float* s_cb  = s_cw2 + 576;
    float* s_spw = s_cb  + 16;
    float* s_spb = s_spw + 81;
    float* s_gam = s_spb + 16;
    float* s_bet = s_gam + 32;
    float* s_au  = s_bet + 32;
    float* s_mu  = s_au  + 288;
    float* s_rs  = s_mu  + 144;
    float* s_red = s_rs  + 144;
    float* s_ars = s_red + 256;            // stores 1/ar_sum
    float* s_aus = s_ars + 16;

    const int tid = threadIdx.x;
    const int bl = blockIdx.x;
    const int b = bl / LL, l = bl % LL;
    const int y = l / HW, x = l % HW;

    {
        int Bi = tid >> 4, c = tid & 15;
        float v = cpose2_w[tid];
        s_cw2[Bi * 36 + c * 2]     = v;     // packed {w,w}
        s_cw2[Bi * 36 + c * 2 + 1] = v;
        if (tid < 16)  s_cb[tid]  = cpose2_b[tid];
        if (tid < 81)  s_spw[tid] = sp_w[tid];
        if (tid < 9)   s_spb[tid] = sp_b[tid];
        if (tid < 32)  s_gam[tid] = ln_gamma[tid];
        if (tid >= 32 && tid < 64) s_bet[tid - 32] = ln_beta[tid - 32];
    }

    // S1: gather pu from transposed pose (coalesced: 9 pixels x 512 consecutive floats)
    {
        int ch = tid * 2;
        int ai = ch >> 4, c = ch & 15;
        #pragma unroll
        for (int kk = 0; kk < 9; kk++) {
            int py = y + kk / 3 - 1, px = x + kk % 3 - 1;
            float2 v = make_float2(0.0f, 0.0f);
            if ((unsigned)py < 14u && (unsigned)px < 14u)
                v = reinterpret_cast<const float2*>(
                        g_poseT + ((size_t)b * LL + py * 14 + px) * 512)[tid];
            int m = kk * 32 + ai;
            int base = (m >> 1) * 32 + (m & 1);
            s_pu[base + c * 2]       = v.x;
            s_pu[base + (c + 1) * 2] = v.y;
        }
    }
    for (int m = tid; m < 288; m += 256) {
        int kk = m >> 5, ai = m & 31;
        int py = y + kk / 3 - 1, px = x + kk % 3 - 1;
        float v = 0.0f;
        if ((unsigned)py < 14u && (unsigned)px < 14u)
            v = a_in[(((size_t)b * 32 + ai) * 14 + py) * 14 + px];
        s_au[m] = v;
    }
    __syncthreads();

    // S2: logits, m-pairs via fma.rn.f32x2 (Bi is loop-invariant per thread)
    {
        const int Bi = tid & 15;
        uint64_t w2[16];
        const uint64_t* cwp = reinterpret_cast<const uint64_t*>(s_cw2 + Bi * 36);
        #pragma unroll
        for (int c = 0; c < 16; c++) w2[c] = cwp[c];
        float cbv = s_cb[Bi];
        uint64_t cb2 = pk2(cbv, cbv);
        for (int idx = tid; idx < 2304; idx += 256) {
            int p = idx >> 4;
            const ulonglong2* pv = reinterpret_cast<const ulonglong2*>(s_pu + p * 32);
            uint64_t acc2 = cb2;
            #pragma unroll
            for (int c2 = 0; c2 < 8; c2++) {
                ulonglong2 u = pv[c2];
                fma2(acc2, u.x, w2[c2 * 2]);
                fma2(acc2, u.y, w2[c2 * 2 + 1]);
            }
            float lo, hi; upk2(lo, hi, acc2);
            s_lg[(2 * p) * 17 + Bi]     = lo;
            s_lg[(2 * p + 1) * 17 + Bi] = hi;
        }
    }
    __syncthreads();

    // S3: LayerNorm over a
    if (tid < 144) {
        int kk = tid >> 4, Bi = tid & 15;
        float s = 0.0f, s2 = 0.0f;
        #pragma unroll 4
        for (int ai = 0; ai < 32; ai++) {
            float v = s_lg[(kk * 32 + ai) * 17 + Bi];
            s += v; s2 += v * v;
        }
        float mu = s * (1.0f / 32.0f);
        float var = s2 * (1.0f / 32.0f) - mu * mu;
        s_mu[tid] = mu;
        s_rs[tid] = rsqrtf(var + 1e-5f);
    }
    __syncthreads();
    for (int idx = tid; idx < 4608; idx += 256) {
        int m = idx >> 4, Bi = idx & 15;
        int kk = m >> 5, ai = m & 31;
        float v = s_lg[m * 17 + Bi];
        s_gn[m * 17 + Bi] = (v - s_mu[kk * 16 + Bi]) * s_rs[kk * 16 + Bi] * s_gam[ai] + s_bet[ai];
    }
    __syncthreads();

    // S4: spatial gate (exact-poly gelu: logits feed softmax, keep precision)
    for (int idx = tid; idx < 4608; idx += 256) {
        int m = idx >> 4, Bi = idx & 15;
        int o = m >> 5, ai = m & 31;
        float acc = s_spb[o];
        #pragma unroll
        for (int i = 0; i < 9; i++)
            acc = fmaf(s_spw[o * 9 + i], s_gn[(i * 32 + ai) * 17 + Bi], acc);
        s_lg[m * 17 + Bi] = 2.0f * s_lg[m * 17 + Bi] + gelu_fast(acc);
    }
    __syncthreads();

    // S5: softmax over Bi; au sum
    for (int m = tid; m < 288; m += 256) {
        float* row = s_lg + m * 17;
        float mx = row[0];
        #pragma unroll
        for (int i = 1; i < 16; i++) mx = fmaxf(mx, row[i]);
        float s = 0.0f;
        #pragma unroll
        for (int i = 0; i < 16; i++) { float e = __expf(row[i] - mx); row[i] = e; s += e; }
        float inv = 1.0f / s;
        #pragma unroll
        for (int i = 0; i < 16; i++) row[i] *= inv;
    }
    if (tid < 32) {
        float p = 0.0f;
        for (int m = tid; m < 288; m += 32) p += s_au[m];
        #pragma unroll
        for (int o = 16; o; o >>= 1) p += __shfl_xor_sync(0xffffffffu, p, o);
        if (tid == 0) *s_aus = p;
    }
    __syncthreads();

    // S6: ar and ar_sum
    {
        int Bi = tid & 15, ck = tid >> 4;
        float p = 0.0f;
        #pragma unroll 2
        for (int r = 0; r < 18; r++) {
            int m = ck * 18 + r;
            float ar = s_au[m] * s_lg[m * 17 + Bi];
            s_gn[m * 17 + Bi] = ar;
            p += ar;
        }
        s_red[ck * 16 + Bi] = p;
    }
    __syncthreads();
    if (tid < 16) {
        float s = 0.0f;
        #pragma unroll
        for (int c = 0; c < 16; c++) s += s_red[c * 16 + tid];
        s_ars[tid] = rcp_approx(s);                            // store reciprocal
        out[((size_t)b * 16 + tid) * LL + l] = s / (*s_aus);
    }
    __syncthreads();

    // S7: coeff = ar * (1/ars); write C[m][col]
    for (int idx = tid; idx < 4608; idx += 256) {
        int m = idx >> 4, Bi = idx & 15;
        float cf = s_gn[m * 17 + Bi] * s_ars[Bi];
        s_gn[m * 17 + Bi] = cf;
        g_C[(size_t)m * NCOL + (size_t)bl * 16 + Bi] = cf;
    }
    __syncthreads();

    // S8: p = gelu_tanh(pu@W^T+b) via fma.rn.f32x2 m-pairs; po_base; P bf16 FLAT [d][col][k]
    {
        int Bi = tid & 15, d = tid >> 4;
        int e = Bi * 16 + d;
        uint64_t W2[16];
        #pragma unroll
        for (int c = 0; c < 16; c++) {
            float w = mpose_w[e * 16 + c];
            W2[c] = pk2(w, w);
        }
        float bsv = mpose_b[e];
        uint64_t bs2 = pk2(bsv, bsv);
        float acc = 0.0f;
        uint4* Pd4 = reinterpret_cast<uint4*>(
            g_Pb + ((size_t)d * NCOL + (size_t)bl * 16 + Bi) * KP);
        for (int g = 0; g < 36; g++) {            // 36 * 8 = 288 m-values
            uint32_t pkk[4];
            #pragma unroll
            for (int pp = 0; pp < 4; pp++) {
                int p = g * 4 + pp;               // m-pair (2p, 2p+1)
                const ulonglong2* pv = reinterpret_cast<const ulonglong2*>(s_pu + p * 32);
                uint64_t v2 = bs2;
                #pragma unroll
                for (int c2 = 0; c2 < 8; c2++) {
                    ulonglong2 u = pv[c2];
                    fma2(v2, u.x, W2[c2 * 2]);
                    fma2(v2, u.y, W2[c2 * 2 + 1]);
                }
                float v0, v1; upk2(v0, v1, v2);
                float p0 = gelu_tanh(v0);
                float p1 = gelu_tanh(v1);
                acc = fmaf(s_gn[(2 * p) * 17 + Bi],     p0, acc);
                acc = fmaf(s_gn[(2 * p + 1) * 17 + Bi], p1, acc);
                __nv_bfloat162 h2 = __floats2bfloat162_rn(p0, p1);
                pkk[pp] = *reinterpret_cast<uint32_t*>(&h2);
            }
            Pd4[g] = make_uint4(pkk[0], pkk[1], pkk[2], pkk[3]);
        }
        out[12544 + (size_t)b * 50176 + (size_t)e * LL + l] = acc;
    }
}

// ============ kernel 3: mma.sync bf16 circulant GEMM + fused coeff reduction ============
// R11/R12 config (155-156 us): tile m=96 x col=128, 2 CTA/SM, K = 4x64 + 1x32 tail.
#define SA_STG 12288            // 96 rows x 128B
#define SB_STG 16384            // 128 rows x 128B
#define GEMM_SMEM (2 * SA_STG + 2 * SB_STG)

__global__ void __launch_bounds__(256, 2) k_gemm_mma(float* __restrict__ out) {
    extern __shared__ __align__(128) char smemc[];
    const uint32_t sb = smem_u32(smemc);
    const int tid  = threadIdx.x;
    const int lane = tid & 31;
    const int wid  = tid >> 5;
    const int wm   = wid >> 2;          // 0..1  (m-warp, 48 rows each)
    const int wn   = wid & 3;           // 0..3  (n-warp, 32 cols each)

    const int d    = blockIdx.z;
    const int m0   = blockIdx.y * 96;
    const int col0 = blockIdx.x * 128;

    const __nv_bfloat16* Hg = g_Hb + ((size_t)d * 288 + m0) * KP;
    const __nv_bfloat16* Pg = g_Pb + ((size_t)d * NCOL + col0) * KP;

    float acc[3][4][4];
    #pragma unroll
    for (int r = 0; r < 3; r++)
        #pragma unroll
        for (int q = 0; q < 4; q++)
            #pragma unroll
            for (int i = 0; i < 4; i++) acc[r][q][i] = 0.0f;

    auto load_chunk64 = [&](int c, int s) {
        uint32_t abase = sb + s * SA_STG;
        uint32_t bbase = sb + 2 * SA_STG + s * SB_STG;
        #pragma unroll
        for (int it = 0; it < 3; it++) {
            int i = tid + it * 256;
            int row = i >> 3, u = i & 7;
            cp_async16(abase + row * 128 + ((u ^ (row & 7)) << 4),
                       Hg + (size_t)row * KP + c * 64 + u * 8);
        }
        #pragma unroll
        for (int it = 0; it < 4; it++) {
            int i = tid + it * 256;
            int row = i >> 3, u = i & 7;
            cp_async16(bbase + row * 128 + ((u ^ (row & 7)) << 4),
                       Pg + (size_t)row * KP + c * 64 + u * 8);
        }
        CP_COMMIT();
    };
    auto load_chunk32 = [&](int s) {
        uint32_t abase = sb + s * SA_STG;
        uint32_t bbase = sb + 2 * SA_STG + s * SB_STG;
        #pragma unroll
        for (int it = 0; it < 2; it++) {
            int i = tid + it * 256;
            if (i < 384) {
                int row = i >> 2, u = i & 3;
                cp_async16(abase + row * 128 + ((u ^ (row & 7)) << 4),
                           Hg + (size_t)row * KP + 256 + u * 8);
            }
        }
        #pragma unroll
        for (int it = 0; it < 2; it++) {
            int i = tid + it * 256;
            int row = i >> 2, u = i & 3;
            cp_async16(bbase + row * 128 + ((u ^ (row & 7)) << 4),
                       Pg + (size_t)row * KP + 256 + u * 8);
        }
        CP_COMMIT();
    };

    load_chunk64(0, 0);

    const int a_row_l = wm * 48 + (lane & 15);
    const int a_chalf = lane >> 4;
    const int b_row_l = wn * 32 + ((lane >> 4) << 3) + (lane & 7);
    const int b_chalf = (lane >> 3) & 1;

    #pragma unroll
    for (int c = 0; c < 4; c++) {
        if (c < 3) load_chunk64(c + 1, (c + 1) & 1);
        else       load_chunk32(0);
        CP_WAIT(1);
        __syncthreads();

        uint32_t Ab = sb + (c & 1) * SA_STG;
        uint32_t Bb = sb + 2 * SA_STG + (c & 1) * SB_STG;

        #pragma unroll
        for (int ks = 0; ks < 4; ks++) {
            uint32_t a[3][4], bfrag[4][2];
            #pragma unroll
            for (int r = 0; r < 3; r++) {
                int row = a_row_l + r * 16;
                int c16 = ks * 2 + a_chalf;
                ldsm_x4(a[r][0], a[r][1], a[r][2], a[r][3],
                        Ab + row * 128 + (((c16 ^ (row & 7)) & 7) << 4));
            }
            #pragma unroll
            for (int qp = 0; qp < 2; qp++) {
                int row = b_row_l + qp * 16;
                int c16 = ks * 2 + b_chalf;
                ldsm_x4(bfrag[qp * 2][0], bfrag[qp * 2][1],
                        bfrag[qp * 2 + 1][0], bfrag[qp * 2 + 1][1],
                        Bb + row * 128 + (((c16 ^ (row & 7)) & 7) << 4));
            }
            #pragma unroll
            for (int r = 0; r < 3; r++)
                #pragma unroll
                for (int q = 0; q < 4; q++)
                    mma_bf16(acc[r][q], a[r], bfrag[q]);
        }
        __syncthreads();
    }

    // tail chunk (k 256..287) in stage 0
    CP_WAIT(0);
    __syncthreads();
    {
        uint32_t Ab = sb;
        uint32_t Bb = sb + 2 * SA_STG;
        #pragma unroll
        for (int ks = 0; ks < 2; ks++) {
            uint32_t a[3][4], bfrag[4][2];
            #pragma unroll
            for (int r = 0; r < 3; r++) {
                int row = a_row_l + r * 16;
                int c16 = ks * 2 + a_chalf;
                ldsm_x4(a[r][0], a[r][1], a[r][2], a[r][3],
                        Ab + row * 128 + (((c16 ^ (row & 7)) & 7) << 4));
            }
            #pragma unroll
            for (int qp = 0; qp < 2; qp++) {
                int row = b_row_l + qp * 16;
                int c16 = ks * 2 + b_chalf;
                ldsm_x4(bfrag[qp * 2][0], bfrag[qp * 2][1],
                        bfrag[qp * 2 + 1][0], bfrag[qp * 2 + 1][1],
                        Bb + row * 128 + (((c16 ^ (row & 7)) & 7) << 4));
            }
            #pragma unroll
            for (int r = 0; r < 3; r++)
                #pragma unroll
                for (int q = 0; q < 4; q++)
                    mma_bf16(acc[r][q], a[r], bfrag[q]);
        }
    }

    // fused epilogue: s[col] = sum_m C[m,col] * D[m,col]
    float s[8];
    #pragma unroll
    for (int j = 0; j < 8; j++) s[j] = 0.0f;
    const int colb = col0 + wn * 32 + ((lane & 3) << 1);
    #pragma unroll
    for (int r = 0; r < 3; r++) {
        #pragma unroll
        for (int half = 0; half < 2; half++) {
            int m = m0 + wm * 48 + r * 16 + (lane >> 2) + half * 8;
            const float* Crow = g_C + (size_t)m * NCOL;
            #pragma unroll
            for (int q = 0; q < 4; q++) {
                s[q * 2 + 0] = fmaf(Crow[colb + q * 8 + 0], acc[r][q][half * 2 + 0], s[q * 2 + 0]);
                s[q * 2 + 1] = fmaf(Crow[colb + q * 8 + 1], acc[r][q][half * 2 + 1], s[q * 2 + 1]);
            }
        }
    }
    #pragma unroll
    for (int off = 4; off < 32; off <<= 1)
        #pragma unroll
        for (int j = 0; j < 8; j++) s[j] += __shfl_xor_sync(0xffffffffu, s[j], off);

    if (lane < 4) {
        #pragma unroll
        for (int q = 0; q < 4; q++) {
            #pragma unroll
            for (int j = 0; j < 2; j++) {
                int col = col0 + wn * 32 + q * 8 + lane * 2 + j;
                int bl = col >> 4, Bi = col & 15;
                int bb = bl / LL, ll = bl % LL;
                atomicAdd(&out[12544 + (size_t)bb * 50176 + (size_t)(Bi * 16 + d) * LL + ll],
                          s[q * 2 + j]);
            }
        }
    }
}

// ---------------- launch ----------------
extern "C" void kernel_launch(void* const* d_in, const int* in_sizes, int n_in,
                              void* d_out, int out_size) {
    const float* a     = (const float*)d_in[0];
    const float* pose  = (const float*)d_in[1];
    const float* mw    = (const float*)d_in[2];
    const float* mb    = (const float*)d_in[3];
    const float* cw2   = (const float*)d_in[4];
    const float* cb2   = (const float*)d_in[5];
    const float* cplx  = (const float*)d_in[6];
    const float* gam   = (const float*)d_in[7];
    const float* bet   = (const float*)d_in[8];
    const float* spw   = (const float*)d_in[9];
    const float* spb   = (const float*)d_in[10];
    float* out = (float*)d_out;

    size_t smem_floats = (size_t)4608 + 4896 + 4896 + 576 + 16 + 81 + 16 + 32 + 32 + 288 + 144 + 144 + 256 + 16 + 1;
    size_t smem_bytes = smem_floats * sizeof(float);
    cudaFuncSetAttribute(k_main, cudaFuncAttributeMaxDynamicSharedMemorySize, (int)smem_bytes);
    cudaFuncSetAttribute(k_gemm_mma, cudaFuncAttributeMaxDynamicSharedMemorySize, GEMM_SMEM);

    k_build_h<<<16, 288>>>(cplx);
    k_expand_Hb<<<dim3(288, 16), 288>>>();
    k_transpose_pose<<<dim3(7, 16, NBSZ), dim3(32, 8)>>>(pose);
    k_main<<<NBL, 256, smem_bytes>>>(a, mw, mb, cw2, cb2, gam, bet, spw, spb, out);
    k_gemm_mma<<<dim3(NCOL / 128, 288 / 96, 16), 256, GEMM_SMEM>>>(out);
}

// round 15
// speedup vs baseline: 1.5107x; 1.0136x over previous
#include <cuda_runtime.h>
#include <cuda_bf16.h>
#include <math.h>
#include <stdint.h>

// ---------------- problem constants ----------------
#define AA    32
#define CC    16
#define KKn   9
#define KKA   288
#define NB    16      // Bc
#define ND    16      // D
#define NE    256     // Bc*D
#define HW    14
#define LL    196
#define NBSZ  4
#define NBL   784     // NBSZ*LL
#define NCOL  12544   // NBL*NB
#define KKA2  145
#define KP    288     // K for tensor GEMM (4 x 64 + 1 x 32, no padding)

// ---------------- scratch (static device mem; no allocs allowed) ----------------
__device__ float g_h[16 * 288];                                        //  18 KB
__device__ __align__(1024) __nv_bfloat16 g_Hb[(size_t)16 * 288 * KP];  //  2.65 MB  H circulant bf16 [d][m][k]
__device__ __align__(1024) __nv_bfloat16 g_Pb[(size_t)16 * NCOL * KP]; //  115.7 MB P bf16 [d][col][k] (FLAT)
__device__ float g_C[(size_t)288 * NCOL];                              //  14.4 MB  coeff [m][col]
__device__ __align__(128) float g_poseT[(size_t)NBSZ * LL * 512];      //  1.6 MB   pose transposed [b][pix][ch]

// lean exact-gelu via Abramowitz-Stegun 7.1.26 erf (|abs err| <= 1.5e-7) — used in S4 gate
__device__ __forceinline__ float rcp_approx(float x) {
    float r; asm("rcp.approx.f32 %0, %1;" : "=f"(r) : "f"(x)); return r;
}
__device__ __forceinline__ float gelu_fast(float v) {
    float x  = v * 0.70710678118654752f;
    float ax = fabsf(x);
    float t  = rcp_approx(fmaf(0.3275911f, ax, 1.0f));
    float poly = t * fmaf(t, fmaf(t, fmaf(t, fmaf(t, 1.061405429f, -1.453152027f),
                                          1.421413741f), -0.284496736f), 0.254829592f);
    float e  = __expf(-ax * ax);
    float r  = fmaf(poly, -e, 1.0f);
    float erfv = copysignf(r, x);
    float hv = 0.5f * v;
    return fmaf(hv, erfv, hv);
}

// ---------------- PTX helpers ----------------
__device__ __forceinline__ uint32_t smem_u32(const void* p) {
    uint32_t a;
    asm("{ .reg .u64 t; cvta.to.shared.u64 t, %1; cvt.u32.u64 %0, t; }" : "=r"(a) : "l"(p));
    return a;
}
__device__ __forceinline__ void cp_async16(uint32_t saddr, const void* gaddr) {
    asm volatile("cp.async.cg.shared.global [%0], [%1], 16;" :: "r"(saddr), "l"(gaddr) : "memory");
}
#define CP_COMMIT() asm volatile("cp.async.commit_group;" ::: "memory")
#define CP_WAIT(n)  asm volatile("cp.async.wait_group %0;" :: "n"(n) : "memory")

__device__ __forceinline__ void ldsm_x4(uint32_t& r0, uint32_t& r1, uint32_t& r2, uint32_t& r3,
                                        uint32_t addr) {
    asm volatile("ldmatrix.sync.aligned.m8n8.x4.shared.b16 {%0,%1,%2,%3}, [%4];"
                 : "=r"(r0), "=r"(r1), "=r"(r2), "=r"(r3) : "r"(addr));
}
__device__ __forceinline__ void mma_bf16(float* d, const uint32_t* a, const uint32_t* b) {
    asm volatile("mma.sync.aligned.m16n8k16.row.col.f32.bf16.bf16.f32 "
                 "{%0,%1,%2,%3}, {%4,%5,%6,%7}, {%8,%9}, {%0,%1,%2,%3};"
                 : "+f"(d[0]), "+f"(d[1]), "+f"(d[2]), "+f"(d[3])
                 : "r"(a[0]), "r"(a[1]), "r"(a[2]), "r"(a[3]), "r"(b[0]), "r"(b[1]));
}

// packed f32x2 helpers (Blackwell family baseline, PTX-only)
__device__ __forceinline__ uint64_t pk2(float lo, float hi) {
    uint64_t r;
    asm("mov.b64 %0, {%1, %2};" : "=l"(r) : "f"(lo), "f"(hi));
    return r;
}
__device__ __forceinline__ void upk2(float& lo, float& hi, uint64_t v) {
    asm("mov.b64 {%0, %1}, %2;" : "=f"(lo), "=f"(hi) : "l"(v));
}
__device__ __forceinline__ void fma2(uint64_t& d, uint64_t a, uint64_t b) {
    asm("fma.rn.f32x2 %0, %1, %2, %0;" : "+l"(d) : "l"(a), "l"(b));
}
__device__ __forceinline__ void mul2(uint64_t& d, uint64_t a, uint64_t b) {
    asm("mul.rn.f32x2 %0, %1, %2;" : "=l"(d) : "l"(a), "l"(b));
}

// packed-poly tanh-gelu on an m-pair: outputs two scalars
__device__ __forceinline__ void gelu_tanh2(uint64_t v2, float& p0, float& p1) {
    const uint64_t c1_2 = pk2(0.03567740814f, 0.03567740814f);
    uint64_t vv2; mul2(vv2, v2, v2);
    uint64_t t2 = pk2(0.79788456080f, 0.79788456080f);
    fma2(t2, vv2, c1_2);                 // t2 = vv2*c1 + c0
    uint64_t s2; mul2(s2, v2, t2);       // s = v*(c0 + c1 v^2)
    float s0, s1; upk2(s0, s1, s2);
    float th0, th1;
    asm("tanh.approx.f32 %0, %1;" : "=f"(th0) : "f"(s0));
    asm("tanh.approx.f32 %0, %1;" : "=f"(th1) : "f"(s1));
    float v0, v1; upk2(v0, v1, v2);
    float hv0 = 0.5f * v0, hv1 = 0.5f * v1;
    p0 = fmaf(hv0, th0, hv0);
    p1 = fmaf(hv1, th1, hv1);
}

// ============ kernel 0: h[d][t] = irfft(W_d)[t] — one block per d ============
__global__ void k_build_h(const float* __restrict__ cw) {
    __shared__ float ct[288], st[288];
    int t = threadIdx.x;  // 288 threads
    int d = blockIdx.x;   // 16 blocks
    float ang = 6.283185307179586f * (float)t * (1.0f / 288.0f);
    ct[t] = cosf(ang);
    st[t] = sinf(ang);
    __syncthreads();
    float wr0  = cw[(0 * 16 + d) * 2];
    float wnyq = cw[(144 * 16 + d) * 2];
    float acc = wr0 + ((t & 1) ? -wnyq : wnyq);
    float s2 = 0.0f;
    int idx = 0;
    for (int k = 1; k <= 143; k++) {
        idx += t; if (idx >= 288) idx -= 288;
        float wr = cw[(k * 16 + d) * 2];
        float wi = cw[(k * 16 + d) * 2 + 1];
        s2 += wr * ct[idx] - wi * st[idx];
    }
    g_h[d * 288 + t] = (acc + 2.0f * s2) * (1.0f / 288.0f);
}

// ============ kernel 1: H bf16 circulant [d][m][k<288] ============
__global__ void k_expand_Hb() {
    int m = blockIdx.x;      // 288
    int d = blockIdx.y;      // 16
    int j = threadIdx.x;     // 288
    int t = m - j; if (t < 0) t += 288;
    g_Hb[((size_t)d * 288 + m) * KP + j] = __float2bfloat16(g_h[d * 288 + t]);
}

// ============ kernel 1b: transpose pose [b][512][196] -> g_poseT [b][196][512] ============
__global__ void k_transpose_pose(const float* __restrict__ pose) {
    __shared__ float tile[32][33];
    const int pix0 = blockIdx.x * 32;   // 7 tiles (196)
    const int ch0  = blockIdx.y * 32;   // 16 tiles (512)
    const int bb   = blockIdx.z;        // 4
    const int tx = threadIdx.x, ty = threadIdx.y;  // 32 x 8
    #pragma unroll
    for (int k = 0; k < 4; k++) {
        int ch = ch0 + ty + k * 8;
        int pix = pix0 + tx;
        float v = 0.0f;
        if (pix < LL) v = pose[((size_t)bb * 512 + ch) * LL + pix];
        tile[ty + k * 8][tx] = v;
    }
    __syncthreads();
    #pragma unroll
    for (int k = 0; k < 4; k++) {
        int pix = pix0 + ty + k * 8;
        int ch = ch0 + tx;
        if (pix < LL)
            g_poseT[((size_t)bb * LL + pix) * 512 + ch] = tile[tx][ty + k * 8];
    }
}

// ============ kernel 2: per-position producer ============
extern __shared__ float smem_dyn[];
__global__ void __launch_bounds__(256, 3) k_main(
    const float* __restrict__ a_in,
    const float* __restrict__ mpose_w, const float* __restrict__ mpose_b,
    const float* __restrict__ cpose2_w, const float* __restrict__ cpose2_b,
    const float* __restrict__ ln_gamma, const float* __restrict__ ln_beta,
    const float* __restrict__ sp_w, const float* __restrict__ sp_b,
    float* __restrict__ out)
{
    // s_pu pair-packed: [p=m/2][c] float2 {pu[2p][c], pu[2p+1][c]}, 32 floats/row (128B)
    float* s_pu  = smem_dyn;               // 4608
    float* s_lg  = s_pu  + 4608;           // [288][17]
    float* s_gn  = s_lg  + 4896;           // [288][17]
    float* s_cw2 = s_gn  + 4896;           // [16][18 float2] = 576
    float* s_cb  = s_cw2 + 576;
    float* s_spw = s_cb  + 16;
    float* s_spb = s_spw + 81;
    float* s_gam = s_spb + 16;
    float* s_bet = s_gam + 32;
    float* s_au  = s_bet + 32;
    float* s_mu  = s_au  + 288;
    float* s_rs  = s_mu  + 144;
    float* s_red = s_rs  + 144;
    float* s_ars = s_red + 256;            // stores 1/ar_sum
    float* s_aus = s_ars + 16;

    const int tid = threadIdx.x;
    const int bl = blockIdx.x;
    const int b = bl / LL, l = bl % LL;
    const int y = l / HW, x = l % HW;

    {
        int Bi = tid >> 4, c = tid & 15;
        float v = cpose2_w[tid];
        s_cw2[Bi * 36 + c * 2]     = v;     // packed {w,w}
        s_cw2[Bi * 36 + c * 2 + 1] = v;
        if (tid < 16)  s_cb[tid]  = cpose2_b[tid];
        if (tid < 81)  s_spw[tid] = sp_w[tid];
        if (tid < 9)   s_spb[tid] = sp_b[tid];
        if (tid < 32)  s_gam[tid] = ln_gamma[tid];
        if (tid >= 32 && tid < 64) s_bet[tid - 32] = ln_beta[tid - 32];
    }

    // S1: gather pu from transposed pose (coalesced: 9 pixels x 512 consecutive floats)
    {
        int ch = tid * 2;
        int ai = ch >> 4, c = ch & 15;
        #pragma unroll
        for (int kk = 0; kk < 9; kk++) {
            int py = y + kk / 3 - 1, px = x + kk % 3 - 1;
            float2 v = make_float2(0.0f, 0.0f);
            if ((unsigned)py < 14u && (unsigned)px < 14u)
                v = reinterpret_cast<const float2*>(
                        g_poseT + ((size_t)b * LL + py * 14 + px) * 512)[tid];
            int m = kk * 32 + ai;
            int base = (m >> 1) * 32 + (m & 1);
            s_pu[base + c * 2]       = v.x;
            s_pu[base + (c + 1) * 2] = v.y;
        }
    }
    for (int m = tid; m < 288; m += 256) {
        int kk = m >> 5, ai = m & 31;
        int py = y + kk / 3 - 1, px = x + kk % 3 - 1;
        float v = 0.0f;
        if ((unsigned)py < 14u && (unsigned)px < 14u)
            v = a_in[(((size_t)b * 32 + ai) * 14 + py) * 14 + px];
        s_au[m] = v;
    }
    __syncthreads();

    // S2: logits, m-pairs via fma.rn.f32x2 (Bi is loop-invariant per thread)
    {
        const int Bi = tid & 15;
        uint64_t w2[16];
        const uint64_t* cwp = reinterpret_cast<const uint64_t*>(s_cw2 + Bi * 36);
        #pragma unroll
        for (int c = 0; c < 16; c++) w2[c] = cwp[c];
        float cbv = s_cb[Bi];
        uint64_t cb2 = pk2(cbv, cbv);
        for (int idx = tid; idx < 2304; idx += 256) {
            int p = idx >> 4;
            const ulonglong2* pv = reinterpret_cast<const ulonglong2*>(s_pu + p * 32);
            uint64_t acc2 = cb2;
            #pragma unroll
            for (int c2 = 0; c2 < 8; c2++) {
                ulonglong2 u = pv[c2];
                fma2(acc2, u.x, w2[c2 * 2]);
                fma2(acc2, u.y, w2[c2 * 2 + 1]);
            }
            float lo, hi; upk2(lo, hi, acc2);
            s_lg[(2 * p) * 17 + Bi]     = lo;
            s_lg[(2 * p + 1) * 17 + Bi] = hi;
        }
    }
    __syncthreads();

    // S3: LayerNorm over a
    if (tid < 144) {
        int kk = tid >> 4, Bi = tid & 15;
        float s = 0.0f, s2 = 0.0f;
        #pragma unroll 4
        for (int ai = 0; ai < 32; ai++) {
            float v = s_lg[(kk * 32 + ai) * 17 + Bi];
            s += v; s2 += v * v;
        }
        float mu = s * (1.0f / 32.0f);
        float var = s2 * (1.0f / 32.0f) - mu * mu;
        s_mu[tid] = mu;
        s_rs[tid] = rsqrtf(var + 1e-5f);
    }
    __syncthreads();
    for (int idx = tid; idx < 4608; idx += 256) {
        int m = idx >> 4, Bi = idx & 15;
        int kk = m >> 5, ai = m & 31;
        float v = s_lg[m * 17 + Bi];
        s_gn[m * 17 + Bi] = (v - s_mu[kk * 16 + Bi]) * s_rs[kk * 16 + Bi] * s_gam[ai] + s_bet[ai];
    }
    __syncthreads();

    // S4: spatial gate (exact-poly gelu: logits feed softmax, keep precision)
    for (int idx = tid; idx < 4608; idx += 256) {
        int m = idx >> 4, Bi = idx & 15;
        int o = m >> 5, ai = m & 31;
        float acc = s_spb[o];
        #pragma unroll
        for (int i = 0; i < 9; i++)
            acc = fmaf(s_spw[o * 9 + i], s_gn[(i * 32 + ai) * 17 + Bi], acc);
        s_lg[m * 17 + Bi] = 2.0f * s_lg[m * 17 + Bi] + gelu_fast(acc);
    }
    __syncthreads();

    // S5: softmax over Bi; au sum
    for (int m = tid; m < 288; m += 256) {
        float* row = s_lg + m * 17;
        float mx = row[0];
        #pragma unroll
        for (int i = 1; i < 16; i++) mx = fmaxf(mx, row[i]);
        float s = 0.0f;
        #pragma unroll
        for (int i = 0; i < 16; i++) { float e = __expf(row[i] - mx); row[i] = e; s += e; }
        float inv = 1.0f / s;
        #pragma unroll
        for (int i = 0; i < 16; i++) row[i] *= inv;
    }
    if (tid < 32) {
        float p = 0.0f;
        for (int m = tid; m < 288; m += 32) p += s_au[m];
        #pragma unroll
        for (int o = 16; o; o >>= 1) p += __shfl_xor_sync(0xffffffffu, p, o);
        if (tid == 0) *s_aus = p;
    }
    __syncthreads();

    // S6: ar and ar_sum
    {
        int Bi = tid & 15, ck = tid >> 4;
        float p = 0.0f;
        #pragma unroll 2
        for (int r = 0; r < 18; r++) {
            int m = ck * 18 + r;
            float ar = s_au[m] * s_lg[m * 17 + Bi];
            s_gn[m * 17 + Bi] = ar;
            p += ar;
        }
        s_red[ck * 16 + Bi] = p;
    }
    __syncthreads();
    if (tid < 16) {
        float s = 0.0f;
        #pragma unroll
        for (int c = 0; c < 16; c++) s += s_red[c * 16 + tid];
        s_ars[tid] = rcp_approx(s);                            // store reciprocal
        out[((size_t)b * 16 + tid) * LL + l] = s / (*s_aus);
    }
    __syncthreads();

    // S7: coeff = ar * (1/ars); write C[m][col]
    for (int idx = tid; idx < 4608; idx += 256) {
        int m = idx >> 4, Bi = idx & 15;
        float cf = s_gn[m * 17 + Bi] * s_ars[Bi];
        s_gn[m * 17 + Bi] = cf;
        g_C[(size_t)m * NCOL + (size_t)bl * 16 + Bi] = cf;
    }
    __syncthreads();

    // S8: p = gelu_tanh(pu@W^T+b) via fma.rn.f32x2 m-pairs; po_base; P bf16 FLAT [d][col][k]
    {
        int Bi = tid & 15, d = tid >> 4;
        int e = Bi * 16 + d;
        uint64_t W2[16];
        #pragma unroll
        for (int c = 0; c < 16; c++) {
            float w = mpose_w[e * 16 + c];
            W2[c] = pk2(w, w);
        }
        float bsv = mpose_b[e];
        uint64_t bs2 = pk2(bsv, bsv);
        float acc = 0.0f;
        uint4* Pd4 = reinterpret_cast<uint4*>(
            g_Pb + ((size_t)d * NCOL + (size_t)bl * 16 + Bi) * KP);
        for (int g = 0; g < 36; g++) {            // 36 * 8 = 288 m-values
            uint32_t pkk[4];
            #pragma unroll
            for (int pp = 0; pp < 4; pp++) {
                int p = g * 4 + pp;               // m-pair (2p, 2p+1)
                const ulonglong2* pv = reinterpret_cast<const ulonglong2*>(s_pu + p * 32);
                uint64_t v2 = bs2;
                #pragma unroll
                for (int c2 = 0; c2 < 8; c2++) {
                    ulonglong2 u = pv[c2];
                    fma2(v2, u.x, W2[c2 * 2]);
                    fma2(v2, u.y, W2[c2 * 2 + 1]);
                }
                float p0, p1;
                gelu_tanh2(v2, p0, p1);
                acc = fmaf(s_gn[(2 * p) * 17 + Bi],     p0, acc);
                acc = fmaf(s_gn[(2 * p + 1) * 17 + Bi], p1, acc);
                __nv_bfloat162 h2 = __floats2bfloat162_rn(p0, p1);
                pkk[pp] = *reinterpret_cast<uint32_t*>(&h2);
            }
            Pd4[g] = make_uint4(pkk[0], pkk[1], pkk[2], pkk[3]);
        }
        out[12544 + (size_t)b * 50176 + (size_t)e * LL + l] = acc;
    }
}

// ============ kernel 3: mma.sync bf16 circulant GEMM + fused coeff reduction ============
// Tile m=96 x col=128, 2 CTA/SM, K = 4x64 + 1x32 tail.
// 3-stage cp.async pipeline, ONE __syncthreads per chunk:
//   per chunk c: wait(1) -> sync -> issue load(c+2) -> mma(c)
// The sync both publishes chunk c's data CTA-wide and guarantees mma(c-1)
// finished before stage (c+2)%3 == (c-1)%3 is overwritten.
#define SA_STG 12288            // 96 rows x 128B
#define SB_STG 16384            // 128 rows x 128B
#define GEMM_SMEM (3 * SA_STG + 3 * SB_STG)

__global__ void __launch_bounds__(256, 2) k_gemm_mma(float* __restrict__ out) {
    extern __shared__ __align__(128) char smemc[];
    const uint32_t sb = smem_u32(smemc);
    const int tid  = threadIdx.x;
    const int lane = tid & 31;
    const int wid  = tid >> 5;
    const int wm   = wid >> 2;          // 0..1  (m-warp, 48 rows each)
    const int wn   = wid & 3;           // 0..3  (n-warp, 32 cols each)

    const int d    = blockIdx.z;
    const int m0   = blockIdx.y * 96;
    const int col0 = blockIdx.x * 128;

    const __nv_bfloat16* Hg = g_Hb + ((size_t)d * 288 + m0) * KP;
    const __nv_bfloat16* Pg = g_Pb + ((size_t)d * NCOL + col0) * KP;

    float acc[3][4][4];
    #pragma unroll
    for (int r = 0; r < 3; r++)
        #pragma unroll
        for (int q = 0; q < 4; q++)
            #pragma unroll
            for (int i = 0; i < 4; i++) acc[r][q][i] = 0.0f;

    auto load_chunk64 = [&](int c, int s) {
        uint32_t abase = sb + s * SA_STG;
        uint32_t bbase = sb + 3 * SA_STG + s * SB_STG;
        #pragma unroll
        for (int it = 0; it < 3; it++) {
            int i = tid + it * 256;
            int row = i >> 3, u = i & 7;
            cp_async16(abase + row * 128 + ((u ^ (row & 7)) << 4),
                       Hg + (size_t)row * KP + c * 64 + u * 8);
        }
        #pragma unroll
        for (int it = 0; it < 4; it++) {
            int i = tid + it * 256;
            int row = i >> 3, u = i & 7;
            cp_async16(bbase + row * 128 + ((u ^ (row & 7)) << 4),
                       Pg + (size_t)row * KP + c * 64 + u * 8);
        }
        CP_COMMIT();
    };
    auto load_chunk32 = [&](int s) {
        uint32_t abase = sb + s * SA_STG;
        uint32_t bbase = sb + 3 * SA_STG + s * SB_STG;
        #pragma unroll
        for (int it = 0; it < 2; it++) {
            int i = tid + it * 256;
            if (i < 384) {
                int row = i >> 2, u = i & 3;
                cp_async16(abase + row * 128 + ((u ^ (row & 7)) << 4),
                           Hg + (size_t)row * KP + 256 + u * 8);
            }
        }
        #pragma unroll
        for (int it = 0; it < 2; it++) {
            int i = tid + it * 256;
            int row = i >> 2, u = i & 3;
            cp_async16(bbase + row * 128 + ((u ^ (row & 7)) << 4),
                       Pg + (size_t)row * KP + 256 + u * 8);
        }
        CP_COMMIT();
    };

    const int a_row_l = wm * 48 + (lane & 15);
    const int a_chalf = lane >> 4;
    const int b_row_l = wn * 32 + ((lane >> 4) << 3) + (lane & 7);
    const int b_chalf = (lane >> 3) & 1;

    // mma over nks k16-steps in stage s
    auto mma_stage = [&](int s, int nks) {
        uint32_t Ab = sb + s * SA_STG;
        uint32_t Bb = sb + 3 * SA_STG + s * SB_STG;
        for (int ks = 0; ks < nks; ks++) {
            uint32_t a[3][4], bfrag[4][2];
            #pragma unroll
            for (int r = 0; r < 3; r++) {
                int row = a_row_l + r * 16;
                int c16 = ks * 2 + a_chalf;
                ldsm_x4(a[r][0], a[r][1], a[r][2], a[r][3],
                        Ab + row * 128 + (((c16 ^ (row & 7)) & 7) << 4));
            }
            #pragma unroll
            for (int qp = 0; qp < 2; qp++) {
                int row = b_row_l + qp * 16;
                int c16 = ks * 2 + b_chalf;
                ldsm_x4(bfrag[qp * 2][0], bfrag[qp * 2][1],
                        bfrag[qp * 2 + 1][0], bfrag[qp * 2 + 1][1],
                        Bb + row * 128 + (((c16 ^ (row & 7)) & 7) << 4));
            }
            #pragma unroll
            for (int r = 0; r < 3; r++)
                #pragma unroll
                for (int q = 0; q < 4; q++)
                    mma_bf16(acc[r][q], a[r], bfrag[q]);
        }
    };

    // prologue: chunks 0,1 into stages 0,1
    load_chunk64(0, 0);
    load_chunk64(1, 1);
    // c=0
    CP_WAIT(1); __syncthreads(); load_chunk64(2, 2); mma_stage(0, 4);
    // c=1
    CP_WAIT(1); __syncthreads(); load_chunk64(3, 0); mma_stage(1, 4);
    // c=2
    CP_WAIT(1); __syncthreads(); load_chunk32(1);    mma_stage(2, 4);
    // c=3
    CP_WAIT(1); __syncthreads();                     mma_stage(0, 4);
    // c=4 (32-wide tail in stage 1)
    CP_WAIT(0); __syncthreads();                     mma_stage(1, 2);

    // fused epilogue: s[col] = sum_m C[m,col] * D[m,col]
    float s[8];
    #pragma unroll
    for (int j = 0; j < 8; j++) s[j] = 0.0f;
    const int colb = col0 + wn * 32 + ((lane & 3) << 1);
    #pragma unroll
    for (int r = 0; r < 3; r++) {
        #pragma unroll
        for (int half = 0; half < 2; half++) {
            int m = m0 + wm * 48 + r * 16 + (lane >> 2) + half * 8;
            const float* Crow = g_C + (size_t)m * NCOL;
            #pragma unroll
            for (int q = 0; q < 4; q++) {
                s[q * 2 + 0] = fmaf(Crow[colb + q * 8 + 0], acc[r][q][half * 2 + 0], s[q * 2 + 0]);
                s[q * 2 + 1] = fmaf(Crow[colb + q * 8 + 1], acc[r][q][half * 2 + 1], s[q * 2 + 1]);
            }
        }
    }
    #pragma unroll
    for (int off = 4; off < 32; off <<= 1)
        #pragma unroll
        for (int j = 0; j < 8; j++) s[j] += __shfl_xor_sync(0xffffffffu, s[j], off);

    if (lane < 4) {
        #pragma unroll
        for (int q = 0; q < 4; q++) {
            #pragma unroll
            for (int j = 0; j < 2; j++) {
                int col = col0 + wn * 32 + q * 8 + lane * 2 + j;
                int bl = col >> 4, Bi = col & 15;
                int bb = bl / LL, ll = bl % LL;
                atomicAdd(&out[12544 + (size_t)bb * 50176 + (size_t)(Bi * 16 + d) * LL + ll],
                          s[q * 2 + j]);
            }
        }
    }
}

// ---------------- launch ----------------
extern "C" void kernel_launch(void* const* d_in, const int* in_sizes, int n_in,
                              void* d_out, int out_size) {
    const float* a     = (const float*)d_in[0];
    const float* pose  = (const float*)d_in[1];
    const float* mw    = (const float*)d_in[2];
    const float* mb    = (const float*)d_in[3];
    const float* cw2   = (const float*)d_in[4];
    const float* cb2   = (const float*)d_in[5];
    const float* cplx  = (const float*)d_in[6];
    const float* gam   = (const float*)d_in[7];
    const float* bet   = (const float*)d_in[8];
    const float* spw   = (const float*)d_in[9];
    const float* spb   = (const float*)d_in[10];
    float* out = (float*)d_out;

    size_t smem_floats = (size_t)4608 + 4896 + 4896 + 576 + 16 + 81 + 16 + 32 + 32 + 288 + 144 + 144 + 256 + 16 + 1;
    size_t smem_bytes = smem_floats * sizeof(float);
    cudaFuncSetAttribute(k_main, cudaFuncAttributeMaxDynamicSharedMemorySize, (int)smem_bytes);
    cudaFuncSetAttribute(k_gemm_mma, cudaFuncAttributeMaxDynamicSharedMemorySize, GEMM_SMEM);

    k_build_h<<<16, 288>>>(cplx);
    k_expand_Hb<<<dim3(288, 16), 288>>>();
    k_transpose_pose<<<dim3(7, 16, NBSZ), dim3(32, 8)>>>(pose);
    k_main<<<NBL, 256, smem_bytes>>>(a, mw, mb, cw2, cb2, gam, bet, spw, spb, out);
    k_gemm_mma<<<dim3(NCOL / 128, 288 / 96, 16), 256, GEMM_SMEM>>>(out);
}

// round 16
// speedup vs baseline: 1.5110x; 1.0002x over previous
#include <cuda_runtime.h>
#include <cuda_bf16.h>
#include <math.h>
#include <stdint.h>

// ---------------- problem constants ----------------
#define AA    32
#define CC    16
#define KKn   9
#define KKA   288
#define NB    16      // Bc
#define ND    16      // D
#define NE    256     // Bc*D
#define HW    14
#define LL    196
#define NBSZ  4
#define NBL   784     // NBSZ*LL
#define NCOL  12544   // NBL*NB
#define KKA2  145
#define KP    288     // K for tensor GEMM (4 x 64 + 1 x 32, no padding)

// ---------------- scratch (static device mem; no allocs allowed) ----------------
__device__ float g_h[16 * 288];                                        //  18 KB
__device__ __align__(1024) __nv_bfloat16 g_Hb[(size_t)16 * 288 * KP];  //  2.65 MB  H circulant bf16 [d][m][k]
__device__ __align__(1024) __nv_bfloat16 g_Pb[(size_t)16 * NCOL * KP]; //  115.7 MB P bf16 [d][col][k] (FLAT)
__device__ float g_C[(size_t)288 * NCOL];                              //  14.4 MB  coeff [m][col]
__device__ __align__(128) float g_poseT[(size_t)NBSZ * LL * 512];      //  1.6 MB   pose transposed [b][pix][ch]

// lean exact-gelu via Abramowitz-Stegun 7.1.26 erf (|abs err| <= 1.5e-7) — used in S4 gate
__device__ __forceinline__ float rcp_approx(float x) {
    float r; asm("rcp.approx.f32 %0, %1;" : "=f"(r) : "f"(x)); return r;
}
__device__ __forceinline__ float gelu_fast(float v) {
    float x  = v * 0.70710678118654752f;
    float ax = fabsf(x);
    float t  = rcp_approx(fmaf(0.3275911f, ax, 1.0f));
    float poly = t * fmaf(t, fmaf(t, fmaf(t, fmaf(t, 1.061405429f, -1.453152027f),
                                          1.421413741f), -0.284496736f), 0.254829592f);
    float e  = __expf(-ax * ax);
    float r  = fmaf(poly, -e, 1.0f);
    float erfv = copysignf(r, x);
    float hv = 0.5f * v;
    return fmaf(hv, erfv, hv);
}

// ---------------- PTX helpers ----------------
__device__ __forceinline__ uint32_t smem_u32(const void* p) {
    uint32_t a;
    asm("{ .reg .u64 t; cvta.to.shared.u64 t, %1; cvt.u32.u64 %0, t; }" : "=r"(a) : "l"(p));
    return a;
}
__device__ __forceinline__ void cp_async16(uint32_t saddr, const void* gaddr) {
    asm volatile("cp.async.cg.shared.global [%0], [%1], 16;" :: "r"(saddr), "l"(gaddr) : "memory");
}
#define CP_COMMIT() asm volatile("cp.async.commit_group;" ::: "memory")
#define CP_WAIT(n)  asm volatile("cp.async.wait_group %0;" :: "n"(n) : "memory")

__device__ __forceinline__ void ldsm_x4(uint32_t& r0, uint32_t& r1, uint32_t& r2, uint32_t& r3,
                                        uint32_t addr) {
    asm volatile("ldmatrix.sync.aligned.m8n8.x4.shared.b16 {%0,%1,%2,%3}, [%4];"
                 : "=r"(r0), "=r"(r1), "=r"(r2), "=r"(r3) : "r"(addr));
}
__device__ __forceinline__ void mma_bf16(float* d, const uint32_t* a, const uint32_t* b) {
    asm volatile("mma.sync.aligned.m16n8k16.row.col.f32.bf16.bf16.f32 "
                 "{%0,%1,%2,%3}, {%4,%5,%6,%7}, {%8,%9}, {%0,%1,%2,%3};"
                 : "+f"(d[0]), "+f"(d[1]), "+f"(d[2]), "+f"(d[3])
                 : "r"(a[0]), "r"(a[1]), "r"(a[2]), "r"(a[3]), "r"(b[0]), "r"(b[1]));
}

// packed f32x2 helpers (Blackwell family baseline, PTX-only)
__device__ __forceinline__ uint64_t pk2(float lo, float hi) {
    uint64_t r;
    asm("mov.b64 %0, {%1, %2};" : "=l"(r) : "f"(lo), "f"(hi));
    return r;
}
__device__ __forceinline__ void upk2(float& lo, float& hi, uint64_t v) {
    asm("mov.b64 {%0, %1}, %2;" : "=f"(lo), "=f"(hi) : "l"(v));
}
__device__ __forceinline__ void fma2(uint64_t& d, uint64_t a, uint64_t b) {
    asm("fma.rn.f32x2 %0, %1, %2, %0;" : "+l"(d) : "l"(a), "l"(b));
}
__device__ __forceinline__ void mul2(uint64_t& d, uint64_t a, uint64_t b) {
    asm("mul.rn.f32x2 %0, %1, %2;" : "=l"(d) : "l"(a), "l"(b));
}

// packed-poly tanh-gelu on an m-pair: outputs two scalars
__device__ __forceinline__ void gelu_tanh2(uint64_t v2, float& p0, float& p1) {
    const uint64_t c1_2 = pk2(0.03567740814f, 0.03567740814f);
    uint64_t vv2; mul2(vv2, v2, v2);
    uint64_t t2 = pk2(0.79788456080f, 0.79788456080f);
    fma2(t2, vv2, c1_2);                 // t2 = vv2*c1 + c0
    uint64_t s2; mul2(s2, v2, t2);       // s = v*(c0 + c1 v^2)
    float s0, s1; upk2(s0, s1, s2);
    float th0, th1;
    asm("tanh.approx.f32 %0, %1;" : "=f"(th0) : "f"(s0));
    asm("tanh.approx.f32 %0, %1;" : "=f"(th1) : "f"(s1));
    float v0, v1; upk2(v0, v1, v2);
    float hv0 = 0.5f * v0, hv1 = 0.5f * v1;
    p0 = fmaf(hv0, th0, hv0);
    p1 = fmaf(hv1, th1, hv1);
}

// ============ kernel 0: h[d][t] = irfft(W_d)[t] — one block per d ============
__global__ void k_build_h(const float* __restrict__ cw) {
    __shared__ float ct[288], st[288];
    int t = threadIdx.x;  // 288 threads
    int d = blockIdx.x;   // 16 blocks
    float ang = 6.283185307179586f * (float)t * (1.0f / 288.0f);
    ct[t] = cosf(ang);
    st[t] = sinf(ang);
    __syncthreads();
    float wr0  = cw[(0 * 16 + d) * 2];
    float wnyq = cw[(144 * 16 + d) * 2];
    float acc = wr0 + ((t & 1) ? -wnyq : wnyq);
    float s2 = 0.0f;
    int idx = 0;
    for (int k = 1; k <= 143; k++) {
        idx += t; if (idx >= 288) idx -= 288;
        float wr = cw[(k * 16 + d) * 2];
        float wi = cw[(k * 16 + d) * 2 + 1];
        s2 += wr * ct[idx] - wi * st[idx];
    }
    g_h[d * 288 + t] = (acc + 2.0f * s2) * (1.0f / 288.0f);
}

// ============ kernel 1: H bf16 circulant [d][m][k<288] ============
__global__ void k_expand_Hb() {
    int m = blockIdx.x;      // 288
    int d = blockIdx.y;      // 16
    int j = threadIdx.x;     // 288
    int t = m - j; if (t < 0) t += 288;
    g_Hb[((size_t)d * 288 + m) * KP + j] = __float2bfloat16(g_h[d * 288 + t]);
}

// ============ kernel 1b: transpose pose [b][512][196] -> g_poseT [b][196][512] ============
__global__ void k_transpose_pose(const float* __restrict__ pose) {
    __shared__ float tile[32][33];
    const int pix0 = blockIdx.x * 32;   // 7 tiles (196)
    const int ch0  = blockIdx.y * 32;   // 16 tiles (512)
    const int bb   = blockIdx.z;        // 4
    const int tx = threadIdx.x, ty = threadIdx.y;  // 32 x 8
    #pragma unroll
    for (int k = 0; k < 4; k++) {
        int ch = ch0 + ty + k * 8;
        int pix = pix0 + tx;
        float v = 0.0f;
        if (pix < LL) v = pose[((size_t)bb * 512 + ch) * LL + pix];
        tile[ty + k * 8][tx] = v;
    }
    __syncthreads();
    #pragma unroll
    for (int k = 0; k < 4; k++) {
        int pix = pix0 + ty + k * 8;
        int ch = ch0 + tx;
        if (pix < LL)
            g_poseT[((size_t)bb * LL + pix) * 512 + ch] = tile[tx][ty + k * 8];
    }
}

// ============ kernel 2: per-position producer ============
extern __shared__ float smem_dyn[];
__global__ void __launch_bounds__(256, 3) k_main(
    const float* __restrict__ a_in,
    const float* __restrict__ mpose_w, const float* __restrict__ mpose_b,
    const float* __restrict__ cpose2_w, const float* __restrict__ cpose2_b,
    const float* __restrict__ ln_gamma, const float* __restrict__ ln_beta,
    const float* __restrict__ sp_w, const float* __restrict__ sp_b,
    float* __restrict__ out)
{
    // s_pu pair-packed: [p=m/2][c] float2 {pu[2p][c], pu[2p+1][c]}, 32 floats/row (128B)
    float* s_pu  = smem_dyn;               // 4608
    float* s_lg  = s_pu  + 4608;           // [288][17]; after S6 reused as s_cfp [144][16] float2
    float* s_gn  = s_lg  + 4896;           // [288][17]
    float* s_cw2 = s_gn  + 4896;           // [16][18 float2] = 576
    float* s_cb  = s_cw2 + 576;
    float* s_spw = s_cb  + 16;
    float* s_spb = s_spw + 81;
    float* s_gam = s_spb + 16;
    float* s_bet = s_gam + 32;
    float* s_au  = s_bet + 32;
    float* s_mu  = s_au  + 288;
    float* s_rs  = s_mu  + 144;
    float* s_red = s_rs  + 144;
    float* s_ars = s_red + 256;            // stores 1/ar_sum
    float* s_aus = s_ars + 16;
    float* s_cfp = s_lg;                   // alias: coeff pair-packed [p][Bi] float2 (4608 <= 4896)

    const int tid = threadIdx.x;
    const int bl = blockIdx.x;
    const int b = bl / LL, l = bl % LL;
    const int y = l / HW, x = l % HW;

    {
        int Bi = tid >> 4, c = tid & 15;
        float v = cpose2_w[tid];
        s_cw2[Bi * 36 + c * 2]     = v;     // packed {w,w}
        s_cw2[Bi * 36 + c * 2 + 1] = v;
        if (tid < 16)  s_cb[tid]  = cpose2_b[tid];
        if (tid < 81)  s_spw[tid] = sp_w[tid];
        if (tid < 9)   s_spb[tid] = sp_b[tid];
        if (tid < 32)  s_gam[tid] = ln_gamma[tid];
        if (tid >= 32 && tid < 64) s_bet[tid - 32] = ln_beta[tid - 32];
    }

    // S1: gather pu from transposed pose (coalesced: 9 pixels x 512 consecutive floats)
    {
        int ch = tid * 2;
        int ai = ch >> 4, c = ch & 15;
        #pragma unroll
        for (int kk = 0; kk < 9; kk++) {
            int py = y + kk / 3 - 1, px = x + kk % 3 - 1;
            float2 v = make_float2(0.0f, 0.0f);
            if ((unsigned)py < 14u && (unsigned)px < 14u)
                v = reinterpret_cast<const float2*>(
                        g_poseT + ((size_t)b * LL + py * 14 + px) * 512)[tid];
            int m = kk * 32 + ai;
            int base = (m >> 1) * 32 + (m & 1);
            s_pu[base + c * 2]       = v.x;
            s_pu[base + (c + 1) * 2] = v.y;
        }
    }
    for (int m = tid; m < 288; m += 256) {
        int kk = m >> 5, ai = m & 31;
        int py = y + kk / 3 - 1, px = x + kk % 3 - 1;
        float v = 0.0f;
        if ((unsigned)py < 14u && (unsigned)px < 14u)
            v = a_in[(((size_t)b * 32 + ai) * 14 + py) * 14 + px];
        s_au[m] = v;
    }
    __syncthreads();

    // S2: logits, m-pairs via fma.rn.f32x2 (Bi is loop-invariant per thread)
    {
        const int Bi = tid & 15;
        uint64_t w2[16];
        const uint64_t* cwp = reinterpret_cast<const uint64_t*>(s_cw2 + Bi * 36);
        #pragma unroll
        for (int c = 0; c < 16; c++) w2[c] = cwp[c];
        float cbv = s_cb[Bi];
        uint64_t cb2 = pk2(cbv, cbv);
        for (int idx = tid; idx < 2304; idx += 256) {
            int p = idx >> 4;
            const ulonglong2* pv = reinterpret_cast<const ulonglong2*>(s_pu + p * 32);
            uint64_t acc2 = cb2;
            #pragma unroll
            for (int c2 = 0; c2 < 8; c2++) {
                ulonglong2 u = pv[c2];
                fma2(acc2, u.x, w2[c2 * 2]);
                fma2(acc2, u.y, w2[c2 * 2 + 1]);
            }
            float lo, hi; upk2(lo, hi, acc2);
            s_lg[(2 * p) * 17 + Bi]     = lo;
            s_lg[(2 * p + 1) * 17 + Bi] = hi;
        }
    }
    __syncthreads();

    // S3: LayerNorm over a
    if (tid < 144) {
        int kk = tid >> 4, Bi = tid & 15;
        float s = 0.0f, s2 = 0.0f;
        #pragma unroll 4
        for (int ai = 0; ai < 32; ai++) {
            float v = s_lg[(kk * 32 + ai) * 17 + Bi];
            s += v; s2 += v * v;
        }
        float mu = s * (1.0f / 32.0f);
        float var = s2 * (1.0f / 32.0f) - mu * mu;
        s_mu[tid] = mu;
        s_rs[tid] = rsqrtf(var + 1e-5f);
    }
    __syncthreads();
    for (int idx = tid; idx < 4608; idx += 256) {
        int m = idx >> 4, Bi = idx & 15;
        int kk = m >> 5, ai = m & 31;
        float v = s_lg[m * 17 + Bi];
        s_gn[m * 17 + Bi] = (v - s_mu[kk * 16 + Bi]) * s_rs[kk * 16 + Bi] * s_gam[ai] + s_bet[ai];
    }
    __syncthreads();

    // S4: spatial gate (exact-poly gelu: logits feed softmax, keep precision)
    for (int idx = tid; idx < 4608; idx += 256) {
        int m = idx >> 4, Bi = idx & 15;
        int o = m >> 5, ai = m & 31;
        float acc = s_spb[o];
        #pragma unroll
        for (int i = 0; i < 9; i++)
            acc = fmaf(s_spw[o * 9 + i], s_gn[(i * 32 + ai) * 17 + Bi], acc);
        s_lg[m * 17 + Bi] = 2.0f * s_lg[m * 17 + Bi] + gelu_fast(acc);
    }
    __syncthreads();

    // S5: softmax over Bi; au sum
    for (int m = tid; m < 288; m += 256) {
        float* row = s_lg + m * 17;
        float mx = row[0];
        #pragma unroll
        for (int i = 1; i < 16; i++) mx = fmaxf(mx, row[i]);
        float s = 0.0f;
        #pragma unroll
        for (int i = 0; i < 16; i++) { float e = __expf(row[i] - mx); row[i] = e; s += e; }
        float inv = 1.0f / s;
        #pragma unroll
        for (int i = 0; i < 16; i++) row[i] *= inv;
    }
    if (tid < 32) {
        float p = 0.0f;
        for (int m = tid; m < 288; m += 32) p += s_au[m];
        #pragma unroll
        for (int o = 16; o; o >>= 1) p += __shfl_xor_sync(0xffffffffu, p, o);
        if (tid == 0) *s_aus = p;
    }
    __syncthreads();

    // S6: ar and ar_sum (ar -> s_gn; s_lg's r becomes dead after this stage)
    {
        int Bi = tid & 15, ck = tid >> 4;
        float p = 0.0f;
        #pragma unroll 2
        for (int r = 0; r < 18; r++) {
            int m = ck * 18 + r;
            float ar = s_au[m] * s_lg[m * 17 + Bi];
            s_gn[m * 17 + Bi] = ar;
            p += ar;
        }
        s_red[ck * 16 + Bi] = p;
    }
    __syncthreads();
    if (tid < 16) {
        float s = 0.0f;
        #pragma unroll
        for (int c = 0; c < 16; c++) s += s_red[c * 16 + tid];
        s_ars[tid] = rcp_approx(s);                            // store reciprocal
        out[((size_t)b * 16 + tid) * LL + l] = s / (*s_aus);
    }
    __syncthreads();

    // S7: coeff = ar * (1/ars); write C[m][col] and pair-packed s_cfp (aliases dead s_lg)
    for (int idx = tid; idx < 4608; idx += 256) {
        int m = idx >> 4, Bi = idx & 15;
        float cf = s_gn[m * 17 + Bi] * s_ars[Bi];
        s_cfp[(m >> 1) * 32 + Bi * 2 + (m & 1)] = cf;
        g_C[(size_t)m * NCOL + (size_t)bl * 16 + Bi] = cf;
    }
    __syncthreads();

    // S8: p = gelu_tanh(pu@W^T+b) via fma.rn.f32x2 m-pairs; po_base with packed
    // coeff (one LDS.64 + one fma2 per pair); P bf16 FLAT [d][col][k]
    {
        int Bi = tid & 15, d = tid >> 4;
        int e = Bi * 16 + d;
        uint64_t W2[16];
        #pragma unroll
        for (int c = 0; c < 16; c++) {
            float w = mpose_w[e * 16 + c];
            W2[c] = pk2(w, w);
        }
        float bsv = mpose_b[e];
        uint64_t bs2 = pk2(bsv, bsv);
        uint64_t acc2 = pk2(0.0f, 0.0f);
        const float* cf_base = s_cfp + Bi * 2;
        uint4* Pd4 = reinterpret_cast<uint4*>(
            g_Pb + ((size_t)d * NCOL + (size_t)bl * 16 + Bi) * KP);
        for (int g = 0; g < 36; g++) {            // 36 * 8 = 288 m-values
            uint32_t pkk[4];
            #pragma unroll
            for (int pp = 0; pp < 4; pp++) {
                int p = g * 4 + pp;               // m-pair (2p, 2p+1)
                const ulonglong2* pv = reinterpret_cast<const ulonglong2*>(s_pu + p * 32);
                uint64_t v2 = bs2;
                #pragma unroll
                for (int c2 = 0; c2 < 8; c2++) {
                    ulonglong2 u = pv[c2];
                    fma2(v2, u.x, W2[c2 * 2]);
                    fma2(v2, u.y, W2[c2 * 2 + 1]);
                }
                float p0, p1;
                gelu_tanh2(v2, p0, p1);
                uint64_t cf2 = *reinterpret_cast<const uint64_t*>(cf_base + p * 32);
                fma2(acc2, cf2, pk2(p0, p1));
                __nv_bfloat162 h2 = __floats2bfloat162_rn(p0, p1);
                pkk[pp] = *reinterpret_cast<uint32_t*>(&h2);
            }
            Pd4[g] = make_uint4(pkk[0], pkk[1], pkk[2], pkk[3]);
        }
        float a0, a1; upk2(a0, a1, acc2);
        out[12544 + (size_t)b * 50176 + (size_t)e * LL + l] = a0 + a1;
    }
}

// ============ kernel 3: mma.sync bf16 circulant GEMM + fused coeff reduction ============
// Tile m=96 x col=128, 2 CTA/SM, K = 4x64 + 1x32 tail.
// 3-stage cp.async pipeline, ONE __syncthreads per chunk (R15 config, ~152 us).
#define SA_STG 12288            // 96 rows x 128B
#define SB_STG 16384            // 128 rows x 128B
#define GEMM_SMEM (3 * SA_STG + 3 * SB_STG)

__global__ void __launch_bounds__(256, 2) k_gemm_mma(float* __restrict__ out) {
    extern __shared__ __align__(128) char smemc[];
    const uint32_t sb = smem_u32(smemc);
    const int tid  = threadIdx.x;
    const int lane = tid & 31;
    const int wid  = tid >> 5;
    const int wm   = wid >> 2;          // 0..1  (m-warp, 48 rows each)
    const int wn   = wid & 3;           // 0..3  (n-warp, 32 cols each)

    const int d    = blockIdx.z;
    const int m0   = blockIdx.y * 96;
    const int col0 = blockIdx.x * 128;

    const __nv_bfloat16* Hg = g_Hb + ((size_t)d * 288 + m0) * KP;
    const __nv_bfloat16* Pg = g_Pb + ((size_t)d * NCOL + col0) * KP;

    float acc[3][4][4];
    #pragma unroll
    for (int r = 0; r < 3; r++)
        #pragma unroll
        for (int q = 0; q < 4; q++)
            #pragma unroll
            for (int i = 0; i < 4; i++) acc[r][q][i] = 0.0f;

    auto load_chunk64 = [&](int c, int s) {
        uint32_t abase = sb + s * SA_STG;
        uint32_t bbase = sb + 3 * SA_STG + s * SB_STG;
        #pragma unroll
        for (int it = 0; it < 3; it++) {
            int i = tid + it * 256;
            int row = i >> 3, u = i & 7;
            cp_async16(abase + row * 128 + ((u ^ (row & 7)) << 4),
                       Hg + (size_t)row * KP + c * 64 + u * 8);
        }
        #pragma unroll
        for (int it = 0; it < 4; it++) {
            int i = tid + it * 256;
            int row = i >> 3, u = i & 7;
            cp_async16(bbase + row * 128 + ((u ^ (row & 7)) << 4),
                       Pg + (size_t)row * KP + c * 64 + u * 8);
        }
        CP_COMMIT();
    };
    auto load_chunk32 = [&](int s) {
        uint32_t abase = sb + s * SA_STG;
        uint32_t bbase = sb + 3 * SA_STG + s * SB_STG;
        #pragma unroll
        for (int it = 0; it < 2; it++) {
            int i = tid + it * 256;
            if (i < 384) {
                int row = i >> 2, u = i & 3;
                cp_async16(abase + row * 128 + ((u ^ (row & 7)) << 4),
                           Hg + (size_t)row * KP + 256 + u * 8);
            }
        }
        #pragma unroll
        for (int it = 0; it < 2; it++) {
            int i = tid + it * 256;
            int row = i >> 2, u = i & 3;
            cp_async16(bbase + row * 128 + ((u ^ (row & 7)) << 4),
                       Pg + (size_t)row * KP + 256 + u * 8);
        }
        CP_COMMIT();
    };

    const int a_row_l = wm * 48 + (lane & 15);
    const int a_chalf = lane >> 4;
    const int b_row_l = wn * 32 + ((lane >> 4) << 3) + (lane & 7);
    const int b_chalf = (lane >> 3) & 1;

    auto mma_stage = [&](int s, int nks) {
        uint32_t Ab = sb + s * SA_STG;
        uint32_t Bb = sb + 3 * SA_STG + s * SB_STG;
        for (int ks = 0; ks < nks; ks++) {
            uint32_t a[3][4], bfrag[4][2];
            #pragma unroll
            for (int r = 0; r < 3; r++) {
                int row = a_row_l + r * 16;
                int c16 = ks * 2 + a_chalf;
                ldsm_x4(a[r][0], a[r][1], a[r][2], a[r][3],
                        Ab + row * 128 + (((c16 ^ (row & 7)) & 7) << 4));
            }
            #pragma unroll
            for (int qp = 0; qp < 2; qp++) {
                int row = b_row_l + qp * 16;
                int c16 = ks * 2 + b_chalf;
                ldsm_x4(bfrag[qp * 2][0], bfrag[qp * 2][1],
                        bfrag[qp * 2 + 1][0], bfrag[qp * 2 + 1][1],
                        Bb + row * 128 + (((c16 ^ (row & 7)) & 7) << 4));
            }
            #pragma unroll
            for (int r = 0; r < 3; r++)
                #pragma unroll
                for (int q = 0; q < 4; q++)
                    mma_bf16(acc[r][q], a[r], bfrag[q]);
        }
    };

    load_chunk64(0, 0);
    load_chunk64(1, 1);
    CP_WAIT(1); __syncthreads(); load_chunk64(2, 2); mma_stage(0, 4);
    CP_WAIT(1); __syncthreads(); load_chunk64(3, 0); mma_stage(1, 4);
    CP_WAIT(1); __syncthreads(); load_chunk32(1);    mma_stage(2, 4);
    CP_WAIT(1); __syncthreads();                     mma_stage(0, 4);
    CP_WAIT(0); __syncthreads();                     mma_stage(1, 2);

    // fused epilogue: s[col] = sum_m C[m,col] * D[m,col]
    float s[8];
    #pragma unroll
    for (int j = 0; j < 8; j++) s[j] = 0.0f;
    const int colb = col0 + wn * 32 + ((lane & 3) << 1);
    #pragma unroll
    for (int r = 0; r < 3; r++) {
        #pragma unroll
        for (int half = 0; half < 2; half++) {
            int m = m0 + wm * 48 + r * 16 + (lane >> 2) + half * 8;
            const float* Crow = g_C + (size_t)m * NCOL;
            #pragma unroll
            for (int q = 0; q < 4; q++) {
                s[q * 2 + 0] = fmaf(Crow[colb + q * 8 + 0], acc[r][q][half * 2 + 0], s[q * 2 + 0]);
                s[q * 2 + 1] = fmaf(Crow[colb + q * 8 + 1], acc[r][q][half * 2 + 1], s[q * 2 + 1]);
            }
        }
    }
    #pragma unroll
    for (int off = 4; off < 32; off <<= 1)
        #pragma unroll
        for (int j = 0; j < 8; j++) s[j] += __shfl_xor_sync(0xffffffffu, s[j], off);

    if (lane < 4) {
        #pragma unroll
        for (int q = 0; q < 4; q++) {
            #pragma unroll
            for (int j = 0; j < 2; j++) {
                int col = col0 + wn * 32 + q * 8 + lane * 2 + j;
                int bl = col >> 4, Bi = col & 15;
                int bb = bl / LL, ll = bl % LL;
                atomicAdd(&out[12544 + (size_t)bb * 50176 + (size_t)(Bi * 16 + d) * LL + ll],
                          s[q * 2 + j]);
            }
        }
    }
}

// ---------------- launch ----------------
extern "C" void kernel_launch(void* const* d_in, const int* in_sizes, int n_in,
                              void* d_out, int out_size) {
    const float* a     = (const float*)d_in[0];
    const float* pose  = (const float*)d_in[1];
    const float* mw    = (const float*)d_in[2];
    const float* mb    = (const float*)d_in[3];
    const float* cw2   = (const float*)d_in[4];
    const float* cb2   = (const float*)d_in[5];
    const float* cplx  = (const float*)d_in[6];
    const float* gam   = (const float*)d_in[7];
    const float* bet   = (const float*)d_in[8];
    const float* spw   = (const float*)d_in[9];
    const float* spb   = (const float*)d_in[10];
    float* out = (float*)d_out;

    size_t smem_floats = (size_t)4608 + 4896 + 4896 + 576 + 16 + 81 + 16 + 32 + 32 + 288 + 144 + 144 + 256 + 16 + 1;
    size_t smem_bytes = smem_floats * sizeof(float);
    cudaFuncSetAttribute(k_main, cudaFuncAttributeMaxDynamicSharedMemorySize, (int)smem_bytes);
    cudaFuncSetAttribute(k_gemm_mma, cudaFuncAttributeMaxDynamicSharedMemorySize, GEMM_SMEM);

    k_build_h<<<16, 288>>>(cplx);
    k_expand_Hb<<<dim3(288, 16), 288>>>();
    k_transpose_pose<<<dim3(7, 16, NBSZ), dim3(32, 8)>>>(pose);
    k_main<<<NBL, 256, smem_bytes>>>(a, mw, mb, cw2, cb2, gam, bet, spw, spb, out);
    k_gemm_mma<<<dim3(NCOL / 128, 288 / 96, 16), 256, GEMM_SMEM>>>(out);
}

// round 17
// speedup vs baseline: 1.5876x; 1.0507x over previous
#include <cuda_runtime.h>
#include <cuda_bf16.h>
#include <math.h>
#include <stdint.h>

// ---------------- problem constants ----------------
#define AA    32
#define CC    16
#define KKn   9
#define KKA   288
#define NB    16      // Bc
#define ND    16      // D
#define NE    256     // Bc*D
#define HW    14
#define LL    196
#define NBSZ  4
#define NBL   784     // NBSZ*LL
#define NCOL  12544   // NBL*NB
#define KKA2  145
#define KP    288     // K for tensor GEMM (4 x 64 + 1 x 32, no padding)

// ---------------- scratch (static device mem; no allocs allowed) ----------------
__device__ float g_h[16 * 288];                                        //  18 KB
__device__ __align__(1024) __nv_bfloat16 g_Hb[(size_t)16 * 288 * KP];  //  2.65 MB  H circulant bf16 [d][m][k]
__device__ __align__(1024) __nv_bfloat16 g_Pb[(size_t)16 * NCOL * KP]; //  115.7 MB P bf16 [d][col][k] (FLAT)
__device__ float g_C[(size_t)288 * NCOL];                              //  14.4 MB  coeff [m][col]
__device__ __align__(128) float g_poseT[(size_t)NBSZ * LL * 512];      //  1.6 MB   pose transposed [b][pix][ch]

// lean exact-gelu via Abramowitz-Stegun 7.1.26 erf (|abs err| <= 1.5e-7) — used in S4 gate
__device__ __forceinline__ float rcp_approx(float x) {
    float r; asm("rcp.approx.f32 %0, %1;" : "=f"(r) : "f"(x)); return r;
}
__device__ __forceinline__ float gelu_fast(float v) {
    float x  = v * 0.70710678118654752f;
    float ax = fabsf(x);
    float t  = rcp_approx(fmaf(0.3275911f, ax, 1.0f));
    float poly = t * fmaf(t, fmaf(t, fmaf(t, fmaf(t, 1.061405429f, -1.453152027f),
                                          1.421413741f), -0.284496736f), 0.254829592f);
    float e  = __expf(-ax * ax);
    float r  = fmaf(poly, -e, 1.0f);
    float erfv = copysignf(r, x);
    float hv = 0.5f * v;
    return fmaf(hv, erfv, hv);
}

// ---------------- PTX helpers ----------------
__device__ __forceinline__ uint32_t smem_u32(const void* p) {
    uint32_t a;
    asm("{ .reg .u64 t; cvta.to.shared.u64 t, %1; cvt.u32.u64 %0, t; }" : "=r"(a) : "l"(p));
    return a;
}
__device__ __forceinline__ void cp_async16(uint32_t saddr, const void* gaddr) {
    asm volatile("cp.async.cg.shared.global [%0], [%1], 16;" :: "r"(saddr), "l"(gaddr) : "memory");
}
#define CP_COMMIT() asm volatile("cp.async.commit_group;" ::: "memory")
#define CP_WAIT(n)  asm volatile("cp.async.wait_group %0;" :: "n"(n) : "memory")

__device__ __forceinline__ void ldsm_x4(uint32_t& r0, uint32_t& r1, uint32_t& r2, uint32_t& r3,
                                        uint32_t addr) {
    asm volatile("ldmatrix.sync.aligned.m8n8.x4.shared.b16 {%0,%1,%2,%3}, [%4];"
                 : "=r"(r0), "=r"(r1), "=r"(r2), "=r"(r3) : "r"(addr));
}
__device__ __forceinline__ void mma_bf16(float* d, const uint32_t* a, const uint32_t* b) {
    asm volatile("mma.sync.aligned.m16n8k16.row.col.f32.bf16.bf16.f32 "
                 "{%0,%1,%2,%3}, {%4,%5,%6,%7}, {%8,%9}, {%0,%1,%2,%3};"
                 : "+f"(d[0]), "+f"(d[1]), "+f"(d[2]), "+f"(d[3])
                 : "r"(a[0]), "r"(a[1]), "r"(a[2]), "r"(a[3]), "r"(b[0]), "r"(b[1]));
}

// packed f32x2 helpers (Blackwell family baseline, PTX-only)
__device__ __forceinline__ uint64_t pk2(float lo, float hi) {
    uint64_t r;
    asm("mov.b64 %0, {%1, %2};" : "=l"(r) : "f"(lo), "f"(hi));
    return r;
}
__device__ __forceinline__ void upk2(float& lo, float& hi, uint64_t v) {
    asm("mov.b64 {%0, %1}, %2;" : "=f"(lo), "=f"(hi) : "l"(v));
}
__device__ __forceinline__ void fma2(uint64_t& d, uint64_t a, uint64_t b) {
    asm("fma.rn.f32x2 %0, %1, %2, %0;" : "+l"(d) : "l"(a), "l"(b));
}
__device__ __forceinline__ void mul2(uint64_t& d, uint64_t a, uint64_t b) {
    asm("mul.rn.f32x2 %0, %1, %2;" : "=l"(d) : "l"(a), "l"(b));
}

// packed-poly tanh-gelu on an m-pair: outputs two scalars
__device__ __forceinline__ void gelu_tanh2(uint64_t v2, float& p0, float& p1) {
    const uint64_t c1_2 = pk2(0.03567740814f, 0.03567740814f);
    uint64_t vv2; mul2(vv2, v2, v2);
    uint64_t t2 = pk2(0.79788456080f, 0.79788456080f);
    fma2(t2, vv2, c1_2);                 // t2 = vv2*c1 + c0
    uint64_t s2; mul2(s2, v2, t2);       // s = v*(c0 + c1 v^2)
    float s0, s1; upk2(s0, s1, s2);
    float th0, th1;
    asm("tanh.approx.f32 %0, %1;" : "=f"(th0) : "f"(s0));
    asm("tanh.approx.f32 %0, %1;" : "=f"(th1) : "f"(s1));
    float v0, v1; upk2(v0, v1, v2);
    float hv0 = 0.5f * v0, hv1 = 0.5f * v1;
    p0 = fmaf(hv0, th0, hv0);
    p1 = fmaf(hv1, th1, hv1);
}

// ============ kernel 0: h[d][t] = irfft(W_d)[t] — one block per d ============
__global__ void k_build_h(const float* __restrict__ cw) {
    __shared__ float ct[288], st[288];
    int t = threadIdx.x;  // 288 threads
    int d = blockIdx.x;   // 16 blocks
    float ang = 6.283185307179586f * (float)t * (1.0f / 288.0f);
    ct[t] = cosf(ang);
    st[t] = sinf(ang);
    __syncthreads();
    float wr0  = cw[(0 * 16 + d) * 2];
    float wnyq = cw[(144 * 16 + d) * 2];
    float acc = wr0 + ((t & 1) ? -wnyq : wnyq);
    float s2 = 0.0f;
    int idx = 0;
    for (int k = 1; k <= 143; k++) {
        idx += t; if (idx >= 288) idx -= 288;
        float wr = cw[(k * 16 + d) * 2];
        float wi = cw[(k * 16 + d) * 2 + 1];
        s2 += wr * ct[idx] - wi * st[idx];
    }
    g_h[d * 288 + t] = (acc + 2.0f * s2) * (1.0f / 288.0f);
}

// ============ kernel 1: H bf16 circulant [d][m][k<288] ============
__global__ void k_expand_Hb() {
    int m = blockIdx.x;      // 288
    int d = blockIdx.y;      // 16
    int j = threadIdx.x;     // 288
    int t = m - j; if (t < 0) t += 288;
    g_Hb[((size_t)d * 288 + m) * KP + j] = __float2bfloat16(g_h[d * 288 + t]);
}

// ============ kernel 1b: transpose pose [b][512][196] -> g_poseT [b][196][512] ============
__global__ void k_transpose_pose(const float* __restrict__ pose) {
    __shared__ float tile[32][33];
    const int pix0 = blockIdx.x * 32;   // 7 tiles (196)
    const int ch0  = blockIdx.y * 32;   // 16 tiles (512)
    const int bb   = blockIdx.z;        // 4
    const int tx = threadIdx.x, ty = threadIdx.y;  // 32 x 8
    #pragma unroll
    for (int k = 0; k < 4; k++) {
        int ch = ch0 + ty + k * 8;
        int pix = pix0 + tx;
        float v = 0.0f;
        if (pix < LL) v = pose[((size_t)bb * 512 + ch) * LL + pix];
        tile[ty + k * 8][tx] = v;
    }
    __syncthreads();
    #pragma unroll
    for (int k = 0; k < 4; k++) {
        int pix = pix0 + ty + k * 8;
        int ch = ch0 + tx;
        if (pix < LL)
            g_poseT[((size_t)bb * LL + pix) * 512 + ch] = tile[tx][ty + k * 8];
    }
}

// ============ kernel 2: per-position producer ============
extern __shared__ float smem_dyn[];
__global__ void __launch_bounds__(256, 2) k_main(
    const float* __restrict__ a_in,
    const float* __restrict__ mpose_w, const float* __restrict__ mpose_b,
    const float* __restrict__ cpose2_w, const float* __restrict__ cpose2_b,
    const float* __restrict__ ln_gamma, const float* __restrict__ ln_beta,
    const float* __restrict__ sp_w, const float* __restrict__ sp_b,
    float* __restrict__ out)
{
    // s_pu pair-packed: [p=m/2][c] float2 {pu[2p][c], pu[2p+1][c]}, 32 floats/row (128B)
    float* s_pu  = smem_dyn;               // 4608
    float* s_lg  = s_pu  + 4608;           // [288][17]; after S6 reused as s_cfp
    float* s_gn  = s_lg  + 4896;           // [288][17]; after S7 reused as reduction scratch
    float* s_cw2 = s_gn  + 4896;           // [16][18 float2] = 576
    float* s_cb  = s_cw2 + 576;
    float* s_spw = s_cb  + 16;
    float* s_spb = s_spw + 81;
    float* s_gam = s_spb + 16;
    float* s_bet = s_gam + 32;
    float* s_au  = s_bet + 32;
    float* s_mu  = s_au  + 288;
    float* s_rs  = s_mu  + 144;
    float* s_red = s_rs  + 144;
    float* s_ars = s_red + 256;            // stores 1/ar_sum
    float* s_aus = s_ars + 16;
    float* s_cfp = s_lg;                   // alias: coeff pair-packed [p][Bi] float2
    float* s_sc  = s_gn;                   // alias: S8 half-reduction scratch [e][half] (512)

    const int tid = threadIdx.x;
    const int bl = blockIdx.x;
    const int b = bl / LL, l = bl % LL;
    const int y = l / HW, x = l % HW;

    {
        int Bi = tid >> 4, c = tid & 15;
        float v = cpose2_w[tid];
        s_cw2[Bi * 36 + c * 2]     = v;     // packed {w,w}
        s_cw2[Bi * 36 + c * 2 + 1] = v;
        if (tid < 16)  s_cb[tid]  = cpose2_b[tid];
        if (tid < 81)  s_spw[tid] = sp_w[tid];
        if (tid < 9)   s_spb[tid] = sp_b[tid];
        if (tid < 32)  s_gam[tid] = ln_gamma[tid];
        if (tid >= 32 && tid < 64) s_bet[tid - 32] = ln_beta[tid - 32];
    }

    // S1: gather pu from transposed pose (coalesced: 9 pixels x 512 consecutive floats)
    {
        int ch = tid * 2;
        int ai = ch >> 4, c = ch & 15;
        #pragma unroll
        for (int kk = 0; kk < 9; kk++) {
            int py = y + kk / 3 - 1, px = x + kk % 3 - 1;
            float2 v = make_float2(0.0f, 0.0f);
            if ((unsigned)py < 14u && (unsigned)px < 14u)
                v = reinterpret_cast<const float2*>(
                        g_poseT + ((size_t)b * LL + py * 14 + px) * 512)[tid];
            int m = kk * 32 + ai;
            int base = (m >> 1) * 32 + (m & 1);
            s_pu[base + c * 2]       = v.x;
            s_pu[base + (c + 1) * 2] = v.y;
        }
    }
    for (int m = tid; m < 288; m += 256) {
        int kk = m >> 5, ai = m & 31;
        int py = y + kk / 3 - 1, px = x + kk % 3 - 1;
        float v = 0.0f;
        if ((unsigned)py < 14u && (unsigned)px < 14u)
            v = a_in[(((size_t)b * 32 + ai) * 14 + py) * 14 + px];
        s_au[m] = v;
    }
    __syncthreads();

    // S2: logits, m-pairs via fma.rn.f32x2 (Bi is loop-invariant per thread)
    {
        const int Bi = tid & 15;
        uint64_t w2[16];
        const uint64_t* cwp = reinterpret_cast<const uint64_t*>(s_cw2 + Bi * 36);
        #pragma unroll
        for (int c = 0; c < 16; c++) w2[c] = cwp[c];
        float cbv = s_cb[Bi];
        uint64_t cb2 = pk2(cbv, cbv);
        for (int idx = tid; idx < 2304; idx += 256) {
            int p = idx >> 4;
            const ulonglong2* pv = reinterpret_cast<const ulonglong2*>(s_pu + p * 32);
            uint64_t acc2 = cb2;
            #pragma unroll
            for (int c2 = 0; c2 < 8; c2++) {
                ulonglong2 u = pv[c2];
                fma2(acc2, u.x, w2[c2 * 2]);
                fma2(acc2, u.y, w2[c2 * 2 + 1]);
            }
            float lo, hi; upk2(lo, hi, acc2);
            s_lg[(2 * p) * 17 + Bi]     = lo;
            s_lg[(2 * p + 1) * 17 + Bi] = hi;
        }
    }
    __syncthreads();

    // S3: LayerNorm over a
    if (tid < 144) {
        int kk = tid >> 4, Bi = tid & 15;
        float s = 0.0f, s2 = 0.0f;
        #pragma unroll 4
        for (int ai = 0; ai < 32; ai++) {
            float v = s_lg[(kk * 32 + ai) * 17 + Bi];
            s += v; s2 += v * v;
        }
        float mu = s * (1.0f / 32.0f);
        float var = s2 * (1.0f / 32.0f) - mu * mu;
        s_mu[tid] = mu;
        s_rs[tid] = rsqrtf(var + 1e-5f);
    }
    __syncthreads();
    for (int idx = tid; idx < 4608; idx += 256) {
        int m = idx >> 4, Bi = idx & 15;
        int kk = m >> 5, ai = m & 31;
        float v = s_lg[m * 17 + Bi];
        s_gn[m * 17 + Bi] = (v - s_mu[kk * 16 + Bi]) * s_rs[kk * 16 + Bi] * s_gam[ai] + s_bet[ai];
    }
    __syncthreads();

    // S4: spatial gate (exact-poly gelu: logits feed softmax, keep precision)
    for (int idx = tid; idx < 4608; idx += 256) {
        int m = idx >> 4, Bi = idx & 15;
        int o = m >> 5, ai = m & 31;
        float acc = s_spb[o];
        #pragma unroll
        for (int i = 0; i < 9; i++)
            acc = fmaf(s_spw[o * 9 + i], s_gn[(i * 32 + ai) * 17 + Bi], acc);
        s_lg[m * 17 + Bi] = 2.0f * s_lg[m * 17 + Bi] + gelu_fast(acc);
    }
    __syncthreads();

    // S5: softmax over Bi; au sum
    for (int m = tid; m < 288; m += 256) {
        float* row = s_lg + m * 17;
        float mx = row[0];
        #pragma unroll
        for (int i = 1; i < 16; i++) mx = fmaxf(mx, row[i]);
        float s = 0.0f;
        #pragma unroll
        for (int i = 0; i < 16; i++) { float e = __expf(row[i] - mx); row[i] = e; s += e; }
        float inv = 1.0f / s;
        #pragma unroll
        for (int i = 0; i < 16; i++) row[i] *= inv;
    }
    if (tid < 32) {
        float p = 0.0f;
        for (int m = tid; m < 288; m += 32) p += s_au[m];
        #pragma unroll
        for (int o = 16; o; o >>= 1) p += __shfl_xor_sync(0xffffffffu, p, o);
        if (tid == 0) *s_aus = p;
    }
    __syncthreads();

    // S6: ar and ar_sum (ar -> s_gn)
    {
        int Bi = tid & 15, ck = tid >> 4;
        float p = 0.0f;
        #pragma unroll 2
        for (int r = 0; r < 18; r++) {
            int m = ck * 18 + r;
            float ar = s_au[m] * s_lg[m * 17 + Bi];
            s_gn[m * 17 + Bi] = ar;
            p += ar;
        }
        s_red[ck * 16 + Bi] = p;
    }
    __syncthreads();
    if (tid < 16) {
        float s = 0.0f;
        #pragma unroll
        for (int c = 0; c < 16; c++) s += s_red[c * 16 + tid];
        s_ars[tid] = rcp_approx(s);                            // store reciprocal
        out[((size_t)b * 16 + tid) * LL + l] = s / (*s_aus);
    }
    __syncthreads();

    // S7: coeff = ar * (1/ars); write C[m][col] and pair-packed s_cfp (aliases dead s_lg)
    for (int idx = tid; idx < 4608; idx += 256) {
        int m = idx >> 4, Bi = idx & 15;
        float cf = s_gn[m * 17 + Bi] * s_ars[Bi];
        s_cfp[(m >> 1) * 32 + Bi * 2 + (m & 1)] = cf;
        g_C[(size_t)m * NCOL + (size_t)bl * 16 + Bi] = cf;
    }
    __syncthreads();

    // S8: TWO output channels per thread over HALF the m-range:
    // thread (Bi, dd, half) handles e0=(Bi,dd), e1=(Bi,dd+8), m-pairs [half*72, half*72+72).
    // Each pu LDS.128 feeds 4 fma2 (2 per e) -> per-thread pu loads halve (1152 -> 576).
    // Half-partial coeff sums combined via s_sc scratch (dead s_gn).
    {
        const int Bi = tid & 15, dd = (tid >> 4) & 7, half = tid >> 7;
        const int e0 = Bi * 16 + dd, e1 = Bi * 16 + dd + 8;
        uint64_t W2a[16], W2b[16];
        #pragma unroll
        for (int c = 0; c < 16; c++) {
            float wa = mpose_w[e0 * 16 + c];
            float wb = mpose_w[e1 * 16 + c];
            W2a[c] = pk2(wa, wa);
            W2b[c] = pk2(wb, wb);
        }
        uint64_t bs2a = pk2(mpose_b[e0], mpose_b[e0]);
        uint64_t bs2b = pk2(mpose_b[e1], mpose_b[e1]);
        uint64_t acc2a = pk2(0.0f, 0.0f), acc2b = pk2(0.0f, 0.0f);
        const float* cf_base = s_cfp + Bi * 2;
        uint4* Pa4 = reinterpret_cast<uint4*>(
            g_Pb + ((size_t)dd * NCOL + (size_t)bl * 16 + Bi) * KP);
        uint4* Pb4 = reinterpret_cast<uint4*>(
            g_Pb + ((size_t)(dd + 8) * NCOL + (size_t)bl * 16 + Bi) * KP);
        const int g0 = half * 18;
        for (int g2 = 0; g2 < 18; g2++) {
            int g = g0 + g2;
            uint32_t pka[4], pkb[4];
            #pragma unroll
            for (int pp = 0; pp < 4; pp++) {
                int p = g * 4 + pp;               // m-pair (2p, 2p+1)
                const ulonglong2* pv = reinterpret_cast<const ulonglong2*>(s_pu + p * 32);
                uint64_t v2a = bs2a, v2b = bs2b;
                #pragma unroll
                for (int c2 = 0; c2 < 8; c2++) {
                    ulonglong2 u = pv[c2];
                    fma2(v2a, u.x, W2a[c2 * 2]);
                    fma2(v2a, u.y, W2a[c2 * 2 + 1]);
                    fma2(v2b, u.x, W2b[c2 * 2]);
                    fma2(v2b, u.y, W2b[c2 * 2 + 1]);
                }
                float p0a, p1a, p0b, p1b;
                gelu_tanh2(v2a, p0a, p1a);
                gelu_tanh2(v2b, p0b, p1b);
                uint64_t cf2 = *reinterpret_cast<const uint64_t*>(cf_base + p * 32);
                fma2(acc2a, cf2, pk2(p0a, p1a));
                fma2(acc2b, cf2, pk2(p0b, p1b));
                __nv_bfloat162 ha = __floats2bfloat162_rn(p0a, p1a);
                __nv_bfloat162 hb = __floats2bfloat162_rn(p0b, p1b);
                pka[pp] = *reinterpret_cast<uint32_t*>(&ha);
                pkb[pp] = *reinterpret_cast<uint32_t*>(&hb);
            }
            Pa4[g] = make_uint4(pka[0], pka[1], pka[2], pka[3]);
            Pb4[g] = make_uint4(pkb[0], pkb[1], pkb[2], pkb[3]);
        }
        float a0, a1;
        upk2(a0, a1, acc2a); s_sc[e0 * 2 + half] = a0 + a1;
        upk2(a0, a1, acc2b); s_sc[e1 * 2 + half] = a0 + a1;
    }
    __syncthreads();
    {
        int e = tid;
        out[12544 + (size_t)b * 50176 + (size_t)e * LL + l] = s_sc[e * 2] + s_sc[e * 2 + 1];
    }
}

// ============ kernel 3: mma.sync bf16 circulant GEMM + fused coeff reduction ============
// Tile m=96 x col=128, 2 CTA/SM, K = 4x64 + 1x32 tail.
// 3-stage cp.async pipeline, ONE __syncthreads per chunk (R15 config, ~152 us).
#define SA_STG 12288            // 96 rows x 128B
#define SB_STG 16384            // 128 rows x 128B
#define GEMM_SMEM (3 * SA_STG + 3 * SB_STG)

__global__ void __launch_bounds__(256, 2) k_gemm_mma(float* __restrict__ out) {
    extern __shared__ __align__(128) char smemc[];
    const uint32_t sb = smem_u32(smemc);
    const int tid  = threadIdx.x;
    const int lane = tid & 31;
    const int wid  = tid >> 5;
    const int wm   = wid >> 2;          // 0..1  (m-warp, 48 rows each)
    const int wn   = wid & 3;           // 0..3  (n-warp, 32 cols each)

    const int d    = blockIdx.z;
    const int m0   = blockIdx.y * 96;
    const int col0 = blockIdx.x * 128;

    const __nv_bfloat16* Hg = g_Hb + ((size_t)d * 288 + m0) * KP;
    const __nv_bfloat16* Pg = g_Pb + ((size_t)d * NCOL + col0) * KP;

    float acc[3][4][4];
    #pragma unroll
    for (int r = 0; r < 3; r++)
        #pragma unroll
        for (int q = 0; q < 4; q++)
            #pragma unroll
            for (int i = 0; i < 4; i++) acc[r][q][i] = 0.0f;

    auto load_chunk64 = [&](int c, int s) {
        uint32_t abase = sb + s * SA_STG;
        uint32_t bbase = sb + 3 * SA_STG + s * SB_STG;
        #pragma unroll
        for (int it = 0; it < 3; it++) {
            int i = tid + it * 256;
            int row = i >> 3, u = i & 7;
            cp_async16(abase + row * 128 + ((u ^ (row & 7)) << 4),
                       Hg + (size_t)row * KP + c * 64 + u * 8);
        }
        #pragma unroll
        for (int it = 0; it < 4; it++) {
            int i = tid + it * 256;
            int row = i >> 3, u = i & 7;
            cp_async16(bbase + row * 128 + ((u ^ (row & 7)) << 4),
                       Pg + (size_t)row * KP + c * 64 + u * 8);
        }
        CP_COMMIT();
    };
    auto load_chunk32 = [&](int s) {
        uint32_t abase = sb + s * SA_STG;
        uint32_t bbase = sb + 3 * SA_STG + s * SB_STG;
        #pragma unroll
        for (int it = 0; it < 2; it++) {
            int i = tid + it * 256;
            if (i < 384) {
                int row = i >> 2, u = i & 3;
                cp_async16(abase + row * 128 + ((u ^ (row & 7)) << 4),
                           Hg + (size_t)row * KP + 256 + u * 8);
            }
        }
        #pragma unroll
        for (int it = 0; it < 2; it++) {
            int i = tid + it * 256;
            int row = i >> 2, u = i & 3;
            cp_async16(bbase + row * 128 + ((u ^ (row & 7)) << 4),
                       Pg + (size_t)row * KP + 256 + u * 8);
        }
        CP_COMMIT();
    };

    const int a_row_l = wm * 48 + (lane & 15);
    const int a_chalf = lane >> 4;
    const int b_row_l = wn * 32 + ((lane >> 4) << 3) + (lane & 7);
    const int b_chalf = (lane >> 3) & 1;

    auto mma_stage = [&](int s, int nks) {
        uint32_t Ab = sb + s * SA_STG;
        uint32_t Bb = sb + 3 * SA_STG + s * SB_STG;
        for (int ks = 0; ks < nks; ks++) {
            uint32_t a[3][4], bfrag[4][2];
            #pragma unroll
            for (int r = 0; r < 3; r++) {
                int row = a_row_l + r * 16;
                int c16 = ks * 2 + a_chalf;
                ldsm_x4(a[r][0], a[r][1], a[r][2], a[r][3],
                        Ab + row * 128 + (((c16 ^ (row & 7)) & 7) << 4));
            }
            #pragma unroll
            for (int qp = 0; qp < 2; qp++) {
                int row = b_row_l + qp * 16;
                int c16 = ks * 2 + b_chalf;
                ldsm_x4(bfrag[qp * 2][0], bfrag[qp * 2][1],
                        bfrag[qp * 2 + 1][0], bfrag[qp * 2 + 1][1],
                        Bb + row * 128 + (((c16 ^ (row & 7)) & 7) << 4));
            }
            #pragma unroll
            for (int r = 0; r < 3; r++)
                #pragma unroll
                for (int q = 0; q < 4; q++)
                    mma_bf16(acc[r][q], a[r], bfrag[q]);
        }
    };

    load_chunk64(0, 0);
    load_chunk64(1, 1);
    CP_WAIT(1); __syncthreads(); load_chunk64(2, 2); mma_stage(0, 4);
    CP_WAIT(1); __syncthreads(); load_chunk64(3, 0); mma_stage(1, 4);
    CP_WAIT(1); __syncthreads(); load_chunk32(1);    mma_stage(2, 4);
    CP_WAIT(1); __syncthreads();                     mma_stage(0, 4);
    CP_WAIT(0); __syncthreads();                     mma_stage(1, 2);

    // fused epilogue: s[col] = sum_m C[m,col] * D[m,col]
    float s[8];
    #pragma unroll
    for (int j = 0; j < 8; j++) s[j] = 0.0f;
    const int colb = col0 + wn * 32 + ((lane & 3) << 1);
    #pragma unroll
    for (int r = 0; r < 3; r++) {
        #pragma unroll
        for (int half = 0; half < 2; half++) {
            int m = m0 + wm * 48 + r * 16 + (lane >> 2) + half * 8;
            const float* Crow = g_C + (size_t)m * NCOL;
            #pragma unroll
            for (int q = 0; q < 4; q++) {
                s[q * 2 + 0] = fmaf(Crow[colb + q * 8 + 0], acc[r][q][half * 2 + 0], s[q * 2 + 0]);
                s[q * 2 + 1] = fmaf(Crow[colb + q * 8 + 1], acc[r][q][half * 2 + 1], s[q * 2 + 1]);
            }
        }
    }
    #pragma unroll
    for (int off = 4; off < 32; off <<= 1)
        #pragma unroll
        for (int j = 0; j < 8; j++) s[j] += __shfl_xor_sync(0xffffffffu, s[j], off);

    if (lane < 4) {
        #pragma unroll
        for (int q = 0; q < 4; q++) {
            #pragma unroll
            for (int j = 0; j < 2; j++) {
                int col = col0 + wn * 32 + q * 8 + lane * 2 + j;
                int bl = col >> 4, Bi = col & 15;
                int bb = bl / LL, ll = bl % LL;
                atomicAdd(&out[12544 + (size_t)bb * 50176 + (size_t)(Bi * 16 + d) * LL + ll],
                          s[q * 2 + j]);
            }
        }
    }
}

// ---------------- launch ----------------
extern "C" void kernel_launch(void* const* d_in, const int* in_sizes, int n_in,
                              void* d_out, int out_size) {
    const float* a     = (const float*)d_in[0];
    const float* pose  = (const float*)d_in[1];
    const float* mw    = (const float*)d_in[2];
    const float* mb    = (const float*)d_in[3];
    const float* cw2   = (const float*)d_in[4];
    const float* cb2   = (const float*)d_in[5];
    const float* cplx  = (const float*)d_in[6];
    const float* gam   = (const float*)d_in[7];
    const float* bet   = (const float*)d_in[8];
    const float* spw   = (const float*)d_in[9];
    const float* spb   = (const float*)d_in[10];
    float* out = (float*)d_out;

    size_t smem_floats = (size_t)4608 + 4896 + 4896 + 576 + 16 + 81 + 16 + 32 + 32 + 288 + 144 + 144 + 256 + 16 + 1;
    size_t smem_bytes = smem_floats * sizeof(float);
    cudaFuncSetAttribute(k_main, cudaFuncAttributeMaxDynamicSharedMemorySize, (int)smem_bytes);
    cudaFuncSetAttribute(k_gemm_mma, cudaFuncAttributeMaxDynamicSharedMemorySize, GEMM_SMEM);

    k_build_h<<<16, 288>>>(cplx);
    k_expand_Hb<<<dim3(288, 16), 288>>>();
    k_transpose_pose<<<dim3(7, 16, NBSZ), dim3(32, 8)>>>(pose);
    k_main<<<NBL, 256, smem_bytes>>>(a, mw, mb, cw2, cb2, gam, bet, spw, spb, out);
    k_gemm_mma<<<dim3(NCOL / 128, 288 / 96, 16), 256, GEMM_SMEM>>>(out);
}